// round 7
// baseline (speedup 1.0000x reference)
#include <cuda_runtime.h>
#include <cuda_bf16.h>
#include <cstdint>
#include <math.h>

// Problem dims (fixed by the dataset)
#define N_Q    2048
#define M_KV   4096
#define DMODEL 1024
#define NHEADS 16
#define DHEAD  64
#define DFF    4096
#define DOUT   1000

typedef __nv_bfloat16 bf16;

// ---------------- scratch (device globals; no allocation allowed) ----------------
__device__ bf16 g_FINh[N_Q * 2 * DMODEL],  g_FINl[N_Q * 2 * DMODEL];
__device__ bf16 g_memh[M_KV * DMODEL],     g_meml[M_KV * DMODEL];
__device__ bf16 g_Wqh[DMODEL * DMODEL],    g_Wql[DMODEL * DMODEL];
__device__ bf16 g_WKVh[2 * DMODEL * DMODEL], g_WKVl[2 * DMODEL * DMODEL];  // [Wk; Wv]
__device__ bf16 g_Woh[DMODEL * DMODEL],    g_Wol[DMODEL * DMODEL];
__device__ bf16 g_W1h[DFF * 2 * DMODEL],   g_W1l[DFF * 2 * DMODEL];
__device__ bf16 g_W2h[DOUT * DFF],         g_W2l[DOUT * DFF];
__device__ bf16 g_Qh[N_Q * DMODEL],        g_Ql[N_Q * DMODEL];
__device__ bf16 g_KVh[M_KV * 2 * DMODEL],  g_KVl[M_KV * 2 * DMODEL];      // K | V
__device__ float g_bKV[2 * DMODEL];
__device__ float g_S[(size_t)NHEADS * N_Q * M_KV];
__device__ float g_tau[NHEADS * N_Q];
__device__ bf16 g_Oh[N_Q * DMODEL],        g_Ol[N_Q * DMODEL];
__device__ bf16 g_Hh[N_Q * DFF],           g_Hl[N_Q * DFF];

// ---------------- helpers ----------------
__device__ __forceinline__ uint32_t smem_u32(const void* p) {
    uint32_t a;
    asm("{ .reg .u64 t; cvta.to.shared.u64 t, %1; cvt.u32.u64 %0, t; }" : "=r"(a) : "l"(p));
    return a;
}
__device__ __forceinline__ void ldmx4(uint32_t* r, uint32_t a) {
    asm volatile("ldmatrix.sync.aligned.m8n8.x4.shared.b16 {%0,%1,%2,%3}, [%4];"
                 : "=r"(r[0]), "=r"(r[1]), "=r"(r[2]), "=r"(r[3]) : "r"(a));
}
__device__ __forceinline__ void mma_bf16(float* d, const uint32_t* a, uint32_t b0, uint32_t b1) {
    asm volatile("mma.sync.aligned.m16n8k16.row.col.f32.bf16.bf16.f32 "
                 "{%0,%1,%2,%3}, {%4,%5,%6,%7}, {%8,%9}, {%0,%1,%2,%3};"
                 : "+f"(d[0]), "+f"(d[1]), "+f"(d[2]), "+f"(d[3])
                 : "r"(a[0]), "r"(a[1]), "r"(a[2]), "r"(a[3]), "r"(b0), "r"(b1));
}
__device__ __forceinline__ void cpa16(uint32_t s, const void* g) {
    asm volatile("cp.async.cg.shared.global [%0], [%1], 16;" :: "r"(s), "l"(g));
}
__device__ __forceinline__ void cpa16z(uint32_t s, const void* g, bool ok) {
    int sz = ok ? 16 : 0;
    asm volatile("cp.async.cg.shared.global [%0], [%1], 16, %2;" :: "r"(s), "l"(g), "r"(sz));
}
#define CPA_COMMIT() asm volatile("cp.async.commit_group;" ::: "memory")
#define CPA_WAIT0()  asm volatile("cp.async.wait_group 0;" ::: "memory")
#define CPA_WAIT1()  asm volatile("cp.async.wait_group 1;" ::: "memory")

// split fp32 pair into packed bf16 hi + bf16 residual
__device__ __forceinline__ void split2(float a, float b, uint32_t& h, uint32_t& l) {
    __nv_bfloat162 hh = __floats2bfloat162_rn(a, b);
    float2 hf = __bfloat1622float2(hh);
    __nv_bfloat162 ll = __floats2bfloat162_rn(a - hf.x, b - hf.y);
    h = *reinterpret_cast<uint32_t*>(&hh);
    l = *reinterpret_cast<uint32_t*>(&ll);
}

// ====================== 512-thread, 3-stage split-bf16 MMA GEMM ======================
// C = alpha * A @ B^T + bias (+ReLU).  A,B pre-split bf16 hi/lo, NT form.
// BM=256, BN=128, warp tile 32x64 (16 warps). 3-stage cp.async pipeline, 1 CTA/SM.
// EPI=0: write fp32 to Cf.  EPI=1: write split hi/lo to Chi/Clo.
template<int BM, int BN, int WM, int WN, int EPI, bool RELU, bool NGUARD>
__global__ __launch_bounds__((BM/WM)*(BN/WN)*32, 1)
void mma_gemm(int M, int N, int K,
              const bf16* __restrict__ Ah, const bf16* __restrict__ Al, int lda, long long sAz,
              const bf16* __restrict__ Bh, const bf16* __restrict__ Bl, int ldb, long long sBz,
              float* __restrict__ Cf, bf16* __restrict__ Chi, bf16* __restrict__ Clo,
              long long ldc, long long sCz,
              const float* __restrict__ bias, float alpha)
{
    constexpr int THREADS = (BM/WM)*(BN/WN)*32;
    constexpr int BK = 32, BKP = 40;               // 80B pitch: 16B-aligned, ldmatrix conflict-free
    constexpr int WNC = BN / WN;
    constexpr int MI = WM / 16, NI2 = WN / 16, NA = WN / 8;
    constexpr int SA = BM * BKP, SB = BN * BKP;
    constexpr int STAGE_BYTES = (2 * SA + 2 * SB) * 2;

    extern __shared__ __align__(16) char smem[];
    const uint32_t uS = smem_u32(smem);

    const int tid = threadIdx.x, wid = tid >> 5, lane = tid & 31;
    Ah += (long long)blockIdx.z * sAz;  Al += (long long)blockIdx.z * sAz;
    Bh += (long long)blockIdx.z * sBz;  Bl += (long long)blockIdx.z * sBz;
    const long long coff = (long long)blockIdx.z * sCz;
    const int row0 = blockIdx.y * BM;
    const int col0 = blockIdx.x * BN;
    const int wm0 = (wid / WNC) * WM;
    const int wn0 = (wid % WNC) * WN;

    float acc[MI][NA][4];
    #pragma unroll
    for (int i = 0; i < MI; i++)
        #pragma unroll
        for (int j = 0; j < NA; j++)
            #pragma unroll
            for (int q = 0; q < 4; q++) acc[i][j][q] = 0.f;

    auto loadT = [&](int stage, int kt) {
        uint32_t base = uS + stage * STAGE_BYTES;
        #pragma unroll
        for (int i = 0; i < (BM * 4) / THREADS; i++) {
            int ch = tid + i * THREADS, r = ch >> 2, q = ch & 3;
            cpa16(base + r * 80 + q * 16,            Ah + (size_t)(row0 + r) * lda + kt + q * 8);
            cpa16(base + SA * 2 + r * 80 + q * 16,   Al + (size_t)(row0 + r) * lda + kt + q * 8);
        }
        #pragma unroll
        for (int i = 0; i < (BN * 4) / THREADS; i++) {
            int ch = tid + i * THREADS, r = ch >> 2, q = ch & 3;
            bool ok = !NGUARD || (col0 + r) < N;
            cpa16z(base + 2 * SA * 2 + r * 80 + q * 16,
                   Bh + (size_t)(col0 + r) * ldb + kt + q * 8, ok);
            cpa16z(base + (2 * SA + SB) * 2 + r * 80 + q * 16,
                   Bl + (size_t)(col0 + r) * ldb + kt + q * 8, ok);
        }
    };
    auto compute = [&](int stage) {
        uint32_t bA = uS + stage * STAGE_BYTES;
        uint32_t bAh = bA, bAl = bA + SA * 2, bBh = bA + 2 * SA * 2, bBl = bA + (2 * SA + SB) * 2;
        const int lr = lane & 15, lc = (lane >> 4) * 8;
        #pragma unroll
        for (int kk = 0; kk < BK; kk += 16) {
            uint32_t bh[NI2][4], bl[NI2][4];
            #pragma unroll
            for (int ni = 0; ni < NI2; ni++) {
                uint32_t off = (uint32_t)((wn0 + ni * 16 + lr) * 80 + (kk + lc) * 2);
                ldmx4(bh[ni], bBh + off);
                ldmx4(bl[ni], bBl + off);
            }
            #pragma unroll
            for (int mi = 0; mi < MI; mi++) {
                uint32_t ah[4], al[4];
                uint32_t off = (uint32_t)((wm0 + mi * 16 + lr) * 80 + (kk + lc) * 2);
                ldmx4(ah, bAh + off);
                ldmx4(al, bAl + off);
                #pragma unroll
                for (int na = 0; na < NA; na++) {
                    int ni = na >> 1, sel = na & 1;
                    uint32_t b0h = bh[ni][sel], b1h = bh[ni][sel + 2];
                    mma_bf16(acc[mi][na], ah, b0h, b1h);
                    mma_bf16(acc[mi][na], al, b0h, b1h);
                    mma_bf16(acc[mi][na], ah, bl[ni][sel], bl[ni][sel + 2]);
                }
            }
        }
    };

    const int tiles = K / BK;
    loadT(0, 0);
    CPA_COMMIT();
    if (tiles > 1) loadT(1, BK);
    CPA_COMMIT();
    for (int t = 0; t < tiles; t++) {
        if (t + 1 < tiles) { CPA_WAIT1(); } else { CPA_WAIT0(); }
        __syncthreads();
        compute(t % 3);
        if (t + 2 < tiles) loadT((t + 2) % 3, (t + 2) * BK);
        CPA_COMMIT();
    }

    // ---------------- epilogue ----------------
    const int lr4 = lane >> 2, lc2 = (lane & 3) * 2;
    #pragma unroll
    for (int mi = 0; mi < MI; mi++) {
        #pragma unroll
        for (int na = 0; na < NA; na++) {
            float* d = acc[mi][na];
            int col = col0 + wn0 + na * 8 + lc2;
            int r0 = row0 + wm0 + mi * 16 + lr4;
            float bb0 = 0.f, bb1 = 0.f;
            if (bias) {
                if (!NGUARD || col     < N) bb0 = bias[col];
                if (!NGUARD || col + 1 < N) bb1 = bias[col + 1];
            }
            float v0 = d[0] * alpha + bb0, v1 = d[1] * alpha + bb1;
            float v2 = d[2] * alpha + bb0, v3 = d[3] * alpha + bb1;
            if (RELU) {
                v0 = fmaxf(v0, 0.f); v1 = fmaxf(v1, 0.f);
                v2 = fmaxf(v2, 0.f); v3 = fmaxf(v3, 0.f);
            }
            if (EPI == 0) {
                long long b0i = (long long)r0 * ldc + col + coff;
                long long b1i = (long long)(r0 + 8) * ldc + col + coff;
                if (!NGUARD || col + 1 < N) {
                    *reinterpret_cast<float2*>(Cf + b0i) = make_float2(v0, v1);
                    *reinterpret_cast<float2*>(Cf + b1i) = make_float2(v2, v3);
                } else if (col < N) {
                    Cf[b0i] = v0;
                    Cf[b1i] = v2;
                }
            } else {
                uint32_t h01, l01, h23, l23;
                split2(v0, v1, h01, l01);
                split2(v2, v3, h23, l23);
                long long b0i = (long long)r0 * ldc + col + coff;
                long long b1i = (long long)(r0 + 8) * ldc + col + coff;
                *reinterpret_cast<uint32_t*>(Chi + b0i) = h01;
                *reinterpret_cast<uint32_t*>(Clo + b0i) = l01;
                *reinterpret_cast<uint32_t*>(Chi + b1i) = h23;
                *reinterpret_cast<uint32_t*>(Clo + b1i) = l23;
            }
        }
    }
}

// ====================== PV: O_h = sparsemax(S_h) @ V_h, tau applied on the fly ======================
// Warp tile 32x32: 8 warps = 4 (m) x 2 (n); MI=2, NA=4, ldmx/MMA = 0.33
__global__ __launch_bounds__(256, 2)
void pv_gemm(const float* __restrict__ S, const float* __restrict__ tau,
             const bf16* __restrict__ KVh, const bf16* __restrict__ KVl,
             bf16* __restrict__ Oh, bf16* __restrict__ Ol)
{
    constexpr int BM = 128, BK = 32, BKP = 40;
    constexpr int SA = BM * BKP, SB = DHEAD * BKP;
    constexpr int STAGE = (2 * SA + 2 * SB) * 2;

    extern __shared__ __align__(16) char smem[];
    float* sTau = reinterpret_cast<float*>(smem + 2 * STAGE);

    const int tid = threadIdx.x, wid = tid >> 5, lane = tid & 31;
    const int head = blockIdx.y;
    const int row0 = blockIdx.x * BM;
    const float* Sb  = S + (size_t)head * N_Q * M_KV + (size_t)row0 * M_KV;
    const float* tb  = tau + head * N_Q + row0;
    const bf16* Vhb  = KVh + DMODEL + head * DHEAD;   // V half of KV buffer
    const bf16* Vlb  = KVl + DMODEL + head * DHEAD;

    if (tid < BM) sTau[tid] = tb[tid];
    __syncthreads();

    const int wm0 = (wid >> 1) * 32;
    const int wn0 = (wid & 1) * 32;
    constexpr int MI = 2, NI2 = 2, NA = 4;

    float acc[MI][NA][4];
    #pragma unroll
    for (int i = 0; i < MI; i++)
        #pragma unroll
        for (int j = 0; j < NA; j++)
            #pragma unroll
            for (int q = 0; q < 4; q++) acc[i][j][q] = 0.f;

    float4 aReg[4];
    uint4 bhReg, blReg;
    const int a_r = tid >> 3, a_c = (tid & 7) * 4;
    const int b_k = tid >> 3, b_c = (tid & 7) * 8;

    auto ldRegs = [&](int kt) {
        #pragma unroll
        for (int i = 0; i < 4; i++)
            aReg[i] = *reinterpret_cast<const float4*>(Sb + (size_t)(a_r + i * 32) * M_KV + kt + a_c);
        bhReg = *reinterpret_cast<const uint4*>(Vhb + (size_t)(kt + b_k) * 2 * DMODEL + b_c);
        blReg = *reinterpret_cast<const uint4*>(Vlb + (size_t)(kt + b_k) * 2 * DMODEL + b_c);
    };
    auto sts = [&](int st) {
        bf16* base = reinterpret_cast<bf16*>(smem + st * STAGE);
        bf16* Ahs = base;
        bf16* Als = base + SA;
        bf16* Bhs = base + 2 * SA;
        bf16* Bls = base + 2 * SA + SB;
        #pragma unroll
        for (int i = 0; i < 4; i++) {
            int r = a_r + i * 32;
            float tv = sTau[r];
            float p0 = fmaxf(aReg[i].x - tv, 0.f), p1 = fmaxf(aReg[i].y - tv, 0.f);
            float p2 = fmaxf(aReg[i].z - tv, 0.f), p3 = fmaxf(aReg[i].w - tv, 0.f);
            uint32_t h01, l01, h23, l23;
            split2(p0, p1, h01, l01);
            split2(p2, p3, h23, l23);
            *reinterpret_cast<uint2*>(Ahs + r * BKP + a_c) = make_uint2(h01, h23);
            *reinterpret_cast<uint2*>(Als + r * BKP + a_c) = make_uint2(l01, l23);
        }
        bf16 th[8], tl[8];
        *reinterpret_cast<uint4*>(th) = bhReg;
        *reinterpret_cast<uint4*>(tl) = blReg;
        #pragma unroll
        for (int j = 0; j < 8; j++) {
            Bhs[(b_c + j) * BKP + b_k] = th[j];
            Bls[(b_c + j) * BKP + b_k] = tl[j];
        }
    };
    auto compute = [&](int st) {
        uint32_t base = smem_u32(smem) + st * STAGE;
        uint32_t uAh = base, uAl = base + SA * 2, uBh = base + 2 * SA * 2, uBl = base + (2 * SA + SB) * 2;
        const int lr = lane & 15, lc = (lane >> 4) * 8;
        #pragma unroll
        for (int kk = 0; kk < BK; kk += 16) {
            uint32_t bh[NI2][4], bl[NI2][4];
            #pragma unroll
            for (int ni = 0; ni < NI2; ni++) {
                uint32_t boff = (uint32_t)((wn0 + ni * 16 + lr) * BKP + kk + lc) * 2;
                ldmx4(bh[ni], uBh + boff);
                ldmx4(bl[ni], uBl + boff);
            }
            #pragma unroll
            for (int mi = 0; mi < MI; mi++) {
                uint32_t ah[4], al[4];
                uint32_t aoff = (uint32_t)((wm0 + mi * 16 + lr) * BKP + kk + lc) * 2;
                ldmx4(ah, uAh + aoff);
                ldmx4(al, uAl + aoff);
                #pragma unroll
                for (int na = 0; na < NA; na++) {
                    int ni = na >> 1, sel = na & 1;
                    uint32_t b0 = bh[ni][sel], b1 = bh[ni][sel + 2];
                    mma_bf16(acc[mi][na], ah, b0, b1);
                    mma_bf16(acc[mi][na], al, b0, b1);
                    mma_bf16(acc[mi][na], ah, bl[ni][sel], bl[ni][sel + 2]);
                }
            }
        }
    };

    const int tiles = M_KV / BK;
    ldRegs(0);
    sts(0);
    for (int t = 0; t < tiles; t++) {
        __syncthreads();
        if (t + 1 < tiles) ldRegs((t + 1) * BK);
        compute(t & 1);
        if (t + 1 < tiles) sts((t + 1) & 1);
    }

    const int lr4 = lane >> 2, lc2 = (lane & 3) * 2;
    #pragma unroll
    for (int mi = 0; mi < MI; mi++) {
        #pragma unroll
        for (int na = 0; na < NA; na++) {
            float* d = acc[mi][na];
            int col = head * DHEAD + wn0 + na * 8 + lc2;
            int r0 = row0 + wm0 + mi * 16 + lr4;
            uint32_t h01, l01, h23, l23;
            split2(d[0], d[1], h01, l01);
            split2(d[2], d[3], h23, l23);
            *reinterpret_cast<uint32_t*>(Oh + (size_t)r0 * DMODEL + col) = h01;
            *reinterpret_cast<uint32_t*>(Ol + (size_t)r0 * DMODEL + col) = l01;
            *reinterpret_cast<uint32_t*>(Oh + (size_t)(r0 + 8) * DMODEL + col) = h23;
            *reinterpret_cast<uint32_t*>(Ol + (size_t)(r0 + 8) * DMODEL + col) = l23;
        }
    }
}

// ---------------- sparsemax tau: 4 rows per 256-thread block, 64 threads/row ----------------
__global__ __launch_bounds__(256)
void sparsemax_tau(const float* __restrict__ S, float* __restrict__ tau)
{
    const int tid = threadIdx.x;
    const int grp = tid >> 6;
    const int gt  = tid & 63;
    const int lane = tid & 31;
    const int wid = tid >> 5;
    const long long row = (long long)blockIdx.x * 4 + grp;

    const float4* z4 = reinterpret_cast<const float4*>(S + row * (long long)M_KV);
    float4 v4[16];
    #pragma unroll
    for (int j = 0; j < 16; j++) v4[j] = z4[gt + j * 64];
    float* v = reinterpret_cast<float*>(v4);

    __shared__ float red_s[8], red_c[8];
    __shared__ float s_tau[4];
    __shared__ int   s_done;

    float m = v[0];
    #pragma unroll
    for (int i = 1; i < 64; i++) m = fmaxf(m, v[i]);
    #pragma unroll
    for (int o = 16; o > 0; o >>= 1) m = fmaxf(m, __shfl_xor_sync(0xffffffffu, m, o));
    if (lane == 0) red_s[wid] = m;
    if (tid == 0) s_done = 0;
    __syncthreads();
    if (gt == 0) s_tau[grp] = fmaxf(red_s[grp * 2], red_s[grp * 2 + 1]) - 1.0f;
    __syncthreads();
    float t = s_tau[grp];

    for (int it = 0; it < 64; ++it) {
        float s = 0.f, c = 0.f;
        #pragma unroll
        for (int i = 0; i < 64; i++) {
            float d = v[i] - t;
            if (d > 0.f) { s += d; c += 1.f; }
        }
        #pragma unroll
        for (int o = 16; o > 0; o >>= 1) {
            s += __shfl_xor_sync(0xffffffffu, s, o);
            c += __shfl_xor_sync(0xffffffffu, c, o);
        }
        if (lane == 0) { red_s[wid] = s; red_c[wid] = c; }
        __syncthreads();
        if (gt == 0) {
            float St = red_s[grp * 2] + red_s[grp * 2 + 1];
            float Ct = red_c[grp * 2] + red_c[grp * 2 + 1];
            float delta = (St - 1.0f) / fmaxf(Ct, 1.0f);
            s_tau[grp] = t + delta;
            if (fabsf(delta) >= 1e-9f) atomicOr(&s_done, 1);
        }
        __syncthreads();
        t = s_tau[grp];
        int nd = s_done;
        __syncthreads();
        if (nd == 0) break;
        if (gt == 0) s_done = 0;
        __syncthreads();
    }
    if (gt == 0) tau[row] = t;
}

// ---------------- prep: fp32 -> hi/lo bf16 ----------------
__global__ __launch_bounds__(256)
void split_convert(const float4* __restrict__ src, uint2* __restrict__ dh,
                   uint2* __restrict__ dl, int n4)
{
    int i = blockIdx.x * 256 + threadIdx.x;
    if (i >= n4) return;
    float4 v = src[i];
    uint32_t h01, l01, h23, l23;
    split2(v.x, v.y, h01, l01);
    split2(v.z, v.w, h23, l23);
    dh[i] = make_uint2(h01, h23);
    dl[i] = make_uint2(l01, l23);
}

// enc -> FIN columns [0, DMODEL)
__global__ __launch_bounds__(256)
void enc_to_fin(const float4* __restrict__ enc, bf16* __restrict__ fh, bf16* __restrict__ fl)
{
    int i = blockIdx.x * 256 + threadIdx.x;
    int row = i >> 8, cg = i & 255;
    float4 v = enc[i];
    uint32_t h01, l01, h23, l23;
    split2(v.x, v.y, h01, l01);
    split2(v.z, v.w, h23, l23);
    int o = row * (2 * DMODEL) + cg * 4;
    *reinterpret_cast<uint2*>(fh + o) = make_uint2(h01, h23);
    *reinterpret_cast<uint2*>(fl + o) = make_uint2(l01, l23);
}

// combined [bk | bv] bias
__global__ __launch_bounds__(256)
void combine_bias(const float* __restrict__ bk, const float* __restrict__ bv,
                  float* __restrict__ bkv)
{
    int i = blockIdx.x * 256 + threadIdx.x;   // over 2*DMODEL
    bkv[i] = (i < DMODEL) ? bk[i] : bv[i - DMODEL];
}

// ---------------- host launcher ----------------
extern "C" void kernel_launch(void* const* d_in, const int* in_sizes, int n_in,
                              void* d_out, int out_size)
{
    const float* enc = (const float*)d_in[0];
    const float* mem = (const float*)d_in[1];
    const float* Wq  = (const float*)d_in[2];
    const float* bq  = (const float*)d_in[3];
    const float* Wk  = (const float*)d_in[4];
    const float* bk  = (const float*)d_in[5];
    const float* Wv  = (const float*)d_in[6];
    const float* bv  = (const float*)d_in[7];
    const float* Wo  = (const float*)d_in[8];
    const float* bo  = (const float*)d_in[9];
    const float* W1  = (const float*)d_in[10];
    const float* b1  = (const float*)d_in[11];
    const float* W2  = (const float*)d_in[12];
    const float* b2  = (const float*)d_in[13];
    float* out = (float*)d_out;

    bf16 *pFINh, *pFINl, *pmemh, *pmeml, *pWqh, *pWql, *pWKVh, *pWKVl;
    bf16 *pWoh, *pWol, *pW1h, *pW1l, *pW2h, *pW2l;
    bf16 *pQh, *pQl, *pKVh, *pKVl, *pOh, *pOl, *pHh, *pHl;
    float *pS, *pTau, *pbKV;
    cudaGetSymbolAddress((void**)&pFINh, g_FINh); cudaGetSymbolAddress((void**)&pFINl, g_FINl);
    cudaGetSymbolAddress((void**)&pmemh, g_memh); cudaGetSymbolAddress((void**)&pmeml, g_meml);
    cudaGetSymbolAddress((void**)&pWqh,  g_Wqh);  cudaGetSymbolAddress((void**)&pWql,  g_Wql);
    cudaGetSymbolAddress((void**)&pWKVh, g_WKVh); cudaGetSymbolAddress((void**)&pWKVl, g_WKVl);
    cudaGetSymbolAddress((void**)&pWoh,  g_Woh);  cudaGetSymbolAddress((void**)&pWol,  g_Wol);
    cudaGetSymbolAddress((void**)&pW1h,  g_W1h);  cudaGetSymbolAddress((void**)&pW1l,  g_W1l);
    cudaGetSymbolAddress((void**)&pW2h,  g_W2h);  cudaGetSymbolAddress((void**)&pW2l,  g_W2l);
    cudaGetSymbolAddress((void**)&pQh,   g_Qh);   cudaGetSymbolAddress((void**)&pQl,   g_Ql);
    cudaGetSymbolAddress((void**)&pKVh,  g_KVh);  cudaGetSymbolAddress((void**)&pKVl,  g_KVl);
    cudaGetSymbolAddress((void**)&pOh,   g_Oh);   cudaGetSymbolAddress((void**)&pOl,   g_Ol);
    cudaGetSymbolAddress((void**)&pHh,   g_Hh);   cudaGetSymbolAddress((void**)&pHl,   g_Hl);
    cudaGetSymbolAddress((void**)&pS,    g_S);
    cudaGetSymbolAddress((void**)&pTau,  g_tau);
    cudaGetSymbolAddress((void**)&pbKV,  g_bKV);

    dim3 blk(256);
    auto cvt = [&](const float* s, bf16* h, bf16* l, int n) {
        int n4 = n / 4;
        split_convert<<<(n4 + 255) / 256, blk>>>(
            (const float4*)s, (uint2*)h, (uint2*)l, n4);
    };
    // prep conversions
    cvt(mem, pmemh, pmeml, M_KV * DMODEL);
    cvt(Wq,  pWqh,  pWql,  DMODEL * DMODEL);
    cvt(Wk,  pWKVh,                 pWKVl,                 DMODEL * DMODEL);
    cvt(Wv,  pWKVh + DMODEL*DMODEL, pWKVl + DMODEL*DMODEL, DMODEL * DMODEL);
    cvt(Wo,  pWoh,  pWol,  DMODEL * DMODEL);
    cvt(W1,  pW1h,  pW1l,  DFF * 2 * DMODEL);
    cvt(W2,  pW2h,  pW2l,  DOUT * DFF);
    enc_to_fin<<<(N_Q * DMODEL / 4) / 256, blk>>>((const float4*)enc, pFINh, pFINl);
    combine_bias<<<(2 * DMODEL) / 256, blk>>>(bk, bv, pbKV);

    constexpr int BKP = 40;
    const int DS_MAIN = 3 * (2 * 256 * BKP + 2 * 128 * BKP) * 2;              // 184320
    const int DS_PV   = (2 * 128 * BKP + 2 * DHEAD * BKP) * 2 * 2 + 512;      // 61952

    auto* kSplit = mma_gemm<256,128,32,64,1,false,false>;   // proj/Wo: split out + bias
    auto* kRelu  = mma_gemm<256,128,32,64,1,true ,false>;   // W1
    auto* kF32   = mma_gemm<256,128,32,64,0,false,false>;   // QK -> S
    auto* kOut   = mma_gemm<256,128,32,64,0,false,true >;   // W2 -> out (N=1000)
    cudaFuncSetAttribute(kSplit, cudaFuncAttributeMaxDynamicSharedMemorySize, DS_MAIN);
    cudaFuncSetAttribute(kRelu , cudaFuncAttributeMaxDynamicSharedMemorySize, DS_MAIN);
    cudaFuncSetAttribute(kF32  , cudaFuncAttributeMaxDynamicSharedMemorySize, DS_MAIN);
    cudaFuncSetAttribute(kOut  , cudaFuncAttributeMaxDynamicSharedMemorySize, DS_MAIN);
    cudaFuncSetAttribute(pv_gemm, cudaFuncAttributeMaxDynamicSharedMemorySize, DS_PV);

    dim3 blk512(512);

    // Q = enc @ Wq^T + bq  (A = FIN cols [0,1024), lda 2048)
    kSplit<<<dim3(DMODEL/128, N_Q/256, 1), blk512, DS_MAIN>>>(
        N_Q, DMODEL, DMODEL, pFINh, pFINl, 2*DMODEL, 0, pWqh, pWql, DMODEL, 0,
        nullptr, pQh, pQl, DMODEL, 0, bq, 1.0f);
    // KV = mem @ [Wk;Wv]^T + [bk;bv]   [4096, 2048]
    kSplit<<<dim3(2*DMODEL/128, M_KV/256, 1), blk512, DS_MAIN>>>(
        M_KV, 2*DMODEL, DMODEL, pmemh, pmeml, DMODEL, 0, pWKVh, pWKVl, DMODEL, 0,
        nullptr, pKVh, pKVl, 2*DMODEL, 0, pbKV, 1.0f);
    // S[h] = (Q_h @ K_h^T) / 32   (K = KV cols [0,1024), ldb 2048)
    kF32<<<dim3(M_KV/128, N_Q/256, NHEADS), blk512, DS_MAIN>>>(
        N_Q, M_KV, DHEAD, pQh, pQl, DMODEL, (long long)DHEAD,
        pKVh, pKVl, 2*DMODEL, (long long)DHEAD,
        pS, nullptr, nullptr, M_KV, (long long)N_Q * M_KV, nullptr, 0.03125f);
    // sparsemax: S -> tau  (4 rows per block)
    sparsemax_tau<<<NHEADS * N_Q / 4, blk>>>(pS, pTau);
    // O_h = max(S_h - tau, 0) @ V_h
    pv_gemm<<<dim3(N_Q/128, NHEADS), blk, DS_PV>>>(pS, pTau, pKVh, pKVl, pOh, pOl);
    // FIN[:, 1024:2048] = O @ Wo^T + bo
    kSplit<<<dim3(DMODEL/128, N_Q/256, 1), blk512, DS_MAIN>>>(
        N_Q, DMODEL, DMODEL, pOh, pOl, DMODEL, 0, pWoh, pWol, DMODEL, 0,
        nullptr, pFINh + DMODEL, pFINl + DMODEL, 2*DMODEL, 0, bo, 1.0f);
    // H = relu(FIN @ W1^T + b1)
    kRelu<<<dim3(DFF/128, N_Q/256, 1), blk512, DS_MAIN>>>(
        N_Q, DFF, 2*DMODEL, pFINh, pFINl, 2*DMODEL, 0, pW1h, pW1l, 2*DMODEL, 0,
        nullptr, pHh, pHl, DFF, 0, b1, 1.0f);
    // OUT = H @ W2^T + b2  (N = 1000)
    kOut<<<dim3((DOUT + 127)/128, N_Q/256, 1), blk512, DS_MAIN>>>(
        N_Q, DOUT, DFF, pHh, pHl, DFF, 0, pW2h, pW2l, DFF, 0,
        out, nullptr, nullptr, DOUT, 0, b2, 1.0f);
}

// round 8
// speedup vs baseline: 1.0793x; 1.0793x over previous
#include <cuda_runtime.h>
#include <cuda_bf16.h>
#include <cstdint>
#include <math.h>

// Problem dims (fixed by the dataset)
#define N_Q    2048
#define M_KV   4096
#define DMODEL 1024
#define NHEADS 16
#define DHEAD  64
#define DFF    4096
#define DOUT   1000

typedef __nv_bfloat16 bf16;

// ---------------- scratch (device globals; no allocation allowed) ----------------
__device__ bf16 g_FINh[N_Q * 2 * DMODEL],  g_FINl[N_Q * 2 * DMODEL];
__device__ bf16 g_memh[M_KV * DMODEL],     g_meml[M_KV * DMODEL];
__device__ bf16 g_Wqh[DMODEL * DMODEL],    g_Wql[DMODEL * DMODEL];
__device__ bf16 g_WKVh[2 * DMODEL * DMODEL], g_WKVl[2 * DMODEL * DMODEL];  // [Wk; Wv]
__device__ bf16 g_Woh[DMODEL * DMODEL],    g_Wol[DMODEL * DMODEL];
__device__ bf16 g_W1h[DFF * 2 * DMODEL],   g_W1l[DFF * 2 * DMODEL];
__device__ bf16 g_W2h[DOUT * DFF],         g_W2l[DOUT * DFF];
__device__ bf16 g_Qh[N_Q * DMODEL],        g_Ql[N_Q * DMODEL];
__device__ bf16 g_KVh[M_KV * 2 * DMODEL],  g_KVl[M_KV * 2 * DMODEL];      // K | V
__device__ float g_S[(size_t)NHEADS * N_Q * M_KV];
__device__ float g_tau[NHEADS * N_Q];
__device__ bf16 g_Oh[N_Q * DMODEL],        g_Ol[N_Q * DMODEL];
__device__ bf16 g_Hh[N_Q * DFF],           g_Hl[N_Q * DFF];

// ---------------- helpers ----------------
__device__ __forceinline__ uint32_t smem_u32(const void* p) {
    uint32_t a;
    asm("{ .reg .u64 t; cvta.to.shared.u64 t, %1; cvt.u32.u64 %0, t; }" : "=r"(a) : "l"(p));
    return a;
}
__device__ __forceinline__ void ldmx4(uint32_t* r, uint32_t a) {
    asm volatile("ldmatrix.sync.aligned.m8n8.x4.shared.b16 {%0,%1,%2,%3}, [%4];"
                 : "=r"(r[0]), "=r"(r[1]), "=r"(r[2]), "=r"(r[3]) : "r"(a));
}
__device__ __forceinline__ void mma_bf16(float* d, const uint32_t* a, uint32_t b0, uint32_t b1) {
    asm volatile("mma.sync.aligned.m16n8k16.row.col.f32.bf16.bf16.f32 "
                 "{%0,%1,%2,%3}, {%4,%5,%6,%7}, {%8,%9}, {%0,%1,%2,%3};"
                 : "+f"(d[0]), "+f"(d[1]), "+f"(d[2]), "+f"(d[3])
                 : "r"(a[0]), "r"(a[1]), "r"(a[2]), "r"(a[3]), "r"(b0), "r"(b1));
}
__device__ __forceinline__ void cpa16(uint32_t s, const void* g) {
    asm volatile("cp.async.cg.shared.global [%0], [%1], 16;" :: "r"(s), "l"(g));
}
__device__ __forceinline__ void cpa16z(uint32_t s, const void* g, bool ok) {
    int sz = ok ? 16 : 0;
    asm volatile("cp.async.cg.shared.global [%0], [%1], 16, %2;" :: "r"(s), "l"(g), "r"(sz));
}
#define CPA_COMMIT() asm volatile("cp.async.commit_group;" ::: "memory")
#define CPA_WAIT0()  asm volatile("cp.async.wait_group 0;" ::: "memory")

// split fp32 pair into packed bf16 hi + bf16 residual
__device__ __forceinline__ void split2(float a, float b, uint32_t& h, uint32_t& l) {
    __nv_bfloat162 hh = __floats2bfloat162_rn(a, b);
    float2 hf = __bfloat1622float2(hh);
    __nv_bfloat162 ll = __floats2bfloat162_rn(a - hf.x, b - hf.y);
    h = *reinterpret_cast<uint32_t*>(&hh);
    l = *reinterpret_cast<uint32_t*>(&ll);
}

// ====================== async double-buffered split-bf16 MMA GEMM ======================
// C = alpha * A @ B^T + bias (+ReLU).  A,B pre-split bf16 hi/lo, NT form.
// EPI=0: write fp32 to Cf.  EPI=1: write split hi/lo to Chi/Clo.
// Warp tile 32x64: MI=2, NI2=4, NA=8 -> ldmx/MMA = 0.25
template<int BM, int BN, int WM, int WN, int EPI, bool RELU, bool NGUARD>
__global__ __launch_bounds__(256, 2)
void mma_gemm(int M, int N, int K,
              const bf16* __restrict__ Ah, const bf16* __restrict__ Al, int lda, long long sAz,
              const bf16* __restrict__ Bh, const bf16* __restrict__ Bl, int ldb, long long sBz,
              float* __restrict__ Cf, bf16* __restrict__ Chi, bf16* __restrict__ Clo,
              long long ldc, long long sCz,
              const float* __restrict__ bias, float alpha)
{
    constexpr int BK = 32, BKP = 40;               // 80B pitch: 16B-aligned, ldmatrix conflict-free
    constexpr int WNC = BN / WN;
    constexpr int MI = WM / 16, NI2 = WN / 16, NA = WN / 8;
    constexpr int SA = BM * BKP, SB = BN * BKP;
    constexpr int STAGE_BYTES = (2 * SA + 2 * SB) * 2;

    extern __shared__ __align__(16) char smem[];
    const uint32_t uS = smem_u32(smem);

    const int tid = threadIdx.x, wid = tid >> 5, lane = tid & 31;
    Ah += (long long)blockIdx.z * sAz;  Al += (long long)blockIdx.z * sAz;
    Bh += (long long)blockIdx.z * sBz;  Bl += (long long)blockIdx.z * sBz;
    const long long coff = (long long)blockIdx.z * sCz;
    const int row0 = blockIdx.y * BM;
    const int col0 = blockIdx.x * BN;
    const int wm0 = (wid / WNC) * WM;
    const int wn0 = (wid % WNC) * WN;

    float acc[MI][NA][4];
    #pragma unroll
    for (int i = 0; i < MI; i++)
        #pragma unroll
        for (int j = 0; j < NA; j++)
            #pragma unroll
            for (int q = 0; q < 4; q++) acc[i][j][q] = 0.f;

    auto loadT = [&](int stage, int kt) {
        uint32_t base = uS + stage * STAGE_BYTES;
        #pragma unroll
        for (int i = 0; i < (BM * 4) / 256; i++) {
            int ch = tid + i * 256, r = ch >> 2, q = ch & 3;
            cpa16(base + r * 80 + q * 16,            Ah + (size_t)(row0 + r) * lda + kt + q * 8);
            cpa16(base + SA * 2 + r * 80 + q * 16,   Al + (size_t)(row0 + r) * lda + kt + q * 8);
        }
        #pragma unroll
        for (int i = 0; i < (BN * 4) / 256; i++) {
            int ch = tid + i * 256, r = ch >> 2, q = ch & 3;
            bool ok = !NGUARD || (col0 + r) < N;
            cpa16z(base + 2 * SA * 2 + r * 80 + q * 16,
                   Bh + (size_t)(col0 + r) * ldb + kt + q * 8, ok);
            cpa16z(base + (2 * SA + SB) * 2 + r * 80 + q * 16,
                   Bl + (size_t)(col0 + r) * ldb + kt + q * 8, ok);
        }
    };
    auto compute = [&](int stage) {
        uint32_t bA = uS + stage * STAGE_BYTES;
        uint32_t bAh = bA, bAl = bA + SA * 2, bBh = bA + 2 * SA * 2, bBl = bA + (2 * SA + SB) * 2;
        const int lr = lane & 15, lc = (lane >> 4) * 8;
        #pragma unroll
        for (int kk = 0; kk < BK; kk += 16) {
            uint32_t bh[NI2][4], bl[NI2][4];
            #pragma unroll
            for (int ni = 0; ni < NI2; ni++) {
                uint32_t off = (uint32_t)((wn0 + ni * 16 + lr) * 80 + (kk + lc) * 2);
                ldmx4(bh[ni], bBh + off);
                ldmx4(bl[ni], bBl + off);
            }
            #pragma unroll
            for (int mi = 0; mi < MI; mi++) {
                uint32_t ah[4], al[4];
                uint32_t off = (uint32_t)((wm0 + mi * 16 + lr) * 80 + (kk + lc) * 2);
                ldmx4(ah, bAh + off);
                ldmx4(al, bAl + off);
                #pragma unroll
                for (int na = 0; na < NA; na++) {
                    int ni = na >> 1, sel = na & 1;
                    uint32_t b0h = bh[ni][sel], b1h = bh[ni][sel + 2];
                    mma_bf16(acc[mi][na], ah, b0h, b1h);
                    mma_bf16(acc[mi][na], al, b0h, b1h);
                    mma_bf16(acc[mi][na], ah, bl[ni][sel], bl[ni][sel + 2]);
                }
            }
        }
    };

    const int tiles = K / BK;
    loadT(0, 0);
    CPA_COMMIT();
    for (int t = 0; t < tiles; t++) {
        int cur = t & 1;
        CPA_WAIT0();
        __syncthreads();
        if (t + 1 < tiles) loadT((t + 1) & 1, (t + 1) * BK);
        CPA_COMMIT();
        compute(cur);
    }

    // ---------------- epilogue ----------------
    const int lr4 = lane >> 2, lc2 = (lane & 3) * 2;
    #pragma unroll
    for (int mi = 0; mi < MI; mi++) {
        #pragma unroll
        for (int na = 0; na < NA; na++) {
            float* d = acc[mi][na];
            int col = col0 + wn0 + na * 8 + lc2;
            int r0 = row0 + wm0 + mi * 16 + lr4;
            float bb0 = 0.f, bb1 = 0.f;
            if (bias) {
                if (!NGUARD || col     < N) bb0 = bias[col];
                if (!NGUARD || col + 1 < N) bb1 = bias[col + 1];
            }
            float v0 = d[0] * alpha + bb0, v1 = d[1] * alpha + bb1;
            float v2 = d[2] * alpha + bb0, v3 = d[3] * alpha + bb1;
            if (RELU) {
                v0 = fmaxf(v0, 0.f); v1 = fmaxf(v1, 0.f);
                v2 = fmaxf(v2, 0.f); v3 = fmaxf(v3, 0.f);
            }
            if (EPI == 0) {
                long long b0i = (long long)r0 * ldc + col + coff;
                long long b1i = (long long)(r0 + 8) * ldc + col + coff;
                if (!NGUARD || col + 1 < N) {
                    *reinterpret_cast<float2*>(Cf + b0i) = make_float2(v0, v1);
                    *reinterpret_cast<float2*>(Cf + b1i) = make_float2(v2, v3);
                } else if (col < N) {
                    Cf[b0i] = v0;
                    Cf[b1i] = v2;
                }
            } else {
                uint32_t h01, l01, h23, l23;
                split2(v0, v1, h01, l01);
                split2(v2, v3, h23, l23);
                long long b0i = (long long)r0 * ldc + col + coff;
                long long b1i = (long long)(r0 + 8) * ldc + col + coff;
                *reinterpret_cast<uint32_t*>(Chi + b0i) = h01;
                *reinterpret_cast<uint32_t*>(Clo + b0i) = l01;
                *reinterpret_cast<uint32_t*>(Chi + b1i) = h23;
                *reinterpret_cast<uint32_t*>(Clo + b1i) = l23;
            }
        }
    }
}

// ====================== PV: O_h = sparsemax(S_h) @ V_h, tau applied on the fly ======================
__global__ __launch_bounds__(256, 2)
void pv_gemm(const float* __restrict__ S, const float* __restrict__ tau,
             const bf16* __restrict__ KVh, const bf16* __restrict__ KVl,
             bf16* __restrict__ Oh, bf16* __restrict__ Ol)
{
    constexpr int BM = 128, BK = 32, BKP = 40;
    constexpr int SA = BM * BKP, SB = DHEAD * BKP;
    constexpr int STAGE = (2 * SA + 2 * SB) * 2;

    extern __shared__ __align__(16) char smem[];
    float* sTau = reinterpret_cast<float*>(smem + 2 * STAGE);

    const int tid = threadIdx.x, wid = tid >> 5, lane = tid & 31;
    const int head = blockIdx.y;
    const int row0 = blockIdx.x * BM;
    const float* Sb  = S + (size_t)head * N_Q * M_KV + (size_t)row0 * M_KV;
    const float* tb  = tau + head * N_Q + row0;
    const bf16* Vhb  = KVh + DMODEL + head * DHEAD;   // V half of KV buffer
    const bf16* Vlb  = KVl + DMODEL + head * DHEAD;

    if (tid < BM) sTau[tid] = tb[tid];
    __syncthreads();

    const int wm0 = (wid >> 2) * 64;
    const int wn0 = (wid & 3) * 16;
    constexpr int MI = 4, NA = 2;

    float acc[MI][NA][4];
    #pragma unroll
    for (int i = 0; i < MI; i++)
        #pragma unroll
        for (int j = 0; j < NA; j++)
            #pragma unroll
            for (int q = 0; q < 4; q++) acc[i][j][q] = 0.f;

    float4 aReg[4];
    uint4 bhReg, blReg;
    const int a_r = tid >> 3, a_c = (tid & 7) * 4;
    const int b_k = tid >> 3, b_c = (tid & 7) * 8;

    auto ldRegs = [&](int kt) {
        #pragma unroll
        for (int i = 0; i < 4; i++)
            aReg[i] = *reinterpret_cast<const float4*>(Sb + (size_t)(a_r + i * 32) * M_KV + kt + a_c);
        bhReg = *reinterpret_cast<const uint4*>(Vhb + (size_t)(kt + b_k) * 2 * DMODEL + b_c);
        blReg = *reinterpret_cast<const uint4*>(Vlb + (size_t)(kt + b_k) * 2 * DMODEL + b_c);
    };
    auto sts = [&](int st) {
        bf16* base = reinterpret_cast<bf16*>(smem + st * STAGE);
        bf16* Ahs = base;
        bf16* Als = base + SA;
        bf16* Bhs = base + 2 * SA;
        bf16* Bls = base + 2 * SA + SB;
        #pragma unroll
        for (int i = 0; i < 4; i++) {
            int r = a_r + i * 32;
            float tv = sTau[r];
            float p0 = fmaxf(aReg[i].x - tv, 0.f), p1 = fmaxf(aReg[i].y - tv, 0.f);
            float p2 = fmaxf(aReg[i].z - tv, 0.f), p3 = fmaxf(aReg[i].w - tv, 0.f);
            uint32_t h01, l01, h23, l23;
            split2(p0, p1, h01, l01);
            split2(p2, p3, h23, l23);
            *reinterpret_cast<uint2*>(Ahs + r * BKP + a_c) = make_uint2(h01, h23);
            *reinterpret_cast<uint2*>(Als + r * BKP + a_c) = make_uint2(l01, l23);
        }
        bf16 th[8], tl[8];
        *reinterpret_cast<uint4*>(th) = bhReg;
        *reinterpret_cast<uint4*>(tl) = blReg;
        #pragma unroll
        for (int j = 0; j < 8; j++) {
            Bhs[(b_c + j) * BKP + b_k] = th[j];
            Bls[(b_c + j) * BKP + b_k] = tl[j];
        }
    };
    auto compute = [&](int st) {
        uint32_t base = smem_u32(smem) + st * STAGE;
        uint32_t uAh = base, uAl = base + SA * 2, uBh = base + 2 * SA * 2, uBl = base + (2 * SA + SB) * 2;
        const int lr = lane & 15, lc = (lane >> 4) * 8;
        #pragma unroll
        for (int kk = 0; kk < BK; kk += 16) {
            uint32_t bh[4], bl[4];
            uint32_t boff = (uint32_t)((wn0 + lr) * BKP + kk + lc) * 2;
            ldmx4(bh, uBh + boff);
            ldmx4(bl, uBl + boff);
            #pragma unroll
            for (int mi = 0; mi < MI; mi++) {
                uint32_t ah[4], al[4];
                uint32_t aoff = (uint32_t)((wm0 + mi * 16 + lr) * BKP + kk + lc) * 2;
                ldmx4(ah, uAh + aoff);
                ldmx4(al, uAl + aoff);
                #pragma unroll
                for (int na = 0; na < NA; na++) {
                    uint32_t b0 = bh[na], b1 = bh[na + 2];
                    mma_bf16(acc[mi][na], ah, b0, b1);
                    mma_bf16(acc[mi][na], al, b0, b1);
                    mma_bf16(acc[mi][na], ah, bl[na], bl[na + 2]);
                }
            }
        }
    };

    const int tiles = M_KV / BK;
    ldRegs(0);
    sts(0);
    for (int t = 0; t < tiles; t++) {
        __syncthreads();
        if (t + 1 < tiles) ldRegs((t + 1) * BK);
        compute(t & 1);
        if (t + 1 < tiles) sts((t + 1) & 1);
    }

    const int lr4 = lane >> 2, lc2 = (lane & 3) * 2;
    #pragma unroll
    for (int mi = 0; mi < MI; mi++) {
        #pragma unroll
        for (int na = 0; na < NA; na++) {
            float* d = acc[mi][na];
            int col = head * DHEAD + wn0 + na * 8 + lc2;
            int r0 = row0 + wm0 + mi * 16 + lr4;
            uint32_t h01, l01, h23, l23;
            split2(d[0], d[1], h01, l01);
            split2(d[2], d[3], h23, l23);
            *reinterpret_cast<uint32_t*>(Oh + (size_t)r0 * DMODEL + col) = h01;
            *reinterpret_cast<uint32_t*>(Ol + (size_t)r0 * DMODEL + col) = l01;
            *reinterpret_cast<uint32_t*>(Oh + (size_t)(r0 + 8) * DMODEL + col) = h23;
            *reinterpret_cast<uint32_t*>(Ol + (size_t)(r0 + 8) * DMODEL + col) = l23;
        }
    }
}

// ---------------- sparsemax tau: 4 rows per 256-thread block, 64 threads/row ----------------
__global__ __launch_bounds__(256)
void sparsemax_tau(const float* __restrict__ S, float* __restrict__ tau)
{
    const int tid = threadIdx.x;
    const int grp = tid >> 6;
    const int gt  = tid & 63;
    const int lane = tid & 31;
    const int wid = tid >> 5;
    const long long row = (long long)blockIdx.x * 4 + grp;

    const float4* z4 = reinterpret_cast<const float4*>(S + row * (long long)M_KV);
    float4 v4[16];
    #pragma unroll
    for (int j = 0; j < 16; j++) v4[j] = z4[gt + j * 64];
    float* v = reinterpret_cast<float*>(v4);

    __shared__ float red_s[8], red_c[8];
    __shared__ float s_tau[4];
    __shared__ int   s_done;

    float m = v[0];
    #pragma unroll
    for (int i = 1; i < 64; i++) m = fmaxf(m, v[i]);
    #pragma unroll
    for (int o = 16; o > 0; o >>= 1) m = fmaxf(m, __shfl_xor_sync(0xffffffffu, m, o));
    if (lane == 0) red_s[wid] = m;
    if (tid == 0) s_done = 0;
    __syncthreads();
    if (gt == 0) s_tau[grp] = fmaxf(red_s[grp * 2], red_s[grp * 2 + 1]) - 1.0f;
    __syncthreads();
    float t = s_tau[grp];

    for (int it = 0; it < 64; ++it) {
        float s = 0.f, c = 0.f;
        #pragma unroll
        for (int i = 0; i < 64; i++) {
            float d = v[i] - t;
            if (d > 0.f) { s += d; c += 1.f; }
        }
        #pragma unroll
        for (int o = 16; o > 0; o >>= 1) {
            s += __shfl_xor_sync(0xffffffffu, s, o);
            c += __shfl_xor_sync(0xffffffffu, c, o);
        }
        if (lane == 0) { red_s[wid] = s; red_c[wid] = c; }
        __syncthreads();
        if (gt == 0) {
            float St = red_s[grp * 2] + red_s[grp * 2 + 1];
            float Ct = red_c[grp * 2] + red_c[grp * 2 + 1];
            float delta = (St - 1.0f) / fmaxf(Ct, 1.0f);
            s_tau[grp] = t + delta;
            if (fabsf(delta) >= 1e-9f) atomicOr(&s_done, 1);
        }
        __syncthreads();
        t = s_tau[grp];
        int nd = s_done;
        __syncthreads();
        if (nd == 0) break;
        if (gt == 0) s_done = 0;
        __syncthreads();
    }
    if (gt == 0) tau[row] = t;
}

// ---------------- prep: fp32 -> hi/lo bf16 ----------------
__global__ __launch_bounds__(256)
void split_convert(const float4* __restrict__ src, uint2* __restrict__ dh,
                   uint2* __restrict__ dl, int n4)
{
    int i = blockIdx.x * 256 + threadIdx.x;
    if (i >= n4) return;
    float4 v = src[i];
    uint32_t h01, l01, h23, l23;
    split2(v.x, v.y, h01, l01);
    split2(v.z, v.w, h23, l23);
    dh[i] = make_uint2(h01, h23);
    dl[i] = make_uint2(l01, l23);
}

// enc -> FIN columns [0, DMODEL)
__global__ __launch_bounds__(256)
void enc_to_fin(const float4* __restrict__ enc, bf16* __restrict__ fh, bf16* __restrict__ fl)
{
    int i = blockIdx.x * 256 + threadIdx.x;
    int row = i >> 8, cg = i & 255;
    float4 v = enc[i];
    uint32_t h01, l01, h23, l23;
    split2(v.x, v.y, h01, l01);
    split2(v.z, v.w, h23, l23);
    int o = row * (2 * DMODEL) + cg * 4;
    *reinterpret_cast<uint2*>(fh + o) = make_uint2(h01, h23);
    *reinterpret_cast<uint2*>(fl + o) = make_uint2(l01, l23);
}

// ---------------- host launcher ----------------
extern "C" void kernel_launch(void* const* d_in, const int* in_sizes, int n_in,
                              void* d_out, int out_size)
{
    const float* enc = (const float*)d_in[0];
    const float* mem = (const float*)d_in[1];
    const float* Wq  = (const float*)d_in[2];
    const float* bq  = (const float*)d_in[3];
    const float* Wk  = (const float*)d_in[4];
    const float* bk  = (const float*)d_in[5];
    const float* Wv  = (const float*)d_in[6];
    const float* bv  = (const float*)d_in[7];
    const float* Wo  = (const float*)d_in[8];
    const float* bo  = (const float*)d_in[9];
    const float* W1  = (const float*)d_in[10];
    const float* b1  = (const float*)d_in[11];
    const float* W2  = (const float*)d_in[12];
    const float* b2  = (const float*)d_in[13];
    float* out = (float*)d_out;

    bf16 *pFINh, *pFINl, *pmemh, *pmeml, *pWqh, *pWql, *pWKVh, *pWKVl;
    bf16 *pWoh, *pWol, *pW1h, *pW1l, *pW2h, *pW2l;
    bf16 *pQh, *pQl, *pKVh, *pKVl, *pOh, *pOl, *pHh, *pHl;
    float *pS, *pTau;
    cudaGetSymbolAddress((void**)&pFINh, g_FINh); cudaGetSymbolAddress((void**)&pFINl, g_FINl);
    cudaGetSymbolAddress((void**)&pmemh, g_memh); cudaGetSymbolAddress((void**)&pmeml, g_meml);
    cudaGetSymbolAddress((void**)&pWqh,  g_Wqh);  cudaGetSymbolAddress((void**)&pWql,  g_Wql);
    cudaGetSymbolAddress((void**)&pWKVh, g_WKVh); cudaGetSymbolAddress((void**)&pWKVl, g_WKVl);
    cudaGetSymbolAddress((void**)&pWoh,  g_Woh);  cudaGetSymbolAddress((void**)&pWol,  g_Wol);
    cudaGetSymbolAddress((void**)&pW1h,  g_W1h);  cudaGetSymbolAddress((void**)&pW1l,  g_W1l);
    cudaGetSymbolAddress((void**)&pW2h,  g_W2h);  cudaGetSymbolAddress((void**)&pW2l,  g_W2l);
    cudaGetSymbolAddress((void**)&pQh,   g_Qh);   cudaGetSymbolAddress((void**)&pQl,   g_Ql);
    cudaGetSymbolAddress((void**)&pKVh,  g_KVh);  cudaGetSymbolAddress((void**)&pKVl,  g_KVl);
    cudaGetSymbolAddress((void**)&pOh,   g_Oh);   cudaGetSymbolAddress((void**)&pOl,   g_Ol);
    cudaGetSymbolAddress((void**)&pHh,   g_Hh);   cudaGetSymbolAddress((void**)&pHl,   g_Hl);
    cudaGetSymbolAddress((void**)&pS,    g_S);
    cudaGetSymbolAddress((void**)&pTau,  g_tau);

    dim3 blk(256);
    auto cvt = [&](const float* s, bf16* h, bf16* l, int n) {
        int n4 = n / 4;
        split_convert<<<(n4 + 255) / 256, blk>>>(
            (const float4*)s, (uint2*)h, (uint2*)l, n4);
    };

    constexpr int BKP = 40;
    const int DS_MAIN = (2 * 128 * BKP + 2 * 128 * BKP) * 2 * 2;              // 81920
    const int DS_PV   = (2 * 128 * BKP + 2 * DHEAD * BKP) * 2 * 2 + 512;      // 61952

    auto* kSplit = mma_gemm<128,128,32,64,1,false,false>;   // proj/Wo: split out + bias
    auto* kRelu  = mma_gemm<128,128,32,64,1,true ,false>;   // W1
    auto* kF32   = mma_gemm<128,128,32,64,0,false,false>;   // QK -> S
    auto* kOut   = mma_gemm<128,128,32,64,0,false,true >;   // W2 -> out (N=1000)
    cudaFuncSetAttribute(kSplit, cudaFuncAttributeMaxDynamicSharedMemorySize, DS_MAIN);
    cudaFuncSetAttribute(kRelu , cudaFuncAttributeMaxDynamicSharedMemorySize, DS_MAIN);
    cudaFuncSetAttribute(kF32  , cudaFuncAttributeMaxDynamicSharedMemorySize, DS_MAIN);
    cudaFuncSetAttribute(kOut  , cudaFuncAttributeMaxDynamicSharedMemorySize, DS_MAIN);
    cudaFuncSetAttribute(pv_gemm, cudaFuncAttributeMaxDynamicSharedMemorySize, DS_PV);

    // ---- launch order arranged so launch index 5 (ncu -s 5 -c 1) = K-proj GEMM ----
    // 0: enc -> FIN
    enc_to_fin<<<(N_Q * DMODEL / 4) / 256, blk>>>((const float4*)enc, pFINh, pFINl);
    // 1: Wq
    cvt(Wq,  pWqh,  pWql,  DMODEL * DMODEL);
    // 2: mem
    cvt(mem, pmemh, pmeml, M_KV * DMODEL);
    // 3: Wk -> WKV[0]
    cvt(Wk,  pWKVh, pWKVl, DMODEL * DMODEL);
    // 4: Q = enc @ Wq^T + bq  (A = FIN cols [0,1024), lda 2048)
    kSplit<<<dim3(DMODEL/128, N_Q/128, 1), blk, DS_MAIN>>>(
        N_Q, DMODEL, DMODEL, pFINh, pFINl, 2*DMODEL, 0, pWqh, pWql, DMODEL, 0,
        nullptr, pQh, pQl, DMODEL, 0, bq, 1.0f);
    // 5: K = mem @ Wk^T + bk -> KV cols [0,1024)          <-- profiled by ncu -s 5
    kSplit<<<dim3(DMODEL/128, M_KV/128, 1), blk, DS_MAIN>>>(
        M_KV, DMODEL, DMODEL, pmemh, pmeml, DMODEL, 0, pWKVh, pWKVl, DMODEL, 0,
        nullptr, pKVh, pKVl, 2*DMODEL, 0, bk, 1.0f);
    // 6: Wv -> WKV[1]
    cvt(Wv,  pWKVh + DMODEL*DMODEL, pWKVl + DMODEL*DMODEL, DMODEL * DMODEL);
    // 7: V = mem @ Wv^T + bv -> KV cols [1024,2048)
    kSplit<<<dim3(DMODEL/128, M_KV/128, 1), blk, DS_MAIN>>>(
        M_KV, DMODEL, DMODEL, pmemh, pmeml, DMODEL, 0,
        pWKVh + DMODEL*DMODEL, pWKVl + DMODEL*DMODEL, DMODEL, 0,
        nullptr, pKVh + DMODEL, pKVl + DMODEL, 2*DMODEL, 0, bv, 1.0f);
    // 8: S[h] = (Q_h @ K_h^T) / 32
    kF32<<<dim3(M_KV/128, N_Q/128, NHEADS), blk, DS_MAIN>>>(
        N_Q, M_KV, DHEAD, pQh, pQl, DMODEL, (long long)DHEAD,
        pKVh, pKVl, 2*DMODEL, (long long)DHEAD,
        pS, nullptr, nullptr, M_KV, (long long)N_Q * M_KV, nullptr, 0.03125f);
    // 9: Wo
    cvt(Wo,  pWoh,  pWol,  DMODEL * DMODEL);
    // 10: sparsemax: S -> tau  (4 rows per block)
    sparsemax_tau<<<NHEADS * N_Q / 4, blk>>>(pS, pTau);
    // 11: O_h = max(S_h - tau, 0) @ V_h
    pv_gemm<<<dim3(N_Q/128, NHEADS), blk, DS_PV>>>(pS, pTau, pKVh, pKVl, pOh, pOl);
    // 12: FIN[:, 1024:2048] = O @ Wo^T + bo
    kSplit<<<dim3(DMODEL/128, N_Q/128, 1), blk, DS_MAIN>>>(
        N_Q, DMODEL, DMODEL, pOh, pOl, DMODEL, 0, pWoh, pWol, DMODEL, 0,
        nullptr, pFINh + DMODEL, pFINl + DMODEL, 2*DMODEL, 0, bo, 1.0f);
    // 13: W1
    cvt(W1,  pW1h,  pW1l,  DFF * 2 * DMODEL);
    // 14: H = relu(FIN @ W1^T + b1)
    kRelu<<<dim3(DFF/128, N_Q/128, 1), blk, DS_MAIN>>>(
        N_Q, DFF, 2*DMODEL, pFINh, pFINl, 2*DMODEL, 0, pW1h, pW1l, 2*DMODEL, 0,
        nullptr, pHh, pHl, DFF, 0, b1, 1.0f);
    // 15: W2
    cvt(W2,  pW2h,  pW2l,  DOUT * DFF);
    // 16: OUT = H @ W2^T + b2  (N = 1000)
    kOut<<<dim3((DOUT + 127)/128, N_Q/128, 1), blk, DS_MAIN>>>(
        N_Q, DOUT, DFF, pHh, pHl, DFF, 0, pW2h, pW2l, DFF, 0,
        out, nullptr, nullptr, DOUT, 0, b2, 1.0f);
}

// round 10
// speedup vs baseline: 1.1901x; 1.1026x over previous
#include <cuda_runtime.h>
#include <cuda_bf16.h>
#include <cuda_fp16.h>
#include <cstdint>
#include <math.h>

// Problem dims (fixed by the dataset)
#define N_Q    2048
#define M_KV   4096
#define DMODEL 1024
#define NHEADS 16
#define DHEAD  64
#define DFF    4096
#define DOUT   1000

typedef __nv_bfloat16 bf16;

// ---------------- scratch (device globals; no allocation allowed) ----------------
__device__ uint16_t g_FINf[N_Q * 2 * DMODEL];                         // fp16 single
__device__ uint16_t g_ENCh[N_Q * DMODEL],  g_ENCl[N_Q * DMODEL];      // bf16 split
__device__ uint16_t g_memh[M_KV * DMODEL], g_meml[M_KV * DMODEL];     // bf16 split
__device__ uint16_t g_Wqh[DMODEL*DMODEL],  g_Wql[DMODEL*DMODEL];      // bf16
__device__ uint16_t g_Wkh[DMODEL*DMODEL],  g_Wkl[DMODEL*DMODEL];      // bf16
__device__ uint16_t g_Wvh[DMODEL*DMODEL],  g_Wvl[DMODEL*DMODEL];      // bf16 split
__device__ uint16_t g_Woh[DMODEL*DMODEL],  g_Wol[DMODEL*DMODEL];      // bf16
__device__ uint16_t g_W1h[DFF*2*DMODEL],   g_W1l[DFF*2*DMODEL];       // fp16 split
__device__ uint16_t g_W2h[DOUT*DFF],       g_W2l[DOUT*DFF];           // fp16 split
__device__ uint16_t g_Qh[N_Q*DMODEL],      g_Ql[N_Q*DMODEL];          // bf16
__device__ uint16_t g_Kh[M_KV*DMODEL],     g_Kl[M_KV*DMODEL];         // bf16
__device__ uint16_t g_Vfh[M_KV*DMODEL],    g_Vfl[M_KV*DMODEL];        // fp16 split (from fp32 acc)
__device__ float    g_S[(size_t)NHEADS * N_Q * M_KV];
__device__ float    g_tau[NHEADS * N_Q];
__device__ uint16_t g_Oh[N_Q*DMODEL],      g_Ol[N_Q*DMODEL];          // bf16
__device__ uint16_t g_Hf[N_Q*DFF];                                    // fp16 single

// ---------------- helpers ----------------
__device__ __forceinline__ uint32_t smem_u32(const void* p) {
    uint32_t a;
    asm("{ .reg .u64 t; cvta.to.shared.u64 t, %1; cvt.u32.u64 %0, t; }" : "=r"(a) : "l"(p));
    return a;
}
__device__ __forceinline__ void ldmx4(uint32_t* r, uint32_t a) {
    asm volatile("ldmatrix.sync.aligned.m8n8.x4.shared.b16 {%0,%1,%2,%3}, [%4];"
                 : "=r"(r[0]), "=r"(r[1]), "=r"(r[2]), "=r"(r[3]) : "r"(a));
}
__device__ __forceinline__ void mma_bf16(float* d, const uint32_t* a, uint32_t b0, uint32_t b1) {
    asm volatile("mma.sync.aligned.m16n8k16.row.col.f32.bf16.bf16.f32 "
                 "{%0,%1,%2,%3}, {%4,%5,%6,%7}, {%8,%9}, {%0,%1,%2,%3};"
                 : "+f"(d[0]), "+f"(d[1]), "+f"(d[2]), "+f"(d[3])
                 : "r"(a[0]), "r"(a[1]), "r"(a[2]), "r"(a[3]), "r"(b0), "r"(b1));
}
__device__ __forceinline__ void mma_f16(float* d, const uint32_t* a, uint32_t b0, uint32_t b1) {
    asm volatile("mma.sync.aligned.m16n8k16.row.col.f32.f16.f16.f32 "
                 "{%0,%1,%2,%3}, {%4,%5,%6,%7}, {%8,%9}, {%0,%1,%2,%3};"
                 : "+f"(d[0]), "+f"(d[1]), "+f"(d[2]), "+f"(d[3])
                 : "r"(a[0]), "r"(a[1]), "r"(a[2]), "r"(a[3]), "r"(b0), "r"(b1));
}
__device__ __forceinline__ void cpa16(uint32_t s, const void* g) {
    asm volatile("cp.async.cg.shared.global [%0], [%1], 16;" :: "r"(s), "l"(g));
}
__device__ __forceinline__ void cpa16z(uint32_t s, const void* g, bool ok) {
    int sz = ok ? 16 : 0;
    asm volatile("cp.async.cg.shared.global [%0], [%1], 16, %2;" :: "r"(s), "l"(g), "r"(sz));
}
#define CPA_COMMIT() asm volatile("cp.async.commit_group;" ::: "memory")
#define CPA_WAIT0()  asm volatile("cp.async.wait_group 0;" ::: "memory")

// fp32 pair -> bf16 hi + bf16 residual
__device__ __forceinline__ void split2(float a, float b, uint32_t& h, uint32_t& l) {
    __nv_bfloat162 hh = __floats2bfloat162_rn(a, b);
    float2 hf = __bfloat1622float2(hh);
    __nv_bfloat162 ll = __floats2bfloat162_rn(a - hf.x, b - hf.y);
    h = *reinterpret_cast<uint32_t*>(&hh);
    l = *reinterpret_cast<uint32_t*>(&ll);
}
// fp32 pair -> fp16 hi + fp16 residual
__device__ __forceinline__ void split2h(float a, float b, uint32_t& h, uint32_t& l) {
    __half2 hh = __floats2half2_rn(a, b);
    float2 hf = __half22float2(hh);
    __half2 ll = __floats2half2_rn(a - hf.x, b - hf.y);
    h = *reinterpret_cast<uint32_t*>(&hh);
    l = *reinterpret_cast<uint32_t*>(&ll);
}

// ====================== async double-buffered MMA GEMM ======================
// DT=0: bf16 3-pass split (A hi/lo, B hi/lo).  DT=1: fp16 2-pass (A single, B hi/lo).
// NT form: C = alpha * A @ B^T + bias (+ReLU). Batch via blockIdx.z.
// EPI: 0 = fp32 -> Cf; 1 = bf16 hi/lo -> Chi/Clo; 2 = fp16 single -> Chi; 3 = fp16 hi/lo.
template<int DT, int BM, int BN, int WM, int WN, int EPI, bool RELU, bool NGUARD>
__global__ __launch_bounds__(256, 2)
void mma_gemm(int M, int N, int K,
              const uint16_t* __restrict__ Ah, const uint16_t* __restrict__ Al, int lda, long long sAz,
              const uint16_t* __restrict__ Bh, const uint16_t* __restrict__ Bl, int ldb, long long sBz,
              float* __restrict__ Cf, uint16_t* __restrict__ Chi, uint16_t* __restrict__ Clo,
              long long ldc, long long sCz,
              const float* __restrict__ bias, float alpha)
{
    constexpr int BK = 32, BKP = 40;
    constexpr int WNC = BN / WN;
    constexpr int MI = WM / 16, NI2 = WN / 16, NA = WN / 8;
    constexpr int SA = BM * BKP, SB = BN * BKP;
    constexpr int NPA = (DT == 0) ? 2 : 1;                 // A passes stored
    constexpr int STAGE_BYTES = (NPA * SA + 2 * SB) * 2;

    extern __shared__ __align__(16) char smem[];
    const uint32_t uS = smem_u32(smem);

    const int tid = threadIdx.x, wid = tid >> 5, lane = tid & 31;
    Ah += (long long)blockIdx.z * sAz;  if (DT == 0) Al += (long long)blockIdx.z * sAz;
    Bh += (long long)blockIdx.z * sBz;  Bl += (long long)blockIdx.z * sBz;
    const long long coff = (long long)blockIdx.z * sCz;
    const int row0 = blockIdx.y * BM;
    const int col0 = blockIdx.x * BN;
    const int wm0 = (wid / WNC) * WM;
    const int wn0 = (wid % WNC) * WN;

    float acc[MI][NA][4];
    #pragma unroll
    for (int i = 0; i < MI; i++)
        #pragma unroll
        for (int j = 0; j < NA; j++)
            #pragma unroll
            for (int q = 0; q < 4; q++) acc[i][j][q] = 0.f;

    auto loadT = [&](int stage, int kt) {
        uint32_t base = uS + stage * STAGE_BYTES;
        #pragma unroll
        for (int i = 0; i < (BM * 4) / 256; i++) {
            int ch = tid + i * 256, r = ch >> 2, q = ch & 3;
            cpa16(base + r * 80 + q * 16, Ah + (size_t)(row0 + r) * lda + kt + q * 8);
            if (DT == 0)
                cpa16(base + SA * 2 + r * 80 + q * 16, Al + (size_t)(row0 + r) * lda + kt + q * 8);
        }
        #pragma unroll
        for (int i = 0; i < (BN * 4) / 256; i++) {
            int ch = tid + i * 256, r = ch >> 2, q = ch & 3;
            bool ok = !NGUARD || (col0 + r) < N;
            cpa16z(base + NPA * SA * 2 + r * 80 + q * 16,
                   Bh + (size_t)(col0 + r) * ldb + kt + q * 8, ok);
            cpa16z(base + (NPA * SA + SB) * 2 + r * 80 + q * 16,
                   Bl + (size_t)(col0 + r) * ldb + kt + q * 8, ok);
        }
    };
    auto compute = [&](int stage) {
        uint32_t bA = uS + stage * STAGE_BYTES;
        uint32_t bAh = bA, bAl = bA + SA * 2;
        uint32_t bBh = bA + NPA * SA * 2, bBl = bA + (NPA * SA + SB) * 2;
        const int lr = lane & 15, lc = (lane >> 4) * 8;
        #pragma unroll
        for (int kk = 0; kk < BK; kk += 16) {
            uint32_t bh[NI2][4], bl[NI2][4];
            #pragma unroll
            for (int ni = 0; ni < NI2; ni++) {
                uint32_t off = (uint32_t)((wn0 + ni * 16 + lr) * 80 + (kk + lc) * 2);
                ldmx4(bh[ni], bBh + off);
                ldmx4(bl[ni], bBl + off);
            }
            #pragma unroll
            for (int mi = 0; mi < MI; mi++) {
                uint32_t ah[4], al[4];
                uint32_t off = (uint32_t)((wm0 + mi * 16 + lr) * 80 + (kk + lc) * 2);
                ldmx4(ah, bAh + off);
                if (DT == 0) ldmx4(al, bAl + off);
                #pragma unroll
                for (int na = 0; na < NA; na++) {
                    int ni = na >> 1, sel = na & 1;
                    uint32_t b0h = bh[ni][sel], b1h = bh[ni][sel + 2];
                    if (DT == 0) {
                        mma_bf16(acc[mi][na], ah, b0h, b1h);
                        mma_bf16(acc[mi][na], al, b0h, b1h);
                        mma_bf16(acc[mi][na], ah, bl[ni][sel], bl[ni][sel + 2]);
                    } else {
                        mma_f16(acc[mi][na], ah, b0h, b1h);
                        mma_f16(acc[mi][na], ah, bl[ni][sel], bl[ni][sel + 2]);
                    }
                }
            }
        }
    };

    const int tiles = K / BK;
    loadT(0, 0);
    CPA_COMMIT();
    for (int t = 0; t < tiles; t++) {
        int cur = t & 1;
        CPA_WAIT0();
        __syncthreads();
        if (t + 1 < tiles) loadT((t + 1) & 1, (t + 1) * BK);
        CPA_COMMIT();
        compute(cur);
    }

    // ---------------- epilogue ----------------
    const int lr4 = lane >> 2, lc2 = (lane & 3) * 2;
    #pragma unroll
    for (int mi = 0; mi < MI; mi++) {
        #pragma unroll
        for (int na = 0; na < NA; na++) {
            float* d = acc[mi][na];
            int col = col0 + wn0 + na * 8 + lc2;
            int r0 = row0 + wm0 + mi * 16 + lr4;
            float bb0 = 0.f, bb1 = 0.f;
            if (bias) {
                if (!NGUARD || col     < N) bb0 = bias[col];
                if (!NGUARD || col + 1 < N) bb1 = bias[col + 1];
            }
            float v0 = d[0] * alpha + bb0, v1 = d[1] * alpha + bb1;
            float v2 = d[2] * alpha + bb0, v3 = d[3] * alpha + bb1;
            if (RELU) {
                v0 = fmaxf(v0, 0.f); v1 = fmaxf(v1, 0.f);
                v2 = fmaxf(v2, 0.f); v3 = fmaxf(v3, 0.f);
            }
            long long b0i = (long long)r0 * ldc + col + coff;
            long long b1i = (long long)(r0 + 8) * ldc + col + coff;
            if (EPI == 0) {
                if (!NGUARD || col + 1 < N) {
                    *reinterpret_cast<float2*>(Cf + b0i) = make_float2(v0, v1);
                    *reinterpret_cast<float2*>(Cf + b1i) = make_float2(v2, v3);
                } else if (col < N) {
                    Cf[b0i] = v0;
                    Cf[b1i] = v2;
                }
            } else if (EPI == 1 || EPI == 3) {
                uint32_t h01, l01, h23, l23;
                if (EPI == 1) { split2 (v0, v1, h01, l01); split2 (v2, v3, h23, l23); }
                else          { split2h(v0, v1, h01, l01); split2h(v2, v3, h23, l23); }
                *reinterpret_cast<uint32_t*>(Chi + b0i) = h01;
                *reinterpret_cast<uint32_t*>(Clo + b0i) = l01;
                *reinterpret_cast<uint32_t*>(Chi + b1i) = h23;
                *reinterpret_cast<uint32_t*>(Clo + b1i) = l23;
            } else {  // EPI==2: fp16 single
                __half2 h01 = __floats2half2_rn(v0, v1);
                __half2 h23 = __floats2half2_rn(v2, v3);
                *reinterpret_cast<uint32_t*>(Chi + b0i) = *reinterpret_cast<uint32_t*>(&h01);
                *reinterpret_cast<uint32_t*>(Chi + b1i) = *reinterpret_cast<uint32_t*>(&h23);
            }
        }
    }
}

// ====================== PV: O_h = sparsemax(S_h) @ V_h (P fp16 single, V fp16 split) ======================
__global__ __launch_bounds__(256, 2)
void pv_gemm(const float* __restrict__ S, const float* __restrict__ tau,
             const uint16_t* __restrict__ Vh, const uint16_t* __restrict__ Vl,
             uint16_t* __restrict__ Oh, uint16_t* __restrict__ Ol)
{
    constexpr int BM = 128, BK = 32, BKP = 40;
    constexpr int SA = BM * BKP, SB = DHEAD * BKP;
    constexpr int STAGE = (SA + 2 * SB) * 2;

    extern __shared__ __align__(16) char smem[];
    float* sTau = reinterpret_cast<float*>(smem + 2 * STAGE);

    const int tid = threadIdx.x, wid = tid >> 5, lane = tid & 31;
    const int head = blockIdx.y;
    const int row0 = blockIdx.x * BM;
    const float* Sb = S + (size_t)head * N_Q * M_KV + (size_t)row0 * M_KV;
    const float* tb = tau + head * N_Q + row0;
    const uint16_t* Vhb = Vh + head * DHEAD;
    const uint16_t* Vlb = Vl + head * DHEAD;

    if (tid < BM) sTau[tid] = tb[tid];
    __syncthreads();

    const int wm0 = (wid >> 2) * 64;
    const int wn0 = (wid & 3) * 16;
    constexpr int MI = 4, NA = 2;

    float acc[MI][NA][4];
    #pragma unroll
    for (int i = 0; i < MI; i++)
        #pragma unroll
        for (int j = 0; j < NA; j++)
            #pragma unroll
            for (int q = 0; q < 4; q++) acc[i][j][q] = 0.f;

    float4 aReg[4];
    uint4 bhReg, blReg;
    const int a_r = tid >> 3, a_c = (tid & 7) * 4;
    const int b_k = tid >> 3, b_c = (tid & 7) * 8;

    auto ldRegs = [&](int kt) {
        #pragma unroll
        for (int i = 0; i < 4; i++)
            aReg[i] = *reinterpret_cast<const float4*>(Sb + (size_t)(a_r + i * 32) * M_KV + kt + a_c);
        bhReg = *reinterpret_cast<const uint4*>(Vhb + (size_t)(kt + b_k) * DMODEL + b_c);
        blReg = *reinterpret_cast<const uint4*>(Vlb + (size_t)(kt + b_k) * DMODEL + b_c);
    };
    auto sts = [&](int st) {
        uint16_t* base = reinterpret_cast<uint16_t*>(smem + st * STAGE);
        uint16_t* As  = base;
        uint16_t* Bhs = base + SA;
        uint16_t* Bls = base + SA + SB;
        #pragma unroll
        for (int i = 0; i < 4; i++) {
            int r = a_r + i * 32;
            float tv = sTau[r];
            __half2 p01 = __floats2half2_rn(fmaxf(aReg[i].x - tv, 0.f), fmaxf(aReg[i].y - tv, 0.f));
            __half2 p23 = __floats2half2_rn(fmaxf(aReg[i].z - tv, 0.f), fmaxf(aReg[i].w - tv, 0.f));
            *reinterpret_cast<uint2*>(As + r * BKP + a_c) =
                make_uint2(*reinterpret_cast<uint32_t*>(&p01), *reinterpret_cast<uint32_t*>(&p23));
        }
        uint16_t th[8], tl[8];
        *reinterpret_cast<uint4*>(th) = bhReg;
        *reinterpret_cast<uint4*>(tl) = blReg;
        #pragma unroll
        for (int j = 0; j < 8; j++) {
            Bhs[(b_c + j) * BKP + b_k] = th[j];
            Bls[(b_c + j) * BKP + b_k] = tl[j];
        }
    };
    auto compute = [&](int st) {
        uint32_t base = smem_u32(smem) + st * STAGE;
        uint32_t uA = base, uBh = base + SA * 2, uBl = base + (SA + SB) * 2;
        const int lr = lane & 15, lc = (lane >> 4) * 8;
        #pragma unroll
        for (int kk = 0; kk < BK; kk += 16) {
            uint32_t bh[4], bl[4];
            uint32_t boff = (uint32_t)((wn0 + lr) * BKP + kk + lc) * 2;
            ldmx4(bh, uBh + boff);
            ldmx4(bl, uBl + boff);
            #pragma unroll
            for (int mi = 0; mi < MI; mi++) {
                uint32_t ah[4];
                uint32_t aoff = (uint32_t)((wm0 + mi * 16 + lr) * BKP + kk + lc) * 2;
                ldmx4(ah, uA + aoff);
                #pragma unroll
                for (int na = 0; na < NA; na++) {
                    mma_f16(acc[mi][na], ah, bh[na], bh[na + 2]);
                    mma_f16(acc[mi][na], ah, bl[na], bl[na + 2]);
                }
            }
        }
    };

    const int tiles = M_KV / BK;
    ldRegs(0);
    sts(0);
    for (int t = 0; t < tiles; t++) {
        __syncthreads();
        if (t + 1 < tiles) ldRegs((t + 1) * BK);
        compute(t & 1);
        if (t + 1 < tiles) sts((t + 1) & 1);
    }

    const int lr4 = lane >> 2, lc2 = (lane & 3) * 2;
    #pragma unroll
    for (int mi = 0; mi < MI; mi++) {
        #pragma unroll
        for (int na = 0; na < NA; na++) {
            float* d = acc[mi][na];
            int col = head * DHEAD + wn0 + na * 8 + lc2;
            int r0 = row0 + wm0 + mi * 16 + lr4;
            uint32_t h01, l01, h23, l23;
            split2(d[0], d[1], h01, l01);
            split2(d[2], d[3], h23, l23);
            *reinterpret_cast<uint32_t*>(Oh + (size_t)r0 * DMODEL + col) = h01;
            *reinterpret_cast<uint32_t*>(Ol + (size_t)r0 * DMODEL + col) = l01;
            *reinterpret_cast<uint32_t*>(Oh + (size_t)(r0 + 8) * DMODEL + col) = h23;
            *reinterpret_cast<uint32_t*>(Ol + (size_t)(r0 + 8) * DMODEL + col) = l23;
        }
    }
}

// ---------------- sparsemax tau: 4 rows per 256-thread block ----------------
__global__ __launch_bounds__(256)
void sparsemax_tau(const float* __restrict__ S, float* __restrict__ tau)
{
    const int tid = threadIdx.x;
    const int grp = tid >> 6;
    const int gt  = tid & 63;
    const int lane = tid & 31;
    const int wid = tid >> 5;
    const long long row = (long long)blockIdx.x * 4 + grp;

    const float4* z4 = reinterpret_cast<const float4*>(S + row * (long long)M_KV);
    float4 v4[16];
    #pragma unroll
    for (int j = 0; j < 16; j++) v4[j] = z4[gt + j * 64];
    float* v = reinterpret_cast<float*>(v4);

    __shared__ float red_s[8], red_c[8];
    __shared__ float s_tau[4];
    __shared__ int   s_done;

    float m = v[0];
    #pragma unroll
    for (int i = 1; i < 64; i++) m = fmaxf(m, v[i]);
    #pragma unroll
    for (int o = 16; o > 0; o >>= 1) m = fmaxf(m, __shfl_xor_sync(0xffffffffu, m, o));
    if (lane == 0) red_s[wid] = m;
    if (tid == 0) s_done = 0;
    __syncthreads();
    if (gt == 0) s_tau[grp] = fmaxf(red_s[grp * 2], red_s[grp * 2 + 1]) - 1.0f;
    __syncthreads();
    float t = s_tau[grp];

    for (int it = 0; it < 64; ++it) {
        float s = 0.f, c = 0.f;
        #pragma unroll
        for (int i = 0; i < 64; i++) {
            float d = v[i] - t;
            if (d > 0.f) { s += d; c += 1.f; }
        }
        #pragma unroll
        for (int o = 16; o > 0; o >>= 1) {
            s += __shfl_xor_sync(0xffffffffu, s, o);
            c += __shfl_xor_sync(0xffffffffu, c, o);
        }
        if (lane == 0) { red_s[wid] = s; red_c[wid] = c; }
        __syncthreads();
        if (gt == 0) {
            float St = red_s[grp * 2] + red_s[grp * 2 + 1];
            float Ct = red_c[grp * 2] + red_c[grp * 2 + 1];
            float delta = (St - 1.0f) / fmaxf(Ct, 1.0f);
            s_tau[grp] = t + delta;
            if (fabsf(delta) >= 1e-9f) atomicOr(&s_done, 1);
        }
        __syncthreads();
        t = s_tau[grp];
        int nd = s_done;
        __syncthreads();
        if (nd == 0) break;
        if (gt == 0) s_done = 0;
        __syncthreads();
    }
    if (gt == 0) tau[row] = t;
}

// ---------------- prep ----------------
__global__ __launch_bounds__(256)
void split_convert(const float4* __restrict__ src, uint2* __restrict__ dh,
                   uint2* __restrict__ dl, int n4)
{
    int i = blockIdx.x * 256 + threadIdx.x;
    if (i >= n4) return;
    float4 v = src[i];
    uint32_t h01, l01, h23, l23;
    split2(v.x, v.y, h01, l01);
    split2(v.z, v.w, h23, l23);
    dh[i] = make_uint2(h01, h23);
    dl[i] = make_uint2(l01, l23);
}
__global__ __launch_bounds__(256)
void split_convert_f16(const float4* __restrict__ src, uint2* __restrict__ dh,
                       uint2* __restrict__ dl, int n4)
{
    int i = blockIdx.x * 256 + threadIdx.x;
    if (i >= n4) return;
    float4 v = src[i];
    uint32_t h01, l01, h23, l23;
    split2h(v.x, v.y, h01, l01);
    split2h(v.z, v.w, h23, l23);
    dh[i] = make_uint2(h01, h23);
    dl[i] = make_uint2(l01, l23);
}
// enc -> FINf fp16 single, columns [0, DMODEL)
__global__ __launch_bounds__(256)
void enc_to_fin(const float4* __restrict__ enc, uint16_t* __restrict__ f)
{
    int i = blockIdx.x * 256 + threadIdx.x;
    int row = i >> 8, cg = i & 255;
    float4 v = enc[i];
    __half2 h01 = __floats2half2_rn(v.x, v.y);
    __half2 h23 = __floats2half2_rn(v.z, v.w);
    int o = row * (2 * DMODEL) + cg * 4;
    *reinterpret_cast<uint2*>(f + o) =
        make_uint2(*reinterpret_cast<uint32_t*>(&h01), *reinterpret_cast<uint32_t*>(&h23));
}

// ---------------- host launcher ----------------
extern "C" void kernel_launch(void* const* d_in, const int* in_sizes, int n_in,
                              void* d_out, int out_size)
{
    const float* enc = (const float*)d_in[0];
    const float* mem = (const float*)d_in[1];
    const float* Wq  = (const float*)d_in[2];
    const float* bq  = (const float*)d_in[3];
    const float* Wk  = (const float*)d_in[4];
    const float* bk  = (const float*)d_in[5];
    const float* Wv  = (const float*)d_in[6];
    const float* bv  = (const float*)d_in[7];
    const float* Wo  = (const float*)d_in[8];
    const float* bo  = (const float*)d_in[9];
    const float* W1  = (const float*)d_in[10];
    const float* b1  = (const float*)d_in[11];
    const float* W2  = (const float*)d_in[12];
    const float* b2  = (const float*)d_in[13];
    float* out = (float*)d_out;

    uint16_t *pFINf, *pENCh, *pENCl, *pmemh, *pmeml;
    uint16_t *pWqh, *pWql, *pWkh, *pWkl, *pWvh, *pWvl, *pWoh, *pWol;
    uint16_t *pW1h, *pW1l, *pW2h, *pW2l;
    uint16_t *pQh, *pQl, *pKh, *pKl, *pVh, *pVl, *pOh, *pOl, *pHf;
    float *pS, *pTau;
    cudaGetSymbolAddress((void**)&pFINf, g_FINf);
    cudaGetSymbolAddress((void**)&pENCh, g_ENCh); cudaGetSymbolAddress((void**)&pENCl, g_ENCl);
    cudaGetSymbolAddress((void**)&pmemh, g_memh); cudaGetSymbolAddress((void**)&pmeml, g_meml);
    cudaGetSymbolAddress((void**)&pWqh,  g_Wqh);  cudaGetSymbolAddress((void**)&pWql,  g_Wql);
    cudaGetSymbolAddress((void**)&pWkh,  g_Wkh);  cudaGetSymbolAddress((void**)&pWkl,  g_Wkl);
    cudaGetSymbolAddress((void**)&pWvh,  g_Wvh);  cudaGetSymbolAddress((void**)&pWvl,  g_Wvl);
    cudaGetSymbolAddress((void**)&pWoh,  g_Woh);  cudaGetSymbolAddress((void**)&pWol,  g_Wol);
    cudaGetSymbolAddress((void**)&pW1h,  g_W1h);  cudaGetSymbolAddress((void**)&pW1l,  g_W1l);
    cudaGetSymbolAddress((void**)&pW2h,  g_W2h);  cudaGetSymbolAddress((void**)&pW2l,  g_W2l);
    cudaGetSymbolAddress((void**)&pQh,   g_Qh);   cudaGetSymbolAddress((void**)&pQl,   g_Ql);
    cudaGetSymbolAddress((void**)&pKh,   g_Kh);   cudaGetSymbolAddress((void**)&pKl,   g_Kl);
    cudaGetSymbolAddress((void**)&pVh,   g_Vfh);  cudaGetSymbolAddress((void**)&pVl,   g_Vfl);
    cudaGetSymbolAddress((void**)&pOh,   g_Oh);   cudaGetSymbolAddress((void**)&pOl,   g_Ol);
    cudaGetSymbolAddress((void**)&pHf,   g_Hf);
    cudaGetSymbolAddress((void**)&pS,    g_S);
    cudaGetSymbolAddress((void**)&pTau,  g_tau);

    dim3 blk(256);
    auto cvtB = [&](const float* s, uint16_t* h, uint16_t* l, int n) {
        int n4 = n / 4;
        split_convert<<<(n4 + 255) / 256, blk>>>((const float4*)s, (uint2*)h, (uint2*)l, n4);
    };
    auto cvtH = [&](const float* s, uint16_t* h, uint16_t* l, int n) {
        int n4 = n / 4;
        split_convert_f16<<<(n4 + 255) / 256, blk>>>((const float4*)s, (uint2*)h, (uint2*)l, n4);
    };

    constexpr int BKP = 40;
    const int DS_B3 = 2 * (2 * 128 * BKP + 2 * 128 * BKP) * 2;               // 81920 (DT0)
    const int DS_F2 = 2 * (1 * 128 * BKP + 2 * 128 * BKP) * 2;               // 61440 (DT1)
    const int DS_PV = 2 * (128 * BKP + 2 * DHEAD * BKP) * 2 + 512;           // 41472

    auto* kProjB = mma_gemm<0,128,128,32,64,1,false,false>;   // Q/K proj: bf16 split out
    auto* kProjV = mma_gemm<0,128,128,32,64,3,false,false>;   // V proj: bf16 compute, fp16 split out
    auto* kWo    = mma_gemm<0,128,128,32,64,2,false,false>;   // Wo: fp16 single out -> FINf
    auto* kQK    = mma_gemm<0,128,128,32,64,0,false,false>;   // QK -> S fp32
    auto* kW1    = mma_gemm<1,128,128,32,64,2,true ,false>;   // W1 2-pass fp16 + ReLU -> Hf
    auto* kW2    = mma_gemm<1,128,128,32,64,0,false,true >;   // W2 2-pass fp16 -> out
    cudaFuncSetAttribute(kProjB, cudaFuncAttributeMaxDynamicSharedMemorySize, DS_B3);
    cudaFuncSetAttribute(kProjV, cudaFuncAttributeMaxDynamicSharedMemorySize, DS_B3);
    cudaFuncSetAttribute(kWo   , cudaFuncAttributeMaxDynamicSharedMemorySize, DS_B3);
    cudaFuncSetAttribute(kQK   , cudaFuncAttributeMaxDynamicSharedMemorySize, DS_B3);
    cudaFuncSetAttribute(kW1   , cudaFuncAttributeMaxDynamicSharedMemorySize, DS_F2);
    cudaFuncSetAttribute(kW2   , cudaFuncAttributeMaxDynamicSharedMemorySize, DS_F2);
    cudaFuncSetAttribute(pv_gemm, cudaFuncAttributeMaxDynamicSharedMemorySize, DS_PV);

    // launch order: index 6 = K-projection GEMM (ncu capture slot)
    // 0
    enc_to_fin<<<(N_Q * DMODEL / 4) / 256, blk>>>((const float4*)enc, pFINf);
    // 1
    cvtB(enc, pENCh, pENCl, N_Q * DMODEL);
    // 2
    cvtB(mem, pmemh, pmeml, M_KV * DMODEL);
    // 3
    cvtB(Wq, pWqh, pWql, DMODEL * DMODEL);
    // 4
    cvtB(Wk, pWkh, pWkl, DMODEL * DMODEL);
    // 5: Q = enc @ Wq^T + bq
    kProjB<<<dim3(DMODEL/128, N_Q/128, 1), blk, DS_B3>>>(
        N_Q, DMODEL, DMODEL, pENCh, pENCl, DMODEL, 0, pWqh, pWql, DMODEL, 0,
        nullptr, pQh, pQl, DMODEL, 0, bq, 1.0f);
    // 6: K = mem @ Wk^T + bk            <-- ncu capture
    kProjB<<<dim3(DMODEL/128, M_KV/128, 1), blk, DS_B3>>>(
        M_KV, DMODEL, DMODEL, pmemh, pmeml, DMODEL, 0, pWkh, pWkl, DMODEL, 0,
        nullptr, pKh, pKl, DMODEL, 0, bk, 1.0f);
    // 7: Wv as bf16 split (compute type of V projection is bf16!)
    cvtB(Wv, pWvh, pWvl, DMODEL * DMODEL);
    // 8: V = mem @ Wv^T + bv  (bf16 3-pass compute; EPI=3 fp16-splits the fp32 accumulator)
    kProjV<<<dim3(DMODEL/128, M_KV/128, 1), blk, DS_B3>>>(
        M_KV, DMODEL, DMODEL, pmemh, pmeml, DMODEL, 0, pWvh, pWvl, DMODEL, 0,
        nullptr, pVh, pVl, DMODEL, 0, bv, 1.0f);
    // 9: S[h] = (Q_h @ K_h^T) / 32
    kQK<<<dim3(M_KV/128, N_Q/128, NHEADS), blk, DS_B3>>>(
        N_Q, M_KV, DHEAD, pQh, pQl, DMODEL, (long long)DHEAD,
        pKh, pKl, DMODEL, (long long)DHEAD,
        pS, nullptr, nullptr, M_KV, (long long)N_Q * M_KV, nullptr, 0.03125f);
    // 10
    cvtB(Wo, pWoh, pWol, DMODEL * DMODEL);
    // 11: sparsemax -> tau
    sparsemax_tau<<<NHEADS * N_Q / 4, blk>>>(pS, pTau);
    // 12: O_h = max(S_h - tau, 0) @ V_h
    pv_gemm<<<dim3(N_Q/128, NHEADS), blk, DS_PV>>>(pS, pTau, pVh, pVl, pOh, pOl);
    // 13: FINf[:, 1024:2048] = O @ Wo^T + bo (fp16 single)
    kWo<<<dim3(DMODEL/128, N_Q/128, 1), blk, DS_B3>>>(
        N_Q, DMODEL, DMODEL, pOh, pOl, DMODEL, 0, pWoh, pWol, DMODEL, 0,
        nullptr, pFINf + DMODEL, nullptr, 2*DMODEL, 0, bo, 1.0f);
    // 14
    cvtH(W1, pW1h, pW1l, DFF * 2 * DMODEL);
    // 15: H = relu(FINf @ W1^T + b1)  (2-pass fp16)
    kW1<<<dim3(DFF/128, N_Q/128, 1), blk, DS_F2>>>(
        N_Q, DFF, 2*DMODEL, pFINf, nullptr, 2*DMODEL, 0, pW1h, pW1l, 2*DMODEL, 0,
        nullptr, pHf, nullptr, DFF, 0, b1, 1.0f);
    // 16
    cvtH(W2, pW2h, pW2l, DOUT * DFF);
    // 17: OUT = H @ W2^T + b2  (2-pass fp16, N=1000)
    kW2<<<dim3((DOUT + 127)/128, N_Q/128, 1), blk, DS_F2>>>(
        N_Q, DOUT, DFF, pHf, nullptr, DFF, 0, pW2h, pW2l, DFF, 0,
        out, nullptr, nullptr, DOUT, 0, b2, 1.0f);
}

// round 12
// speedup vs baseline: 1.2642x; 1.0622x over previous
#include <cuda_runtime.h>
#include <cuda_bf16.h>
#include <cuda_fp16.h>
#include <cstdint>
#include <math.h>

// Problem dims (fixed by the dataset)
#define N_Q    2048
#define M_KV   4096
#define DMODEL 1024
#define NHEADS 16
#define DHEAD  64
#define DFF    4096
#define DOUT   1000

// ---------------- scratch (device globals; no allocation allowed) ----------------
__device__ uint16_t g_FINf[N_Q * 2 * DMODEL];                       // fp16 single: [enc | attn-out]
__device__ uint16_t g_memf[M_KV * DMODEL];                          // fp16 single
__device__ uint16_t g_Wqh[DMODEL*DMODEL],  g_Wql[DMODEL*DMODEL];    // fp16 split
__device__ uint16_t g_Wkh[DMODEL*DMODEL],  g_Wkl[DMODEL*DMODEL];    // fp16 split
__device__ uint16_t g_Wvh[DMODEL*DMODEL],  g_Wvl[DMODEL*DMODEL];    // fp16 split
__device__ uint16_t g_Woh[DMODEL*DMODEL],  g_Wol[DMODEL*DMODEL];    // fp16 split
__device__ uint16_t g_W1h[DFF*2*DMODEL],   g_W1l[DFF*2*DMODEL];     // fp16 split
__device__ uint16_t g_W2h[DOUT*DFF],       g_W2l[DOUT*DFF];         // fp16 split
__device__ uint16_t g_Qf[N_Q*DMODEL];                               // fp16 single
__device__ uint16_t g_Kh[M_KV*DMODEL],     g_Kl[M_KV*DMODEL];       // fp16 split
__device__ uint16_t g_Vh[M_KV*DMODEL],     g_Vl[M_KV*DMODEL];       // fp16 split
__device__ float    g_S[(size_t)NHEADS * N_Q * M_KV];
__device__ float    g_tau[NHEADS * N_Q];
__device__ uint16_t g_Of[N_Q*DMODEL];                               // fp16 single
__device__ uint16_t g_Hf[N_Q*DFF];                                  // fp16 single

// ---------------- helpers ----------------
__device__ __forceinline__ uint32_t smem_u32(const void* p) {
    uint32_t a;
    asm("{ .reg .u64 t; cvta.to.shared.u64 t, %1; cvt.u32.u64 %0, t; }" : "=r"(a) : "l"(p));
    return a;
}
__device__ __forceinline__ void ldmx4(uint32_t* r, uint32_t a) {
    asm volatile("ldmatrix.sync.aligned.m8n8.x4.shared.b16 {%0,%1,%2,%3}, [%4];"
                 : "=r"(r[0]), "=r"(r[1]), "=r"(r[2]), "=r"(r[3]) : "r"(a));
}
__device__ __forceinline__ void mma_f16(float* d, const uint32_t* a, uint32_t b0, uint32_t b1) {
    asm volatile("mma.sync.aligned.m16n8k16.row.col.f32.f16.f16.f32 "
                 "{%0,%1,%2,%3}, {%4,%5,%6,%7}, {%8,%9}, {%0,%1,%2,%3};"
                 : "+f"(d[0]), "+f"(d[1]), "+f"(d[2]), "+f"(d[3])
                 : "r"(a[0]), "r"(a[1]), "r"(a[2]), "r"(a[3]), "r"(b0), "r"(b1));
}
__device__ __forceinline__ void cpa16(uint32_t s, const void* g) {
    asm volatile("cp.async.cg.shared.global [%0], [%1], 16;" :: "r"(s), "l"(g));
}
__device__ __forceinline__ void cpa16z(uint32_t s, const void* g, bool ok) {
    int sz = ok ? 16 : 0;
    asm volatile("cp.async.cg.shared.global [%0], [%1], 16, %2;" :: "r"(s), "l"(g), "r"(sz));
}
#define CPA_COMMIT() asm volatile("cp.async.commit_group;" ::: "memory")
#define CPA_WAIT0()  asm volatile("cp.async.wait_group 0;" ::: "memory")

// fp32 pair -> fp16 hi + fp16 residual
__device__ __forceinline__ void split2h(float a, float b, uint32_t& h, uint32_t& l) {
    __half2 hh = __floats2half2_rn(a, b);
    float2 hf = __half22float2(hh);
    __half2 ll = __floats2half2_rn(a - hf.x, b - hf.y);
    h = *reinterpret_cast<uint32_t*>(&hh);
    l = *reinterpret_cast<uint32_t*>(&ll);
}

// ====================== async double-buffered 2-pass fp16 MMA GEMM ======================
// C = alpha * A @ B^T + bias (+ReLU).  A fp16 single, B fp16 hi/lo (exact split).
// Batch via blockIdx.z. EPI: 0 = fp32 -> Cf; 2 = fp16 single -> Chi; 3 = fp16 hi/lo -> Chi/Clo.
template<int BM, int BN, int WM, int WN, int EPI, bool RELU, bool NGUARD>
__global__ __launch_bounds__(256, 2)
void mma_gemm(int M, int N, int K,
              const uint16_t* __restrict__ Ah, int lda, long long sAz,
              const uint16_t* __restrict__ Bh, const uint16_t* __restrict__ Bl, int ldb, long long sBz,
              float* __restrict__ Cf, uint16_t* __restrict__ Chi, uint16_t* __restrict__ Clo,
              long long ldc, long long sCz,
              const float* __restrict__ bias, float alpha)
{
    constexpr int BK = 32, BKP = 40;
    constexpr int WNC = BN / WN;
    constexpr int MI = WM / 16, NI2 = WN / 16, NA = WN / 8;
    constexpr int SA = BM * BKP, SB = BN * BKP;
    constexpr int STAGE_BYTES = (SA + 2 * SB) * 2;

    extern __shared__ __align__(16) char smem[];
    const uint32_t uS = smem_u32(smem);

    const int tid = threadIdx.x, wid = tid >> 5, lane = tid & 31;
    Ah += (long long)blockIdx.z * sAz;
    Bh += (long long)blockIdx.z * sBz;  Bl += (long long)blockIdx.z * sBz;
    const long long coff = (long long)blockIdx.z * sCz;
    const int row0 = blockIdx.y * BM;
    const int col0 = blockIdx.x * BN;
    const int wm0 = (wid / WNC) * WM;
    const int wn0 = (wid % WNC) * WN;

    float acc[MI][NA][4];
    #pragma unroll
    for (int i = 0; i < MI; i++)
        #pragma unroll
        for (int j = 0; j < NA; j++)
            #pragma unroll
            for (int q = 0; q < 4; q++) acc[i][j][q] = 0.f;

    auto loadT = [&](int stage, int kt) {
        uint32_t base = uS + stage * STAGE_BYTES;
        #pragma unroll
        for (int i = 0; i < (BM * 4) / 256; i++) {
            int ch = tid + i * 256, r = ch >> 2, q = ch & 3;
            cpa16(base + r * 80 + q * 16, Ah + (size_t)(row0 + r) * lda + kt + q * 8);
        }
        #pragma unroll
        for (int i = 0; i < (BN * 4) / 256; i++) {
            int ch = tid + i * 256, r = ch >> 2, q = ch & 3;
            bool ok = !NGUARD || (col0 + r) < N;
            cpa16z(base + SA * 2 + r * 80 + q * 16,
                   Bh + (size_t)(col0 + r) * ldb + kt + q * 8, ok);
            cpa16z(base + (SA + SB) * 2 + r * 80 + q * 16,
                   Bl + (size_t)(col0 + r) * ldb + kt + q * 8, ok);
        }
    };
    auto compute = [&](int stage) {
        uint32_t bA = uS + stage * STAGE_BYTES;
        uint32_t bBh = bA + SA * 2, bBl = bA + (SA + SB) * 2;
        const int lr = lane & 15, lc = (lane >> 4) * 8;
        #pragma unroll
        for (int kk = 0; kk < BK; kk += 16) {
            uint32_t bh[NI2][4], bl[NI2][4];
            #pragma unroll
            for (int ni = 0; ni < NI2; ni++) {
                uint32_t off = (uint32_t)((wn0 + ni * 16 + lr) * 80 + (kk + lc) * 2);
                ldmx4(bh[ni], bBh + off);
                ldmx4(bl[ni], bBl + off);
            }
            #pragma unroll
            for (int mi = 0; mi < MI; mi++) {
                uint32_t ah[4];
                uint32_t off = (uint32_t)((wm0 + mi * 16 + lr) * 80 + (kk + lc) * 2);
                ldmx4(ah, bA + off);
                #pragma unroll
                for (int na = 0; na < NA; na++) {
                    int ni = na >> 1, sel = na & 1;
                    mma_f16(acc[mi][na], ah, bh[ni][sel], bh[ni][sel + 2]);
                    mma_f16(acc[mi][na], ah, bl[ni][sel], bl[ni][sel + 2]);
                }
            }
        }
    };

    const int tiles = K / BK;
    loadT(0, 0);
    CPA_COMMIT();
    for (int t = 0; t < tiles; t++) {
        int cur = t & 1;
        CPA_WAIT0();
        __syncthreads();
        if (t + 1 < tiles) loadT((t + 1) & 1, (t + 1) * BK);
        CPA_COMMIT();
        compute(cur);
    }

    // ---------------- epilogue ----------------
    const int lr4 = lane >> 2, lc2 = (lane & 3) * 2;
    #pragma unroll
    for (int mi = 0; mi < MI; mi++) {
        #pragma unroll
        for (int na = 0; na < NA; na++) {
            float* d = acc[mi][na];
            int col = col0 + wn0 + na * 8 + lc2;
            int r0 = row0 + wm0 + mi * 16 + lr4;
            float bb0 = 0.f, bb1 = 0.f;
            if (bias) {
                if (!NGUARD || col     < N) bb0 = bias[col];
                if (!NGUARD || col + 1 < N) bb1 = bias[col + 1];
            }
            float v0 = d[0] * alpha + bb0, v1 = d[1] * alpha + bb1;
            float v2 = d[2] * alpha + bb0, v3 = d[3] * alpha + bb1;
            if (RELU) {
                v0 = fmaxf(v0, 0.f); v1 = fmaxf(v1, 0.f);
                v2 = fmaxf(v2, 0.f); v3 = fmaxf(v3, 0.f);
            }
            long long b0i = (long long)r0 * ldc + col + coff;
            long long b1i = (long long)(r0 + 8) * ldc + col + coff;
            if (EPI == 0) {
                if (!NGUARD || col + 1 < N) {
                    *reinterpret_cast<float2*>(Cf + b0i) = make_float2(v0, v1);
                    *reinterpret_cast<float2*>(Cf + b1i) = make_float2(v2, v3);
                } else if (col < N) {
                    Cf[b0i] = v0;
                    Cf[b1i] = v2;
                }
            } else if (EPI == 3) {
                uint32_t h01, l01, h23, l23;
                split2h(v0, v1, h01, l01);
                split2h(v2, v3, h23, l23);
                *reinterpret_cast<uint32_t*>(Chi + b0i) = h01;
                *reinterpret_cast<uint32_t*>(Clo + b0i) = l01;
                *reinterpret_cast<uint32_t*>(Chi + b1i) = h23;
                *reinterpret_cast<uint32_t*>(Clo + b1i) = l23;
            } else {  // EPI==2: fp16 single
                __half2 h01 = __floats2half2_rn(v0, v1);
                __half2 h23 = __floats2half2_rn(v2, v3);
                *reinterpret_cast<uint32_t*>(Chi + b0i) = *reinterpret_cast<uint32_t*>(&h01);
                *reinterpret_cast<uint32_t*>(Chi + b1i) = *reinterpret_cast<uint32_t*>(&h23);
            }
        }
    }
}

// ====================== PV: O_h = sparsemax(S_h) @ V_h (P fp16 single, V fp16 split) ======================
__global__ __launch_bounds__(256, 2)
void pv_gemm(const float* __restrict__ S, const float* __restrict__ tau,
             const uint16_t* __restrict__ Vh, const uint16_t* __restrict__ Vl,
             uint16_t* __restrict__ Of)
{
    constexpr int BM = 128, BK = 32, BKP = 40;
    constexpr int SA = BM * BKP, SB = DHEAD * BKP;
    constexpr int STAGE = (SA + 2 * SB) * 2;

    extern __shared__ __align__(16) char smem[];
    float* sTau = reinterpret_cast<float*>(smem + 2 * STAGE);

    const int tid = threadIdx.x, wid = tid >> 5, lane = tid & 31;
    const int head = blockIdx.y;
    const int row0 = blockIdx.x * BM;
    const float* Sb = S + (size_t)head * N_Q * M_KV + (size_t)row0 * M_KV;
    const float* tb = tau + head * N_Q + row0;
    const uint16_t* Vhb = Vh + head * DHEAD;
    const uint16_t* Vlb = Vl + head * DHEAD;

    if (tid < BM) sTau[tid] = tb[tid];
    __syncthreads();

    const int wm0 = (wid >> 2) * 64;
    const int wn0 = (wid & 3) * 16;
    constexpr int MI = 4, NA = 2;

    float acc[MI][NA][4];
    #pragma unroll
    for (int i = 0; i < MI; i++)
        #pragma unroll
        for (int j = 0; j < NA; j++)
            #pragma unroll
            for (int q = 0; q < 4; q++) acc[i][j][q] = 0.f;

    float4 aReg[4];
    uint4 bhReg, blReg;
    const int a_r = tid >> 3, a_c = (tid & 7) * 4;
    const int b_k = tid >> 3, b_c = (tid & 7) * 8;

    auto ldRegs = [&](int kt) {
        #pragma unroll
        for (int i = 0; i < 4; i++)
            aReg[i] = *reinterpret_cast<const float4*>(Sb + (size_t)(a_r + i * 32) * M_KV + kt + a_c);
        bhReg = *reinterpret_cast<const uint4*>(Vhb + (size_t)(kt + b_k) * DMODEL + b_c);
        blReg = *reinterpret_cast<const uint4*>(Vlb + (size_t)(kt + b_k) * DMODEL + b_c);
    };
    auto sts = [&](int st) {
        uint16_t* base = reinterpret_cast<uint16_t*>(smem + st * STAGE);
        uint16_t* As  = base;
        uint16_t* Bhs = base + SA;
        uint16_t* Bls = base + SA + SB;
        #pragma unroll
        for (int i = 0; i < 4; i++) {
            int r = a_r + i * 32;
            float tv = sTau[r];
            __half2 p01 = __floats2half2_rn(fmaxf(aReg[i].x - tv, 0.f), fmaxf(aReg[i].y - tv, 0.f));
            __half2 p23 = __floats2half2_rn(fmaxf(aReg[i].z - tv, 0.f), fmaxf(aReg[i].w - tv, 0.f));
            *reinterpret_cast<uint2*>(As + r * BKP + a_c) =
                make_uint2(*reinterpret_cast<uint32_t*>(&p01), *reinterpret_cast<uint32_t*>(&p23));
        }
        uint16_t th[8], tl[8];
        *reinterpret_cast<uint4*>(th) = bhReg;
        *reinterpret_cast<uint4*>(tl) = blReg;
        #pragma unroll
        for (int j = 0; j < 8; j++) {
            Bhs[(b_c + j) * BKP + b_k] = th[j];
            Bls[(b_c + j) * BKP + b_k] = tl[j];
        }
    };
    auto compute = [&](int st) {
        uint32_t base = smem_u32(smem) + st * STAGE;
        uint32_t uA = base, uBh = base + SA * 2, uBl = base + (SA + SB) * 2;
        const int lr = lane & 15, lc = (lane >> 4) * 8;
        #pragma unroll
        for (int kk = 0; kk < BK; kk += 16) {
            uint32_t bh[4], bl[4];
            uint32_t boff = (uint32_t)((wn0 + lr) * BKP + kk + lc) * 2;
            ldmx4(bh, uBh + boff);
            ldmx4(bl, uBl + boff);
            #pragma unroll
            for (int mi = 0; mi < MI; mi++) {
                uint32_t ah[4];
                uint32_t aoff = (uint32_t)((wm0 + mi * 16 + lr) * BKP + kk + lc) * 2;
                ldmx4(ah, uA + aoff);
                #pragma unroll
                for (int na = 0; na < NA; na++) {
                    mma_f16(acc[mi][na], ah, bh[na], bh[na + 2]);
                    mma_f16(acc[mi][na], ah, bl[na], bl[na + 2]);
                }
            }
        }
    };

    const int tiles = M_KV / BK;
    ldRegs(0);
    sts(0);
    for (int t = 0; t < tiles; t++) {
        __syncthreads();
        if (t + 1 < tiles) ldRegs((t + 1) * BK);
        compute(t & 1);
        if (t + 1 < tiles) sts((t + 1) & 1);
    }

    const int lr4 = lane >> 2, lc2 = (lane & 3) * 2;
    #pragma unroll
    for (int mi = 0; mi < MI; mi++) {
        #pragma unroll
        for (int na = 0; na < NA; na++) {
            float* d = acc[mi][na];
            int col = head * DHEAD + wn0 + na * 8 + lc2;
            int r0 = row0 + wm0 + mi * 16 + lr4;
            __half2 h01 = __floats2half2_rn(d[0], d[1]);
            __half2 h23 = __floats2half2_rn(d[2], d[3]);
            *reinterpret_cast<uint32_t*>(Of + (size_t)r0 * DMODEL + col) =
                *reinterpret_cast<uint32_t*>(&h01);
            *reinterpret_cast<uint32_t*>(Of + (size_t)(r0 + 8) * DMODEL + col) =
                *reinterpret_cast<uint32_t*>(&h23);
        }
    }
}

// ---------------- sparsemax tau: 4 rows per 256-thread block ----------------
__global__ __launch_bounds__(256)
void sparsemax_tau(const float* __restrict__ S, float* __restrict__ tau)
{
    const int tid = threadIdx.x;
    const int grp = tid >> 6;
    const int gt  = tid & 63;
    const int lane = tid & 31;
    const int wid = tid >> 5;
    const long long row = (long long)blockIdx.x * 4 + grp;

    const float4* z4 = reinterpret_cast<const float4*>(S + row * (long long)M_KV);
    float4 v4[16];
    #pragma unroll
    for (int j = 0; j < 16; j++) v4[j] = z4[gt + j * 64];
    float* v = reinterpret_cast<float*>(v4);

    __shared__ float red_s[8], red_c[8];
    __shared__ float s_tau[4];
    __shared__ int   s_done;

    float m = v[0];
    #pragma unroll
    for (int i = 1; i < 64; i++) m = fmaxf(m, v[i]);
    #pragma unroll
    for (int o = 16; o > 0; o >>= 1) m = fmaxf(m, __shfl_xor_sync(0xffffffffu, m, o));
    if (lane == 0) red_s[wid] = m;
    if (tid == 0) s_done = 0;
    __syncthreads();
    if (gt == 0) s_tau[grp] = fmaxf(red_s[grp * 2], red_s[grp * 2 + 1]) - 1.0f;
    __syncthreads();
    float t = s_tau[grp];

    for (int it = 0; it < 64; ++it) {
        float s = 0.f, c = 0.f;
        #pragma unroll
        for (int i = 0; i < 64; i++) {
            float d = v[i] - t;
            if (d > 0.f) { s += d; c += 1.f; }
        }
        #pragma unroll
        for (int o = 16; o > 0; o >>= 1) {
            s += __shfl_xor_sync(0xffffffffu, s, o);
            c += __shfl_xor_sync(0xffffffffu, c, o);
        }
        if (lane == 0) { red_s[wid] = s; red_c[wid] = c; }
        __syncthreads();
        if (gt == 0) {
            float St = red_s[grp * 2] + red_s[grp * 2 + 1];
            float Ct = red_c[grp * 2] + red_c[grp * 2 + 1];
            float delta = (St - 1.0f) / fmaxf(Ct, 1.0f);
            s_tau[grp] = t + delta;
            if (fabsf(delta) >= 1e-9f) atomicOr(&s_done, 1);
        }
        __syncthreads();
        t = s_tau[grp];
        int nd = s_done;
        __syncthreads();
        if (nd == 0) break;
        if (gt == 0) s_done = 0;
        __syncthreads();
    }
    if (gt == 0) tau[row] = t;
}

// ---------------- prep ----------------
__global__ __launch_bounds__(256)
void split_convert_f16(const float4* __restrict__ src, uint2* __restrict__ dh,
                       uint2* __restrict__ dl, int n4)
{
    int i = blockIdx.x * 256 + threadIdx.x;
    if (i >= n4) return;
    float4 v = src[i];
    uint32_t h01, l01, h23, l23;
    split2h(v.x, v.y, h01, l01);
    split2h(v.z, v.w, h23, l23);
    dh[i] = make_uint2(h01, h23);
    dl[i] = make_uint2(l01, l23);
}
__global__ __launch_bounds__(256)
void to_f16(const float4* __restrict__ src, uint2* __restrict__ dst, int n4)
{
    int i = blockIdx.x * 256 + threadIdx.x;
    if (i >= n4) return;
    float4 v = src[i];
    __half2 h01 = __floats2half2_rn(v.x, v.y);
    __half2 h23 = __floats2half2_rn(v.z, v.w);
    dst[i] = make_uint2(*reinterpret_cast<uint32_t*>(&h01), *reinterpret_cast<uint32_t*>(&h23));
}
// enc -> FINf fp16 single, columns [0, DMODEL)
__global__ __launch_bounds__(256)
void enc_to_fin(const float4* __restrict__ enc, uint16_t* __restrict__ f)
{
    int i = blockIdx.x * 256 + threadIdx.x;
    int row = i >> 8, cg = i & 255;
    float4 v = enc[i];
    __half2 h01 = __floats2half2_rn(v.x, v.y);
    __half2 h23 = __floats2half2_rn(v.z, v.w);
    int o = row * (2 * DMODEL) + cg * 4;
    *reinterpret_cast<uint2*>(f + o) =
        make_uint2(*reinterpret_cast<uint32_t*>(&h01), *reinterpret_cast<uint32_t*>(&h23));
}

// ---------------- host launcher ----------------
extern "C" void kernel_launch(void* const* d_in, const int* in_sizes, int n_in,
                              void* d_out, int out_size)
{
    const float* enc = (const float*)d_in[0];
    const float* mem = (const float*)d_in[1];
    const float* Wq  = (const float*)d_in[2];
    const float* bq  = (const float*)d_in[3];
    const float* Wk  = (const float*)d_in[4];
    const float* bk  = (const float*)d_in[5];
    const float* Wv  = (const float*)d_in[6];
    const float* bv  = (const float*)d_in[7];
    const float* Wo  = (const float*)d_in[8];
    const float* bo  = (const float*)d_in[9];
    const float* W1  = (const float*)d_in[10];
    const float* b1  = (const float*)d_in[11];
    const float* W2  = (const float*)d_in[12];
    const float* b2  = (const float*)d_in[13];
    float* out = (float*)d_out;

    uint16_t *pFINf, *pmemf;
    uint16_t *pWqh, *pWql, *pWkh, *pWkl, *pWvh, *pWvl, *pWoh, *pWol;
    uint16_t *pW1h, *pW1l, *pW2h, *pW2l;
    uint16_t *pQf, *pKh, *pKl, *pVh, *pVl, *pOf, *pHf;
    float *pS, *pTau;
    cudaGetSymbolAddress((void**)&pFINf, g_FINf);
    cudaGetSymbolAddress((void**)&pmemf, g_memf);
    cudaGetSymbolAddress((void**)&pWqh,  g_Wqh);  cudaGetSymbolAddress((void**)&pWql,  g_Wql);
    cudaGetSymbolAddress((void**)&pWkh,  g_Wkh);  cudaGetSymbolAddress((void**)&pWkl,  g_Wkl);
    cudaGetSymbolAddress((void**)&pWvh,  g_Wvh);  cudaGetSymbolAddress((void**)&pWvl,  g_Wvl);
    cudaGetSymbolAddress((void**)&pWoh,  g_Woh);  cudaGetSymbolAddress((void**)&pWol,  g_Wol);
    cudaGetSymbolAddress((void**)&pW1h,  g_W1h);  cudaGetSymbolAddress((void**)&pW1l,  g_W1l);
    cudaGetSymbolAddress((void**)&pW2h,  g_W2h);  cudaGetSymbolAddress((void**)&pW2l,  g_W2l);
    cudaGetSymbolAddress((void**)&pQf,   g_Qf);
    cudaGetSymbolAddress((void**)&pKh,   g_Kh);   cudaGetSymbolAddress((void**)&pKl,   g_Kl);
    cudaGetSymbolAddress((void**)&pVh,   g_Vh);   cudaGetSymbolAddress((void**)&pVl,   g_Vl);
    cudaGetSymbolAddress((void**)&pOf,   g_Of);
    cudaGetSymbolAddress((void**)&pHf,   g_Hf);
    cudaGetSymbolAddress((void**)&pS,    g_S);
    cudaGetSymbolAddress((void**)&pTau,  g_tau);

    dim3 blk(256);
    auto cvtH = [&](const float* s, uint16_t* h, uint16_t* l, int n) {
        int n4 = n / 4;
        split_convert_f16<<<(n4 + 255) / 256, blk>>>((const float4*)s, (uint2*)h, (uint2*)l, n4);
    };

    constexpr int BKP = 40;
    const int DS_F2 = 2 * (128 * BKP + 2 * 128 * BKP) * 2;            // 61440
    const int DS_PV = 2 * (128 * BKP + 2 * DHEAD * BKP) * 2 + 512;    // 41472

    auto* kSingle = mma_gemm<128,128,32,64,2,false,false>;  // fp16 single out (+bias)
    auto* kSplit  = mma_gemm<128,128,32,64,3,false,false>;  // fp16 hi/lo out (+bias)
    auto* kQK     = mma_gemm<128,128,32,64,0,false,false>;  // fp32 out
    auto* kW1     = mma_gemm<128,128,32,64,2,true ,false>;  // + ReLU
    auto* kW2     = mma_gemm<128,128,32,64,0,false,true >;  // N=1000 guarded
    cudaFuncSetAttribute(kSingle, cudaFuncAttributeMaxDynamicSharedMemorySize, DS_F2);
    cudaFuncSetAttribute(kSplit , cudaFuncAttributeMaxDynamicSharedMemorySize, DS_F2);
    cudaFuncSetAttribute(kQK    , cudaFuncAttributeMaxDynamicSharedMemorySize, DS_F2);
    cudaFuncSetAttribute(kW1    , cudaFuncAttributeMaxDynamicSharedMemorySize, DS_F2);
    cudaFuncSetAttribute(kW2    , cudaFuncAttributeMaxDynamicSharedMemorySize, DS_F2);
    cudaFuncSetAttribute(pv_gemm, cudaFuncAttributeMaxDynamicSharedMemorySize, DS_PV);

    // 0: enc -> FINf left half (fp16)
    enc_to_fin<<<(N_Q * DMODEL / 4) / 256, blk>>>((const float4*)enc, pFINf);
    // 1: mem -> fp16 single
    to_f16<<<(M_KV * DMODEL / 4 + 255) / 256, blk>>>((const float4*)mem, (uint2*)pmemf, M_KV * DMODEL / 4);
    // 2-4: weights fp16 split
    cvtH(Wq, pWqh, pWql, DMODEL * DMODEL);
    cvtH(Wk, pWkh, pWkl, DMODEL * DMODEL);
    cvtH(Wv, pWvh, pWvl, DMODEL * DMODEL);
    // 5: Q = enc @ Wq^T + bq  (A = FINf left, lda 2048) -> fp16 single
    kSingle<<<dim3(DMODEL/128, N_Q/128, 1), blk, DS_F2>>>(
        N_Q, DMODEL, DMODEL, pFINf, 2*DMODEL, 0, pWqh, pWql, DMODEL, 0,
        nullptr, pQf, nullptr, DMODEL, 0, bq, 1.0f);
    // 6: K = mem @ Wk^T + bk -> fp16 split
    kSplit<<<dim3(DMODEL/128, M_KV/128, 1), blk, DS_F2>>>(
        M_KV, DMODEL, DMODEL, pmemf, DMODEL, 0, pWkh, pWkl, DMODEL, 0,
        nullptr, pKh, pKl, DMODEL, 0, bk, 1.0f);
    // 7: V = mem @ Wv^T + bv -> fp16 split
    kSplit<<<dim3(DMODEL/128, M_KV/128, 1), blk, DS_F2>>>(
        M_KV, DMODEL, DMODEL, pmemf, DMODEL, 0, pWvh, pWvl, DMODEL, 0,
        nullptr, pVh, pVl, DMODEL, 0, bv, 1.0f);
    // 8: S[h] = (Q_h @ K_h^T) / 32
    kQK<<<dim3(M_KV/128, N_Q/128, NHEADS), blk, DS_F2>>>(
        N_Q, M_KV, DHEAD, pQf, DMODEL, (long long)DHEAD,
        pKh, pKl, DMODEL, (long long)DHEAD,
        pS, nullptr, nullptr, M_KV, (long long)N_Q * M_KV, nullptr, 0.03125f);
    // 9: Wo fp16 split
    cvtH(Wo, pWoh, pWol, DMODEL * DMODEL);
    // 10: sparsemax -> tau
    sparsemax_tau<<<NHEADS * N_Q / 4, blk>>>(pS, pTau);
    // 11: O_h = max(S_h - tau, 0) @ V_h -> fp16 single
    pv_gemm<<<dim3(N_Q/128, NHEADS), blk, DS_PV>>>(pS, pTau, pVh, pVl, pOf);
    // 12: FINf[:, 1024:2048] = O @ Wo^T + bo (fp16 single)
    kSingle<<<dim3(DMODEL/128, N_Q/128, 1), blk, DS_F2>>>(
        N_Q, DMODEL, DMODEL, pOf, DMODEL, 0, pWoh, pWol, DMODEL, 0,
        nullptr, pFINf + DMODEL, nullptr, 2*DMODEL, 0, bo, 1.0f);
    // 13: W1 fp16 split
    cvtH(W1, pW1h, pW1l, DFF * 2 * DMODEL);
    // 14: H = relu(FINf @ W1^T + b1)
    kW1<<<dim3(DFF/128, N_Q/128, 1), blk, DS_F2>>>(
        N_Q, DFF, 2*DMODEL, pFINf, 2*DMODEL, 0, pW1h, pW1l, 2*DMODEL, 0,
        nullptr, pHf, nullptr, DFF, 0, b1, 1.0f);
    // 15: W2 fp16 split
    cvtH(W2, pW2h, pW2l, DOUT * DFF);
    // 16: OUT = H @ W2^T + b2  (N = 1000)
    kW2<<<dim3((DOUT + 127)/128, N_Q/128, 1), blk, DS_F2>>>(
        N_Q, DOUT, DFF, pHf, DFF, 0, pW2h, pW2l, DFF, 0,
        out, nullptr, nullptr, DOUT, 0, b2, 1.0f);
}

// round 13
// speedup vs baseline: 1.3719x; 1.0852x over previous
#include <cuda_runtime.h>
#include <cuda_bf16.h>
#include <cuda_fp16.h>
#include <cstdint>
#include <math.h>

// Problem dims (fixed by the dataset)
#define N_Q    2048
#define M_KV   4096
#define DMODEL 1024
#define NHEADS 16
#define DHEAD  64
#define DFF    4096
#define DOUT   1000

// ---------------- scratch (device globals; no allocation allowed) ----------------
__device__ uint16_t g_FINf[N_Q * 2 * DMODEL];                       // fp16 single: [enc | attn-out]
__device__ uint16_t g_memf[M_KV * DMODEL];                          // fp16 single
__device__ uint16_t g_Wqh[DMODEL*DMODEL],  g_Wql[DMODEL*DMODEL];    // fp16 split
__device__ uint16_t g_Wkh[DMODEL*DMODEL],  g_Wkl[DMODEL*DMODEL];    // fp16 split
__device__ uint16_t g_Wvh[DMODEL*DMODEL],  g_Wvl[DMODEL*DMODEL];    // fp16 split
__device__ uint16_t g_Woh[DMODEL*DMODEL],  g_Wol[DMODEL*DMODEL];    // fp16 split
__device__ uint16_t g_W1f[DFF*2*DMODEL];                            // fp16 single
__device__ uint16_t g_W2f[DOUT*DFF];                                // fp16 single
__device__ uint16_t g_Qf[N_Q*DMODEL];                               // fp16 single
__device__ uint16_t g_Kf[M_KV*DMODEL];                              // fp16 single
__device__ uint16_t g_Vh[M_KV*DMODEL],     g_Vl[M_KV*DMODEL];       // fp16 split
__device__ float    g_S[(size_t)NHEADS * N_Q * M_KV];
__device__ float    g_tau[NHEADS * N_Q];
__device__ uint16_t g_Of[N_Q*DMODEL];                               // fp16 single
__device__ uint16_t g_Hf[N_Q*DFF];                                  // fp16 single

// ---------------- helpers ----------------
__device__ __forceinline__ uint32_t smem_u32(const void* p) {
    uint32_t a;
    asm("{ .reg .u64 t; cvta.to.shared.u64 t, %1; cvt.u32.u64 %0, t; }" : "=r"(a) : "l"(p));
    return a;
}
__device__ __forceinline__ void ldmx4(uint32_t* r, uint32_t a) {
    asm volatile("ldmatrix.sync.aligned.m8n8.x4.shared.b16 {%0,%1,%2,%3}, [%4];"
                 : "=r"(r[0]), "=r"(r[1]), "=r"(r[2]), "=r"(r[3]) : "r"(a));
}
__device__ __forceinline__ void mma_f16(float* d, const uint32_t* a, uint32_t b0, uint32_t b1) {
    asm volatile("mma.sync.aligned.m16n8k16.row.col.f32.f16.f16.f32 "
                 "{%0,%1,%2,%3}, {%4,%5,%6,%7}, {%8,%9}, {%0,%1,%2,%3};"
                 : "+f"(d[0]), "+f"(d[1]), "+f"(d[2]), "+f"(d[3])
                 : "r"(a[0]), "r"(a[1]), "r"(a[2]), "r"(a[3]), "r"(b0), "r"(b1));
}
__device__ __forceinline__ void cpa16(uint32_t s, const void* g) {
    asm volatile("cp.async.cg.shared.global [%0], [%1], 16;" :: "r"(s), "l"(g));
}
__device__ __forceinline__ void cpa16z(uint32_t s, const void* g, bool ok) {
    int sz = ok ? 16 : 0;
    asm volatile("cp.async.cg.shared.global [%0], [%1], 16, %2;" :: "r"(s), "l"(g), "r"(sz));
}
#define CPA_COMMIT() asm volatile("cp.async.commit_group;" ::: "memory")
#define CPA_WAIT0()  asm volatile("cp.async.wait_group 0;" ::: "memory")

// fp32 pair -> fp16 hi + fp16 residual
__device__ __forceinline__ void split2h(float a, float b, uint32_t& h, uint32_t& l) {
    __half2 hh = __floats2half2_rn(a, b);
    float2 hf = __half22float2(hh);
    __half2 ll = __floats2half2_rn(a - hf.x, b - hf.y);
    h = *reinterpret_cast<uint32_t*>(&hh);
    l = *reinterpret_cast<uint32_t*>(&ll);
}

// ====================== async double-buffered fp16 MMA GEMM ======================
// C = alpha * A @ B^T + bias (+ReLU).  A fp16 single.
// NPB=2: B fp16 hi/lo (2-pass).  NPB=1: B fp16 single (1-pass).
// Batch via blockIdx.z. EPI: 0 = fp32 -> Cf; 2 = fp16 single -> Chi; 3 = fp16 hi/lo -> Chi/Clo.
template<int NPB, int BM, int BN, int WM, int WN, int EPI, bool RELU, bool NGUARD>
__global__ __launch_bounds__(256, 2)
void mma_gemm(int M, int N, int K,
              const uint16_t* __restrict__ Ah, int lda, long long sAz,
              const uint16_t* __restrict__ Bh, const uint16_t* __restrict__ Bl, int ldb, long long sBz,
              float* __restrict__ Cf, uint16_t* __restrict__ Chi, uint16_t* __restrict__ Clo,
              long long ldc, long long sCz,
              const float* __restrict__ bias, float alpha)
{
    constexpr int BK = 32, BKP = 40;
    constexpr int WNC = BN / WN;
    constexpr int MI = WM / 16, NI2 = WN / 16, NA = WN / 8;
    constexpr int SA = BM * BKP, SB = BN * BKP;
    constexpr int STAGE_BYTES = (SA + NPB * SB) * 2;

    extern __shared__ __align__(16) char smem[];
    const uint32_t uS = smem_u32(smem);

    const int tid = threadIdx.x, wid = tid >> 5, lane = tid & 31;
    Ah += (long long)blockIdx.z * sAz;
    Bh += (long long)blockIdx.z * sBz;
    if (NPB == 2) Bl += (long long)blockIdx.z * sBz;
    const long long coff = (long long)blockIdx.z * sCz;
    const int row0 = blockIdx.y * BM;
    const int col0 = blockIdx.x * BN;
    const int wm0 = (wid / WNC) * WM;
    const int wn0 = (wid % WNC) * WN;

    float acc[MI][NA][4];
    #pragma unroll
    for (int i = 0; i < MI; i++)
        #pragma unroll
        for (int j = 0; j < NA; j++)
            #pragma unroll
            for (int q = 0; q < 4; q++) acc[i][j][q] = 0.f;

    auto loadT = [&](int stage, int kt) {
        uint32_t base = uS + stage * STAGE_BYTES;
        #pragma unroll
        for (int i = 0; i < (BM * 4) / 256; i++) {
            int ch = tid + i * 256, r = ch >> 2, q = ch & 3;
            cpa16(base + r * 80 + q * 16, Ah + (size_t)(row0 + r) * lda + kt + q * 8);
        }
        #pragma unroll
        for (int i = 0; i < (BN * 4) / 256; i++) {
            int ch = tid + i * 256, r = ch >> 2, q = ch & 3;
            bool ok = !NGUARD || (col0 + r) < N;
            cpa16z(base + SA * 2 + r * 80 + q * 16,
                   Bh + (size_t)(col0 + r) * ldb + kt + q * 8, ok);
            if (NPB == 2)
                cpa16z(base + (SA + SB) * 2 + r * 80 + q * 16,
                       Bl + (size_t)(col0 + r) * ldb + kt + q * 8, ok);
        }
    };
    auto compute = [&](int stage) {
        uint32_t bA = uS + stage * STAGE_BYTES;
        uint32_t bBh = bA + SA * 2, bBl = bA + (SA + SB) * 2;
        const int lr = lane & 15, lc = (lane >> 4) * 8;
        #pragma unroll
        for (int kk = 0; kk < BK; kk += 16) {
            uint32_t bh[NI2][4], bl[NI2][4];
            #pragma unroll
            for (int ni = 0; ni < NI2; ni++) {
                uint32_t off = (uint32_t)((wn0 + ni * 16 + lr) * 80 + (kk + lc) * 2);
                ldmx4(bh[ni], bBh + off);
                if (NPB == 2) ldmx4(bl[ni], bBl + off);
            }
            #pragma unroll
            for (int mi = 0; mi < MI; mi++) {
                uint32_t ah[4];
                uint32_t off = (uint32_t)((wm0 + mi * 16 + lr) * 80 + (kk + lc) * 2);
                ldmx4(ah, bA + off);
                #pragma unroll
                for (int na = 0; na < NA; na++) {
                    int ni = na >> 1, sel = na & 1;
                    mma_f16(acc[mi][na], ah, bh[ni][sel], bh[ni][sel + 2]);
                    if (NPB == 2)
                        mma_f16(acc[mi][na], ah, bl[ni][sel], bl[ni][sel + 2]);
                }
            }
        }
    };

    const int tiles = K / BK;
    loadT(0, 0);
    CPA_COMMIT();
    for (int t = 0; t < tiles; t++) {
        int cur = t & 1;
        CPA_WAIT0();
        __syncthreads();
        if (t + 1 < tiles) loadT((t + 1) & 1, (t + 1) * BK);
        CPA_COMMIT();
        compute(cur);
    }

    // ---------------- epilogue ----------------
    const int lr4 = lane >> 2, lc2 = (lane & 3) * 2;
    #pragma unroll
    for (int mi = 0; mi < MI; mi++) {
        #pragma unroll
        for (int na = 0; na < NA; na++) {
            float* d = acc[mi][na];
            int col = col0 + wn0 + na * 8 + lc2;
            int r0 = row0 + wm0 + mi * 16 + lr4;
            float bb0 = 0.f, bb1 = 0.f;
            if (bias) {
                if (!NGUARD || col     < N) bb0 = bias[col];
                if (!NGUARD || col + 1 < N) bb1 = bias[col + 1];
            }
            float v0 = d[0] * alpha + bb0, v1 = d[1] * alpha + bb1;
            float v2 = d[2] * alpha + bb0, v3 = d[3] * alpha + bb1;
            if (RELU) {
                v0 = fmaxf(v0, 0.f); v1 = fmaxf(v1, 0.f);
                v2 = fmaxf(v2, 0.f); v3 = fmaxf(v3, 0.f);
            }
            long long b0i = (long long)r0 * ldc + col + coff;
            long long b1i = (long long)(r0 + 8) * ldc + col + coff;
            if (EPI == 0) {
                if (!NGUARD || col + 1 < N) {
                    *reinterpret_cast<float2*>(Cf + b0i) = make_float2(v0, v1);
                    *reinterpret_cast<float2*>(Cf + b1i) = make_float2(v2, v3);
                } else if (col < N) {
                    Cf[b0i] = v0;
                    Cf[b1i] = v2;
                }
            } else if (EPI == 3) {
                uint32_t h01, l01, h23, l23;
                split2h(v0, v1, h01, l01);
                split2h(v2, v3, h23, l23);
                *reinterpret_cast<uint32_t*>(Chi + b0i) = h01;
                *reinterpret_cast<uint32_t*>(Clo + b0i) = l01;
                *reinterpret_cast<uint32_t*>(Chi + b1i) = h23;
                *reinterpret_cast<uint32_t*>(Clo + b1i) = l23;
            } else {  // EPI==2: fp16 single
                __half2 h01 = __floats2half2_rn(v0, v1);
                __half2 h23 = __floats2half2_rn(v2, v3);
                *reinterpret_cast<uint32_t*>(Chi + b0i) = *reinterpret_cast<uint32_t*>(&h01);
                *reinterpret_cast<uint32_t*>(Chi + b1i) = *reinterpret_cast<uint32_t*>(&h23);
            }
        }
    }
}

// ====================== PV: O_h = sparsemax(S_h) @ V_h (P fp16 single, V fp16 split) ======================
__global__ __launch_bounds__(256, 2)
void pv_gemm(const float* __restrict__ S, const float* __restrict__ tau,
             const uint16_t* __restrict__ Vh, const uint16_t* __restrict__ Vl,
             uint16_t* __restrict__ Of)
{
    constexpr int BM = 128, BK = 32, BKP = 40;
    constexpr int SA = BM * BKP, SB = DHEAD * BKP;
    constexpr int STAGE = (SA + 2 * SB) * 2;

    extern __shared__ __align__(16) char smem[];
    float* sTau = reinterpret_cast<float*>(smem + 2 * STAGE);

    const int tid = threadIdx.x, wid = tid >> 5, lane = tid & 31;
    const int head = blockIdx.y;
    const int row0 = blockIdx.x * BM;
    const float* Sb = S + (size_t)head * N_Q * M_KV + (size_t)row0 * M_KV;
    const float* tb = tau + head * N_Q + row0;
    const uint16_t* Vhb = Vh + head * DHEAD;
    const uint16_t* Vlb = Vl + head * DHEAD;

    if (tid < BM) sTau[tid] = tb[tid];
    __syncthreads();

    const int wm0 = (wid >> 2) * 64;
    const int wn0 = (wid & 3) * 16;
    constexpr int MI = 4, NA = 2;

    float acc[MI][NA][4];
    #pragma unroll
    for (int i = 0; i < MI; i++)
        #pragma unroll
        for (int j = 0; j < NA; j++)
            #pragma unroll
            for (int q = 0; q < 4; q++) acc[i][j][q] = 0.f;

    float4 aReg[4];
    uint4 bhReg, blReg;
    const int a_r = tid >> 3, a_c = (tid & 7) * 4;
    const int b_k = tid >> 3, b_c = (tid & 7) * 8;

    auto ldRegs = [&](int kt) {
        #pragma unroll
        for (int i = 0; i < 4; i++)
            aReg[i] = *reinterpret_cast<const float4*>(Sb + (size_t)(a_r + i * 32) * M_KV + kt + a_c);
        bhReg = *reinterpret_cast<const uint4*>(Vhb + (size_t)(kt + b_k) * DMODEL + b_c);
        blReg = *reinterpret_cast<const uint4*>(Vlb + (size_t)(kt + b_k) * DMODEL + b_c);
    };
    auto sts = [&](int st) {
        uint16_t* base = reinterpret_cast<uint16_t*>(smem + st * STAGE);
        uint16_t* As  = base;
        uint16_t* Bhs = base + SA;
        uint16_t* Bls = base + SA + SB;
        #pragma unroll
        for (int i = 0; i < 4; i++) {
            int r = a_r + i * 32;
            float tv = sTau[r];
            __half2 p01 = __floats2half2_rn(fmaxf(aReg[i].x - tv, 0.f), fmaxf(aReg[i].y - tv, 0.f));
            __half2 p23 = __floats2half2_rn(fmaxf(aReg[i].z - tv, 0.f), fmaxf(aReg[i].w - tv, 0.f));
            *reinterpret_cast<uint2*>(As + r * BKP + a_c) =
                make_uint2(*reinterpret_cast<uint32_t*>(&p01), *reinterpret_cast<uint32_t*>(&p23));
        }
        uint16_t th[8], tl[8];
        *reinterpret_cast<uint4*>(th) = bhReg;
        *reinterpret_cast<uint4*>(tl) = blReg;
        #pragma unroll
        for (int j = 0; j < 8; j++) {
            Bhs[(b_c + j) * BKP + b_k] = th[j];
            Bls[(b_c + j) * BKP + b_k] = tl[j];
        }
    };
    auto compute = [&](int st) {
        uint32_t base = smem_u32(smem) + st * STAGE;
        uint32_t uA = base, uBh = base + SA * 2, uBl = base + (SA + SB) * 2;
        const int lr = lane & 15, lc = (lane >> 4) * 8;
        #pragma unroll
        for (int kk = 0; kk < BK; kk += 16) {
            uint32_t bh[4], bl[4];
            uint32_t boff = (uint32_t)((wn0 + lr) * BKP + kk + lc) * 2;
            ldmx4(bh, uBh + boff);
            ldmx4(bl, uBl + boff);
            #pragma unroll
            for (int mi = 0; mi < MI; mi++) {
                uint32_t ah[4];
                uint32_t aoff = (uint32_t)((wm0 + mi * 16 + lr) * BKP + kk + lc) * 2;
                ldmx4(ah, uA + aoff);
                #pragma unroll
                for (int na = 0; na < NA; na++) {
                    mma_f16(acc[mi][na], ah, bh[na], bh[na + 2]);
                    mma_f16(acc[mi][na], ah, bl[na], bl[na + 2]);
                }
            }
        }
    };

    const int tiles = M_KV / BK;
    ldRegs(0);
    sts(0);
    for (int t = 0; t < tiles; t++) {
        __syncthreads();
        if (t + 1 < tiles) ldRegs((t + 1) * BK);
        compute(t & 1);
        if (t + 1 < tiles) sts((t + 1) & 1);
    }

    const int lr4 = lane >> 2, lc2 = (lane & 3) * 2;
    #pragma unroll
    for (int mi = 0; mi < MI; mi++) {
        #pragma unroll
        for (int na = 0; na < NA; na++) {
            float* d = acc[mi][na];
            int col = head * DHEAD + wn0 + na * 8 + lc2;
            int r0 = row0 + wm0 + mi * 16 + lr4;
            __half2 h01 = __floats2half2_rn(d[0], d[1]);
            __half2 h23 = __floats2half2_rn(d[2], d[3]);
            *reinterpret_cast<uint32_t*>(Of + (size_t)r0 * DMODEL + col) =
                *reinterpret_cast<uint32_t*>(&h01);
            *reinterpret_cast<uint32_t*>(Of + (size_t)(r0 + 8) * DMODEL + col) =
                *reinterpret_cast<uint32_t*>(&h23);
        }
    }
}

// ---------------- sparsemax tau: 4 rows per 256-thread block ----------------
__global__ __launch_bounds__(256)
void sparsemax_tau(const float* __restrict__ S, float* __restrict__ tau)
{
    const int tid = threadIdx.x;
    const int grp = tid >> 6;
    const int gt  = tid & 63;
    const int lane = tid & 31;
    const int wid = tid >> 5;
    const long long row = (long long)blockIdx.x * 4 + grp;

    const float4* z4 = reinterpret_cast<const float4*>(S + row * (long long)M_KV);
    float4 v4[16];
    #pragma unroll
    for (int j = 0; j < 16; j++) v4[j] = z4[gt + j * 64];
    float* v = reinterpret_cast<float*>(v4);

    __shared__ float red_s[8], red_c[8];
    __shared__ float s_tau[4];
    __shared__ int   s_done;

    float m = v[0];
    #pragma unroll
    for (int i = 1; i < 64; i++) m = fmaxf(m, v[i]);
    #pragma unroll
    for (int o = 16; o > 0; o >>= 1) m = fmaxf(m, __shfl_xor_sync(0xffffffffu, m, o));
    if (lane == 0) red_s[wid] = m;
    if (tid == 0) s_done = 0;
    __syncthreads();
    if (gt == 0) s_tau[grp] = fmaxf(red_s[grp * 2], red_s[grp * 2 + 1]) - 1.0f;
    __syncthreads();
    float t = s_tau[grp];

    for (int it = 0; it < 64; ++it) {
        float s = 0.f, c = 0.f;
        #pragma unroll
        for (int i = 0; i < 64; i++) {
            float d = v[i] - t;
            if (d > 0.f) { s += d; c += 1.f; }
        }
        #pragma unroll
        for (int o = 16; o > 0; o >>= 1) {
            s += __shfl_xor_sync(0xffffffffu, s, o);
            c += __shfl_xor_sync(0xffffffffu, c, o);
        }
        if (lane == 0) { red_s[wid] = s; red_c[wid] = c; }
        __syncthreads();
        if (gt == 0) {
            float St = red_s[grp * 2] + red_s[grp * 2 + 1];
            float Ct = red_c[grp * 2] + red_c[grp * 2 + 1];
            float delta = (St - 1.0f) / fmaxf(Ct, 1.0f);
            s_tau[grp] = t + delta;
            if (fabsf(delta) >= 1e-9f) atomicOr(&s_done, 1);
        }
        __syncthreads();
        t = s_tau[grp];
        int nd = s_done;
        __syncthreads();
        if (nd == 0) break;
        if (gt == 0) s_done = 0;
        __syncthreads();
    }
    if (gt == 0) tau[row] = t;
}

// ---------------- prep ----------------
__global__ __launch_bounds__(256)
void split_convert_f16(const float4* __restrict__ src, uint2* __restrict__ dh,
                       uint2* __restrict__ dl, int n4)
{
    int i = blockIdx.x * 256 + threadIdx.x;
    if (i >= n4) return;
    float4 v = src[i];
    uint32_t h01, l01, h23, l23;
    split2h(v.x, v.y, h01, l01);
    split2h(v.z, v.w, h23, l23);
    dh[i] = make_uint2(h01, h23);
    dl[i] = make_uint2(l01, l23);
}
__global__ __launch_bounds__(256)
void to_f16(const float4* __restrict__ src, uint2* __restrict__ dst, int n4)
{
    int i = blockIdx.x * 256 + threadIdx.x;
    if (i >= n4) return;
    float4 v = src[i];
    __half2 h01 = __floats2half2_rn(v.x, v.y);
    __half2 h23 = __floats2half2_rn(v.z, v.w);
    dst[i] = make_uint2(*reinterpret_cast<uint32_t*>(&h01), *reinterpret_cast<uint32_t*>(&h23));
}
// enc -> FINf fp16 single, columns [0, DMODEL)
__global__ __launch_bounds__(256)
void enc_to_fin(const float4* __restrict__ enc, uint16_t* __restrict__ f)
{
    int i = blockIdx.x * 256 + threadIdx.x;
    int row = i >> 8, cg = i & 255;
    float4 v = enc[i];
    __half2 h01 = __floats2half2_rn(v.x, v.y);
    __half2 h23 = __floats2half2_rn(v.z, v.w);
    int o = row * (2 * DMODEL) + cg * 4;
    *reinterpret_cast<uint2*>(f + o) =
        make_uint2(*reinterpret_cast<uint32_t*>(&h01), *reinterpret_cast<uint32_t*>(&h23));
}

// ---------------- host launcher ----------------
extern "C" void kernel_launch(void* const* d_in, const int* in_sizes, int n_in,
                              void* d_out, int out_size)
{
    const float* enc = (const float*)d_in[0];
    const float* mem = (const float*)d_in[1];
    const float* Wq  = (const float*)d_in[2];
    const float* bq  = (const float*)d_in[3];
    const float* Wk  = (const float*)d_in[4];
    const float* bk  = (const float*)d_in[5];
    const float* Wv  = (const float*)d_in[6];
    const float* bv  = (const float*)d_in[7];
    const float* Wo  = (const float*)d_in[8];
    const float* bo  = (const float*)d_in[9];
    const float* W1  = (const float*)d_in[10];
    const float* b1  = (const float*)d_in[11];
    const float* W2  = (const float*)d_in[12];
    const float* b2  = (const float*)d_in[13];
    float* out = (float*)d_out;

    uint16_t *pFINf, *pmemf;
    uint16_t *pWqh, *pWql, *pWkh, *pWkl, *pWvh, *pWvl, *pWoh, *pWol;
    uint16_t *pW1f, *pW2f;
    uint16_t *pQf, *pKf, *pVh, *pVl, *pOf, *pHf;
    float *pS, *pTau;
    cudaGetSymbolAddress((void**)&pFINf, g_FINf);
    cudaGetSymbolAddress((void**)&pmemf, g_memf);
    cudaGetSymbolAddress((void**)&pWqh,  g_Wqh);  cudaGetSymbolAddress((void**)&pWql,  g_Wql);
    cudaGetSymbolAddress((void**)&pWkh,  g_Wkh);  cudaGetSymbolAddress((void**)&pWkl,  g_Wkl);
    cudaGetSymbolAddress((void**)&pWvh,  g_Wvh);  cudaGetSymbolAddress((void**)&pWvl,  g_Wvl);
    cudaGetSymbolAddress((void**)&pWoh,  g_Woh);  cudaGetSymbolAddress((void**)&pWol,  g_Wol);
    cudaGetSymbolAddress((void**)&pW1f,  g_W1f);
    cudaGetSymbolAddress((void**)&pW2f,  g_W2f);
    cudaGetSymbolAddress((void**)&pQf,   g_Qf);
    cudaGetSymbolAddress((void**)&pKf,   g_Kf);
    cudaGetSymbolAddress((void**)&pVh,   g_Vh);   cudaGetSymbolAddress((void**)&pVl,   g_Vl);
    cudaGetSymbolAddress((void**)&pOf,   g_Of);
    cudaGetSymbolAddress((void**)&pHf,   g_Hf);
    cudaGetSymbolAddress((void**)&pS,    g_S);
    cudaGetSymbolAddress((void**)&pTau,  g_tau);

    dim3 blk(256);
    auto cvtH = [&](const float* s, uint16_t* h, uint16_t* l, int n) {
        int n4 = n / 4;
        split_convert_f16<<<(n4 + 255) / 256, blk>>>((const float4*)s, (uint2*)h, (uint2*)l, n4);
    };
    auto cvt1 = [&](const float* s, uint16_t* d, int n) {
        int n4 = n / 4;
        to_f16<<<(n4 + 255) / 256, blk>>>((const float4*)s, (uint2*)d, n4);
    };

    constexpr int BKP = 40;
    const int DS_2B = 2 * (128 * BKP + 2 * 128 * BKP) * 2;            // 61440
    const int DS_1B = 2 * (128 * BKP + 1 * 128 * BKP) * 2;            // 40960
    const int DS_PV = 2 * (128 * BKP + 2 * DHEAD * BKP) * 2 + 512;    // 41472

    auto* kProjQ = mma_gemm<2,128,128,32,64,2,false,false>;  // Q: split-B, fp16 single out
    auto* kProjK = mma_gemm<2,128,128,32,64,2,false,false>;  // K: split-B, fp16 single out
    auto* kProjV = mma_gemm<2,128,128,32,64,3,false,false>;  // V: split-B, fp16 hi/lo out
    auto* kWo    = mma_gemm<2,128,128,32,64,2,false,false>;  // Wo: split-B, single out
    auto* kQK    = mma_gemm<1,128,128,32,64,0,false,false>;  // QK: 1-pass, fp32 out
    auto* kW1    = mma_gemm<1,128,128,32,64,2,true ,false>;  // W1: 1-pass + ReLU
    auto* kW2    = mma_gemm<1,128,128,32,64,0,false,true >;  // W2: 1-pass, N=1000 guarded
    cudaFuncSetAttribute(kProjQ, cudaFuncAttributeMaxDynamicSharedMemorySize, DS_2B);
    cudaFuncSetAttribute(kProjV, cudaFuncAttributeMaxDynamicSharedMemorySize, DS_2B);
    cudaFuncSetAttribute(kQK   , cudaFuncAttributeMaxDynamicSharedMemorySize, DS_1B);
    cudaFuncSetAttribute(kW1   , cudaFuncAttributeMaxDynamicSharedMemorySize, DS_1B);
    cudaFuncSetAttribute(kW2   , cudaFuncAttributeMaxDynamicSharedMemorySize, DS_1B);
    cudaFuncSetAttribute(pv_gemm, cudaFuncAttributeMaxDynamicSharedMemorySize, DS_PV);

    // 0: enc -> FINf left half (fp16)
    enc_to_fin<<<(N_Q * DMODEL / 4) / 256, blk>>>((const float4*)enc, pFINf);
    // 1: mem -> fp16 single
    cvt1(mem, pmemf, M_KV * DMODEL);
    // 2-4: projection weights fp16 split
    cvtH(Wq, pWqh, pWql, DMODEL * DMODEL);
    cvtH(Wk, pWkh, pWkl, DMODEL * DMODEL);
    cvtH(Wv, pWvh, pWvl, DMODEL * DMODEL);
    // 5: Q = enc @ Wq^T + bq -> fp16 single
    kProjQ<<<dim3(DMODEL/128, N_Q/128, 1), blk, DS_2B>>>(
        N_Q, DMODEL, DMODEL, pFINf, 2*DMODEL, 0, pWqh, pWql, DMODEL, 0,
        nullptr, pQf, nullptr, DMODEL, 0, bq, 1.0f);
    // 6: K = mem @ Wk^T + bk -> fp16 single
    kProjK<<<dim3(DMODEL/128, M_KV/128, 1), blk, DS_2B>>>(
        M_KV, DMODEL, DMODEL, pmemf, DMODEL, 0, pWkh, pWkl, DMODEL, 0,
        nullptr, pKf, nullptr, DMODEL, 0, bk, 1.0f);
    // 7: V = mem @ Wv^T + bv -> fp16 split
    kProjV<<<dim3(DMODEL/128, M_KV/128, 1), blk, DS_2B>>>(
        M_KV, DMODEL, DMODEL, pmemf, DMODEL, 0, pWvh, pWvl, DMODEL, 0,
        nullptr, pVh, pVl, DMODEL, 0, bv, 1.0f);
    // 8: S[h] = (Q_h @ K_h^T) / 32  (1-pass fp16)
    kQK<<<dim3(M_KV/128, N_Q/128, NHEADS), blk, DS_1B>>>(
        N_Q, M_KV, DHEAD, pQf, DMODEL, (long long)DHEAD,
        pKf, nullptr, DMODEL, (long long)DHEAD,
        pS, nullptr, nullptr, M_KV, (long long)N_Q * M_KV, nullptr, 0.03125f);
    // 9: Wo fp16 split
    cvtH(Wo, pWoh, pWol, DMODEL * DMODEL);
    // 10: sparsemax -> tau
    sparsemax_tau<<<NHEADS * N_Q / 4, blk>>>(pS, pTau);
    // 11: O_h = max(S_h - tau, 0) @ V_h -> fp16 single
    pv_gemm<<<dim3(N_Q/128, NHEADS), blk, DS_PV>>>(pS, pTau, pVh, pVl, pOf);
    // 12: FINf[:, 1024:2048] = O @ Wo^T + bo (fp16 single)
    kWo<<<dim3(DMODEL/128, N_Q/128, 1), blk, DS_2B>>>(
        N_Q, DMODEL, DMODEL, pOf, DMODEL, 0, pWoh, pWol, DMODEL, 0,
        nullptr, pFINf + DMODEL, nullptr, 2*DMODEL, 0, bo, 1.0f);
    // 13: W1 fp16 single
    cvt1(W1, pW1f, DFF * 2 * DMODEL);
    // 14: H = relu(FINf @ W1^T + b1)  (1-pass fp16)
    kW1<<<dim3(DFF/128, N_Q/128, 1), blk, DS_1B>>>(
        N_Q, DFF, 2*DMODEL, pFINf, 2*DMODEL, 0, pW1f, nullptr, 2*DMODEL, 0,
        nullptr, pHf, nullptr, DFF, 0, b1, 1.0f);
    // 15: W2 fp16 single
    cvt1(W2, pW2f, DOUT * DFF);
    // 16: OUT = H @ W2^T + b2  (1-pass fp16, N = 1000)
    kW2<<<dim3((DOUT + 127)/128, N_Q/128, 1), blk, DS_1B>>>(
        N_Q, DOUT, DFF, pHf, DFF, 0, pW2f, nullptr, DFF, 0,
        out, nullptr, nullptr, DOUT, 0, b2, 1.0f);
}

// round 14
// speedup vs baseline: 1.4261x; 1.0395x over previous
#include <cuda_runtime.h>
#include <cuda_bf16.h>
#include <cuda_fp16.h>
#include <cstdint>
#include <math.h>

// Problem dims (fixed by the dataset)
#define N_Q    2048
#define M_KV   4096
#define DMODEL 1024
#define NHEADS 16
#define DHEAD  64
#define DFF    4096
#define DOUT   1000

// ---------------- scratch (device globals; no allocation allowed) ----------------
__device__ uint16_t g_FINf[N_Q * 2 * DMODEL];                       // fp16 single: [enc | attn-out]
__device__ uint16_t g_memf[M_KV * DMODEL];                          // fp16 single
__device__ uint16_t g_Wqh[DMODEL*DMODEL],  g_Wql[DMODEL*DMODEL];    // fp16 split
__device__ uint16_t g_Wkh[DMODEL*DMODEL],  g_Wkl[DMODEL*DMODEL];    // fp16 split
__device__ uint16_t g_Wvh[DMODEL*DMODEL],  g_Wvl[DMODEL*DMODEL];    // fp16 split
__device__ uint16_t g_Woh[DMODEL*DMODEL],  g_Wol[DMODEL*DMODEL];    // fp16 split
__device__ uint16_t g_W1f[DFF*2*DMODEL];                            // fp16 single
__device__ uint16_t g_W2f[DOUT*DFF];                                // fp16 single
__device__ uint16_t g_Qf[N_Q*DMODEL];                               // fp16 single
__device__ uint16_t g_Kf[M_KV*DMODEL];                              // fp16 single
__device__ uint16_t g_Vf[M_KV*DMODEL];                              // fp16 single
__device__ uint16_t g_Sf[(size_t)NHEADS * N_Q * M_KV];              // fp16 logits (256 MB)
__device__ float    g_tau[NHEADS * N_Q];
__device__ uint16_t g_Of[N_Q*DMODEL];                               // fp16 single
__device__ uint16_t g_Hf[N_Q*DFF];                                  // fp16 single

// ---------------- helpers ----------------
__device__ __forceinline__ uint32_t smem_u32(const void* p) {
    uint32_t a;
    asm("{ .reg .u64 t; cvta.to.shared.u64 t, %1; cvt.u32.u64 %0, t; }" : "=r"(a) : "l"(p));
    return a;
}
__device__ __forceinline__ void ldmx4(uint32_t* r, uint32_t a) {
    asm volatile("ldmatrix.sync.aligned.m8n8.x4.shared.b16 {%0,%1,%2,%3}, [%4];"
                 : "=r"(r[0]), "=r"(r[1]), "=r"(r[2]), "=r"(r[3]) : "r"(a));
}
__device__ __forceinline__ void mma_f16(float* d, const uint32_t* a, uint32_t b0, uint32_t b1) {
    asm volatile("mma.sync.aligned.m16n8k16.row.col.f32.f16.f16.f32 "
                 "{%0,%1,%2,%3}, {%4,%5,%6,%7}, {%8,%9}, {%0,%1,%2,%3};"
                 : "+f"(d[0]), "+f"(d[1]), "+f"(d[2]), "+f"(d[3])
                 : "r"(a[0]), "r"(a[1]), "r"(a[2]), "r"(a[3]), "r"(b0), "r"(b1));
}
__device__ __forceinline__ void cpa16(uint32_t s, const void* g) {
    asm volatile("cp.async.cg.shared.global [%0], [%1], 16;" :: "r"(s), "l"(g));
}
__device__ __forceinline__ void cpa16z(uint32_t s, const void* g, bool ok) {
    int sz = ok ? 16 : 0;
    asm volatile("cp.async.cg.shared.global [%0], [%1], 16, %2;" :: "r"(s), "l"(g), "r"(sz));
}
#define CPA_COMMIT() asm volatile("cp.async.commit_group;" ::: "memory")
#define CPA_WAIT0()  asm volatile("cp.async.wait_group 0;" ::: "memory")

// fp32 pair -> fp16 hi + fp16 residual
__device__ __forceinline__ void split2h(float a, float b, uint32_t& h, uint32_t& l) {
    __half2 hh = __floats2half2_rn(a, b);
    float2 hf = __half22float2(hh);
    __half2 ll = __floats2half2_rn(a - hf.x, b - hf.y);
    h = *reinterpret_cast<uint32_t*>(&hh);
    l = *reinterpret_cast<uint32_t*>(&ll);
}

// ====================== async double-buffered fp16 MMA GEMM ======================
// C = alpha * A @ B^T + bias (+ReLU).  A fp16 single.
// NPB=2: B fp16 hi/lo (2-pass).  NPB=1: B fp16 single (1-pass).
// Batch via blockIdx.z. EPI: 0 = fp32 -> Cf; 2 = fp16 single -> Chi.
template<int NPB, int BM, int BN, int WM, int WN, int EPI, bool RELU, bool NGUARD>
__global__ __launch_bounds__(256, 2)
void mma_gemm(int M, int N, int K,
              const uint16_t* __restrict__ Ah, int lda, long long sAz,
              const uint16_t* __restrict__ Bh, const uint16_t* __restrict__ Bl, int ldb, long long sBz,
              float* __restrict__ Cf, uint16_t* __restrict__ Chi,
              long long ldc, long long sCz,
              const float* __restrict__ bias, float alpha)
{
    constexpr int BK = 32, BKP = 40;
    constexpr int WNC = BN / WN;
    constexpr int MI = WM / 16, NI2 = WN / 16, NA = WN / 8;
    constexpr int SA = BM * BKP, SB = BN * BKP;
    constexpr int STAGE_BYTES = (SA + NPB * SB) * 2;

    extern __shared__ __align__(16) char smem[];
    const uint32_t uS = smem_u32(smem);

    const int tid = threadIdx.x, wid = tid >> 5, lane = tid & 31;
    Ah += (long long)blockIdx.z * sAz;
    Bh += (long long)blockIdx.z * sBz;
    if (NPB == 2) Bl += (long long)blockIdx.z * sBz;
    const long long coff = (long long)blockIdx.z * sCz;
    const int row0 = blockIdx.y * BM;
    const int col0 = blockIdx.x * BN;
    const int wm0 = (wid / WNC) * WM;
    const int wn0 = (wid % WNC) * WN;

    float acc[MI][NA][4];
    #pragma unroll
    for (int i = 0; i < MI; i++)
        #pragma unroll
        for (int j = 0; j < NA; j++)
            #pragma unroll
            for (int q = 0; q < 4; q++) acc[i][j][q] = 0.f;

    auto loadT = [&](int stage, int kt) {
        uint32_t base = uS + stage * STAGE_BYTES;
        #pragma unroll
        for (int i = 0; i < (BM * 4) / 256; i++) {
            int ch = tid + i * 256, r = ch >> 2, q = ch & 3;
            cpa16(base + r * 80 + q * 16, Ah + (size_t)(row0 + r) * lda + kt + q * 8);
        }
        #pragma unroll
        for (int i = 0; i < (BN * 4) / 256; i++) {
            int ch = tid + i * 256, r = ch >> 2, q = ch & 3;
            bool ok = !NGUARD || (col0 + r) < N;
            cpa16z(base + SA * 2 + r * 80 + q * 16,
                   Bh + (size_t)(col0 + r) * ldb + kt + q * 8, ok);
            if (NPB == 2)
                cpa16z(base + (SA + SB) * 2 + r * 80 + q * 16,
                       Bl + (size_t)(col0 + r) * ldb + kt + q * 8, ok);
        }
    };
    auto compute = [&](int stage) {
        uint32_t bA = uS + stage * STAGE_BYTES;
        uint32_t bBh = bA + SA * 2, bBl = bA + (SA + SB) * 2;
        const int lr = lane & 15, lc = (lane >> 4) * 8;
        #pragma unroll
        for (int kk = 0; kk < BK; kk += 16) {
            uint32_t bh[NI2][4], bl[NI2][4];
            #pragma unroll
            for (int ni = 0; ni < NI2; ni++) {
                uint32_t off = (uint32_t)((wn0 + ni * 16 + lr) * 80 + (kk + lc) * 2);
                ldmx4(bh[ni], bBh + off);
                if (NPB == 2) ldmx4(bl[ni], bBl + off);
            }
            #pragma unroll
            for (int mi = 0; mi < MI; mi++) {
                uint32_t ah[4];
                uint32_t off = (uint32_t)((wm0 + mi * 16 + lr) * 80 + (kk + lc) * 2);
                ldmx4(ah, bA + off);
                #pragma unroll
                for (int na = 0; na < NA; na++) {
                    int ni = na >> 1, sel = na & 1;
                    mma_f16(acc[mi][na], ah, bh[ni][sel], bh[ni][sel + 2]);
                    if (NPB == 2)
                        mma_f16(acc[mi][na], ah, bl[ni][sel], bl[ni][sel + 2]);
                }
            }
        }
    };

    const int tiles = K / BK;
    loadT(0, 0);
    CPA_COMMIT();
    for (int t = 0; t < tiles; t++) {
        int cur = t & 1;
        CPA_WAIT0();
        __syncthreads();
        if (t + 1 < tiles) loadT((t + 1) & 1, (t + 1) * BK);
        CPA_COMMIT();
        compute(cur);
    }

    // ---------------- epilogue ----------------
    const int lr4 = lane >> 2, lc2 = (lane & 3) * 2;
    #pragma unroll
    for (int mi = 0; mi < MI; mi++) {
        #pragma unroll
        for (int na = 0; na < NA; na++) {
            float* d = acc[mi][na];
            int col = col0 + wn0 + na * 8 + lc2;
            int r0 = row0 + wm0 + mi * 16 + lr4;
            float bb0 = 0.f, bb1 = 0.f;
            if (bias) {
                if (!NGUARD || col     < N) bb0 = bias[col];
                if (!NGUARD || col + 1 < N) bb1 = bias[col + 1];
            }
            float v0 = d[0] * alpha + bb0, v1 = d[1] * alpha + bb1;
            float v2 = d[2] * alpha + bb0, v3 = d[3] * alpha + bb1;
            if (RELU) {
                v0 = fmaxf(v0, 0.f); v1 = fmaxf(v1, 0.f);
                v2 = fmaxf(v2, 0.f); v3 = fmaxf(v3, 0.f);
            }
            long long b0i = (long long)r0 * ldc + col + coff;
            long long b1i = (long long)(r0 + 8) * ldc + col + coff;
            if (EPI == 0) {
                if (!NGUARD || col + 1 < N) {
                    *reinterpret_cast<float2*>(Cf + b0i) = make_float2(v0, v1);
                    *reinterpret_cast<float2*>(Cf + b1i) = make_float2(v2, v3);
                } else if (col < N) {
                    Cf[b0i] = v0;
                    Cf[b1i] = v2;
                }
            } else {  // EPI==2: fp16 single
                __half2 h01 = __floats2half2_rn(v0, v1);
                __half2 h23 = __floats2half2_rn(v2, v3);
                *reinterpret_cast<uint32_t*>(Chi + b0i) = *reinterpret_cast<uint32_t*>(&h01);
                *reinterpret_cast<uint32_t*>(Chi + b1i) = *reinterpret_cast<uint32_t*>(&h23);
            }
        }
    }
}

// ====================== V projection with fp16-split weights, fp16 single out ==================
// (reuses mma_gemm<2,...,EPI=2>)

// ====================== PV: O_h = sparsemax(S_h) @ V_h  (all fp16 1-pass) ======================
__global__ __launch_bounds__(256, 2)
void pv_gemm(const uint16_t* __restrict__ S, const float* __restrict__ tau,
             const uint16_t* __restrict__ Vf, uint16_t* __restrict__ Of)
{
    constexpr int BM = 128, BK = 32, BKP = 40;
    constexpr int SA = BM * BKP, SB = DHEAD * BKP;
    constexpr int STAGE = (SA + SB) * 2;

    extern __shared__ __align__(16) char smem[];
    float* sTau = reinterpret_cast<float*>(smem + 2 * STAGE);

    const int tid = threadIdx.x, wid = tid >> 5, lane = tid & 31;
    const int head = blockIdx.y;
    const int row0 = blockIdx.x * BM;
    const uint16_t* Sb = S + (size_t)head * N_Q * M_KV + (size_t)row0 * M_KV;
    const float* tb = tau + head * N_Q + row0;
    const uint16_t* Vb = Vf + head * DHEAD;

    if (tid < BM) sTau[tid] = tb[tid];
    __syncthreads();

    const int wm0 = (wid >> 2) * 64;
    const int wn0 = (wid & 3) * 16;
    constexpr int MI = 4, NA = 2;

    float acc[MI][NA][4];
    #pragma unroll
    for (int i = 0; i < MI; i++)
        #pragma unroll
        for (int j = 0; j < NA; j++)
            #pragma unroll
            for (int q = 0; q < 4; q++) acc[i][j][q] = 0.f;

    uint2 aReg[4];                      // 4 rows x 4 halves
    uint4 bReg;                         // 8 halves of V
    const int a_r = tid >> 3, a_c = (tid & 7) * 4;
    const int b_k = tid >> 3, b_c = (tid & 7) * 8;

    auto ldRegs = [&](int kt) {
        #pragma unroll
        for (int i = 0; i < 4; i++)
            aReg[i] = *reinterpret_cast<const uint2*>(Sb + (size_t)(a_r + i * 32) * M_KV + kt + a_c);
        bReg = *reinterpret_cast<const uint4*>(Vb + (size_t)(kt + b_k) * DMODEL + b_c);
    };
    auto sts = [&](int st) {
        uint16_t* base = reinterpret_cast<uint16_t*>(smem + st * STAGE);
        uint16_t* As = base;
        uint16_t* Bs = base + SA;
        #pragma unroll
        for (int i = 0; i < 4; i++) {
            int r = a_r + i * 32;
            float tv = sTau[r];
            float2 s01 = __half22float2(*reinterpret_cast<const __half2*>(&aReg[i].x));
            float2 s23 = __half22float2(*reinterpret_cast<const __half2*>(&aReg[i].y));
            __half2 p01 = __floats2half2_rn(fmaxf(s01.x - tv, 0.f), fmaxf(s01.y - tv, 0.f));
            __half2 p23 = __floats2half2_rn(fmaxf(s23.x - tv, 0.f), fmaxf(s23.y - tv, 0.f));
            *reinterpret_cast<uint2*>(As + r * BKP + a_c) =
                make_uint2(*reinterpret_cast<uint32_t*>(&p01), *reinterpret_cast<uint32_t*>(&p23));
        }
        uint16_t tv16[8];
        *reinterpret_cast<uint4*>(tv16) = bReg;
        #pragma unroll
        for (int j = 0; j < 8; j++)
            Bs[(b_c + j) * BKP + b_k] = tv16[j];
    };
    auto compute = [&](int st) {
        uint32_t base = smem_u32(smem) + st * STAGE;
        uint32_t uA = base, uB = base + SA * 2;
        const int lr = lane & 15, lc = (lane >> 4) * 8;
        #pragma unroll
        for (int kk = 0; kk < BK; kk += 16) {
            uint32_t bh[4];
            uint32_t boff = (uint32_t)((wn0 + lr) * BKP + kk + lc) * 2;
            ldmx4(bh, uB + boff);
            #pragma unroll
            for (int mi = 0; mi < MI; mi++) {
                uint32_t ah[4];
                uint32_t aoff = (uint32_t)((wm0 + mi * 16 + lr) * BKP + kk + lc) * 2;
                ldmx4(ah, uA + aoff);
                #pragma unroll
                for (int na = 0; na < NA; na++)
                    mma_f16(acc[mi][na], ah, bh[na], bh[na + 2]);
            }
        }
    };

    const int tiles = M_KV / BK;
    ldRegs(0);
    sts(0);
    for (int t = 0; t < tiles; t++) {
        __syncthreads();
        if (t + 1 < tiles) ldRegs((t + 1) * BK);
        compute(t & 1);
        if (t + 1 < tiles) sts((t + 1) & 1);
    }

    const int lr4 = lane >> 2, lc2 = (lane & 3) * 2;
    #pragma unroll
    for (int mi = 0; mi < MI; mi++) {
        #pragma unroll
        for (int na = 0; na < NA; na++) {
            float* d = acc[mi][na];
            int col = head * DHEAD + wn0 + na * 8 + lc2;
            int r0 = row0 + wm0 + mi * 16 + lr4;
            __half2 h01 = __floats2half2_rn(d[0], d[1]);
            __half2 h23 = __floats2half2_rn(d[2], d[3]);
            *reinterpret_cast<uint32_t*>(Of + (size_t)r0 * DMODEL + col) =
                *reinterpret_cast<uint32_t*>(&h01);
            *reinterpret_cast<uint32_t*>(Of + (size_t)(r0 + 8) * DMODEL + col) =
                *reinterpret_cast<uint32_t*>(&h23);
        }
    }
}

// ---------------- sparsemax tau: fp16 S in, 4 rows per 256-thread block ----------------
__global__ __launch_bounds__(256)
void sparsemax_tau(const uint16_t* __restrict__ S, float* __restrict__ tau)
{
    const int tid = threadIdx.x;
    const int grp = tid >> 6;
    const int gt  = tid & 63;
    const int lane = tid & 31;
    const int wid = tid >> 5;
    const long long row = (long long)blockIdx.x * 4 + grp;

    // 64 halves per thread: 16 x uint2 (4 halves each), stride 64 threads
    const uint2* z2 = reinterpret_cast<const uint2*>(S + row * (long long)M_KV);
    float v[64];
    #pragma unroll
    for (int j = 0; j < 16; j++) {
        uint2 p = z2[gt + j * 64];
        float2 a = __half22float2(*reinterpret_cast<const __half2*>(&p.x));
        float2 b = __half22float2(*reinterpret_cast<const __half2*>(&p.y));
        v[j * 4 + 0] = a.x; v[j * 4 + 1] = a.y;
        v[j * 4 + 2] = b.x; v[j * 4 + 3] = b.y;
    }

    __shared__ float red_s[8], red_c[8];
    __shared__ float s_tau[4];
    __shared__ int   s_done;

    float m = v[0];
    #pragma unroll
    for (int i = 1; i < 64; i++) m = fmaxf(m, v[i]);
    #pragma unroll
    for (int o = 16; o > 0; o >>= 1) m = fmaxf(m, __shfl_xor_sync(0xffffffffu, m, o));
    if (lane == 0) red_s[wid] = m;
    if (tid == 0) s_done = 0;
    __syncthreads();
    if (gt == 0) s_tau[grp] = fmaxf(red_s[grp * 2], red_s[grp * 2 + 1]) - 1.0f;
    __syncthreads();
    float t = s_tau[grp];

    for (int it = 0; it < 64; ++it) {
        float s = 0.f, c = 0.f;
        #pragma unroll
        for (int i = 0; i < 64; i++) {
            float d = v[i] - t;
            if (d > 0.f) { s += d; c += 1.f; }
        }
        #pragma unroll
        for (int o = 16; o > 0; o >>= 1) {
            s += __shfl_xor_sync(0xffffffffu, s, o);
            c += __shfl_xor_sync(0xffffffffu, c, o);
        }
        if (lane == 0) { red_s[wid] = s; red_c[wid] = c; }
        __syncthreads();
        if (gt == 0) {
            float St = red_s[grp * 2] + red_s[grp * 2 + 1];
            float Ct = red_c[grp * 2] + red_c[grp * 2 + 1];
            float delta = (St - 1.0f) / fmaxf(Ct, 1.0f);
            s_tau[grp] = t + delta;
            if (fabsf(delta) >= 1e-9f) atomicOr(&s_done, 1);
        }
        __syncthreads();
        t = s_tau[grp];
        int nd = s_done;
        __syncthreads();
        if (nd == 0) break;
        if (gt == 0) s_done = 0;
        __syncthreads();
    }
    if (gt == 0) tau[row] = t;
}

// ---------------- prep ----------------
__global__ __launch_bounds__(256)
void split_convert_f16(const float4* __restrict__ src, uint2* __restrict__ dh,
                       uint2* __restrict__ dl, int n4)
{
    int i = blockIdx.x * 256 + threadIdx.x;
    if (i >= n4) return;
    float4 v = src[i];
    uint32_t h01, l01, h23, l23;
    split2h(v.x, v.y, h01, l01);
    split2h(v.z, v.w, h23, l23);
    dh[i] = make_uint2(h01, h23);
    dl[i] = make_uint2(l01, l23);
}
__global__ __launch_bounds__(256)
void to_f16(const float4* __restrict__ src, uint2* __restrict__ dst, int n4)
{
    int i = blockIdx.x * 256 + threadIdx.x;
    if (i >= n4) return;
    float4 v = src[i];
    __half2 h01 = __floats2half2_rn(v.x, v.y);
    __half2 h23 = __floats2half2_rn(v.z, v.w);
    dst[i] = make_uint2(*reinterpret_cast<uint32_t*>(&h01), *reinterpret_cast<uint32_t*>(&h23));
}
// enc -> FINf fp16 single, columns [0, DMODEL)
__global__ __launch_bounds__(256)
void enc_to_fin(const float4* __restrict__ enc, uint16_t* __restrict__ f)
{
    int i = blockIdx.x * 256 + threadIdx.x;
    int row = i >> 8, cg = i & 255;
    float4 v = enc[i];
    __half2 h01 = __floats2half2_rn(v.x, v.y);
    __half2 h23 = __floats2half2_rn(v.z, v.w);
    int o = row * (2 * DMODEL) + cg * 4;
    *reinterpret_cast<uint2*>(f + o) =
        make_uint2(*reinterpret_cast<uint32_t*>(&h01), *reinterpret_cast<uint32_t*>(&h23));
}

// ---------------- host launcher ----------------
extern "C" void kernel_launch(void* const* d_in, const int* in_sizes, int n_in,
                              void* d_out, int out_size)
{
    const float* enc = (const float*)d_in[0];
    const float* mem = (const float*)d_in[1];
    const float* Wq  = (const float*)d_in[2];
    const float* bq  = (const float*)d_in[3];
    const float* Wk  = (const float*)d_in[4];
    const float* bk  = (const float*)d_in[5];
    const float* Wv  = (const float*)d_in[6];
    const float* bv  = (const float*)d_in[7];
    const float* Wo  = (const float*)d_in[8];
    const float* bo  = (const float*)d_in[9];
    const float* W1  = (const float*)d_in[10];
    const float* b1  = (const float*)d_in[11];
    const float* W2  = (const float*)d_in[12];
    const float* b2  = (const float*)d_in[13];
    float* out = (float*)d_out;

    uint16_t *pFINf, *pmemf;
    uint16_t *pWqh, *pWql, *pWkh, *pWkl, *pWvh, *pWvl, *pWoh, *pWol;
    uint16_t *pW1f, *pW2f;
    uint16_t *pQf, *pKf, *pVf, *pSf, *pOf, *pHf;
    float *pTau;
    cudaGetSymbolAddress((void**)&pFINf, g_FINf);
    cudaGetSymbolAddress((void**)&pmemf, g_memf);
    cudaGetSymbolAddress((void**)&pWqh,  g_Wqh);  cudaGetSymbolAddress((void**)&pWql,  g_Wql);
    cudaGetSymbolAddress((void**)&pWkh,  g_Wkh);  cudaGetSymbolAddress((void**)&pWkl,  g_Wkl);
    cudaGetSymbolAddress((void**)&pWvh,  g_Wvh);  cudaGetSymbolAddress((void**)&pWvl,  g_Wvl);
    cudaGetSymbolAddress((void**)&pWoh,  g_Woh);  cudaGetSymbolAddress((void**)&pWol,  g_Wol);
    cudaGetSymbolAddress((void**)&pW1f,  g_W1f);
    cudaGetSymbolAddress((void**)&pW2f,  g_W2f);
    cudaGetSymbolAddress((void**)&pQf,   g_Qf);
    cudaGetSymbolAddress((void**)&pKf,   g_Kf);
    cudaGetSymbolAddress((void**)&pVf,   g_Vf);
    cudaGetSymbolAddress((void**)&pSf,   g_Sf);
    cudaGetSymbolAddress((void**)&pOf,   g_Of);
    cudaGetSymbolAddress((void**)&pHf,   g_Hf);
    cudaGetSymbolAddress((void**)&pTau,  g_tau);

    dim3 blk(256);
    auto cvtH = [&](const float* s, uint16_t* h, uint16_t* l, int n) {
        int n4 = n / 4;
        split_convert_f16<<<(n4 + 255) / 256, blk>>>((const float4*)s, (uint2*)h, (uint2*)l, n4);
    };
    auto cvt1 = [&](const float* s, uint16_t* d, int n) {
        int n4 = n / 4;
        to_f16<<<(n4 + 255) / 256, blk>>>((const float4*)s, (uint2*)d, n4);
    };

    constexpr int BKP = 40;
    const int DS_2B = 2 * (128 * BKP + 2 * 128 * BKP) * 2;            // 61440
    const int DS_1B = 2 * (128 * BKP + 1 * 128 * BKP) * 2;            // 40960
    const int DS_PV = 2 * (128 * BKP + DHEAD * BKP) * 2 + 512;        // 31232

    auto* kProj  = mma_gemm<2,128,128,32,64,2,false,false>;  // Q/K/V/Wo: split-B, fp16 single out
    auto* kQK    = mma_gemm<1,128,128,32,64,2,false,false>;  // QK: 1-pass, fp16 out
    auto* kW1    = mma_gemm<1,128,128,32,64,2,true ,false>;  // W1: 1-pass + ReLU
    auto* kW2    = mma_gemm<1,128,128,32,64,0,false,true >;  // W2: 1-pass, N=1000 guarded
    cudaFuncSetAttribute(kProj, cudaFuncAttributeMaxDynamicSharedMemorySize, DS_2B);
    cudaFuncSetAttribute(kQK  , cudaFuncAttributeMaxDynamicSharedMemorySize, DS_1B);
    cudaFuncSetAttribute(kW1  , cudaFuncAttributeMaxDynamicSharedMemorySize, DS_1B);
    cudaFuncSetAttribute(kW2  , cudaFuncAttributeMaxDynamicSharedMemorySize, DS_1B);
    cudaFuncSetAttribute(pv_gemm, cudaFuncAttributeMaxDynamicSharedMemorySize, DS_PV);

    // 0: enc -> FINf left half (fp16)
    enc_to_fin<<<(N_Q * DMODEL / 4) / 256, blk>>>((const float4*)enc, pFINf);
    // 1: mem -> fp16 single
    cvt1(mem, pmemf, M_KV * DMODEL);
    // 2-4: projection weights fp16 split
    cvtH(Wq, pWqh, pWql, DMODEL * DMODEL);
    cvtH(Wk, pWkh, pWkl, DMODEL * DMODEL);
    cvtH(Wv, pWvh, pWvl, DMODEL * DMODEL);
    // 5: Q = enc @ Wq^T + bq -> fp16 single
    kProj<<<dim3(DMODEL/128, N_Q/128, 1), blk, DS_2B>>>(
        N_Q, DMODEL, DMODEL, pFINf, 2*DMODEL, 0, pWqh, pWql, DMODEL, 0,
        nullptr, pQf, DMODEL, 0, bq, 1.0f);
    // 6: K = mem @ Wk^T + bk -> fp16 single
    kProj<<<dim3(DMODEL/128, M_KV/128, 1), blk, DS_2B>>>(
        M_KV, DMODEL, DMODEL, pmemf, DMODEL, 0, pWkh, pWkl, DMODEL, 0,
        nullptr, pKf, DMODEL, 0, bk, 1.0f);
    // 7: V = mem @ Wv^T + bv -> fp16 single
    kProj<<<dim3(DMODEL/128, M_KV/128, 1), blk, DS_2B>>>(
        M_KV, DMODEL, DMODEL, pmemf, DMODEL, 0, pWvh, pWvl, DMODEL, 0,
        nullptr, pVf, DMODEL, 0, bv, 1.0f);
    // 8: S[h] = (Q_h @ K_h^T) / 32  (1-pass fp16, fp16 out)
    kQK<<<dim3(M_KV/128, N_Q/128, NHEADS), blk, DS_1B>>>(
        N_Q, M_KV, DHEAD, pQf, DMODEL, (long long)DHEAD,
        pKf, nullptr, DMODEL, (long long)DHEAD,
        nullptr, pSf, M_KV, (long long)N_Q * M_KV, nullptr, 0.03125f);
    // 9: Wo fp16 split
    cvtH(Wo, pWoh, pWol, DMODEL * DMODEL);
    // 10: sparsemax -> tau (fp16 S)
    sparsemax_tau<<<NHEADS * N_Q / 4, blk>>>(pSf, pTau);
    // 11: O_h = max(S_h - tau, 0) @ V_h -> fp16 single (1-pass)
    pv_gemm<<<dim3(N_Q/128, NHEADS), blk, DS_PV>>>(pSf, pTau, pVf, pOf);
    // 12: FINf[:, 1024:2048] = O @ Wo^T + bo (fp16 single)
    kProj<<<dim3(DMODEL/128, N_Q/128, 1), blk, DS_2B>>>(
        N_Q, DMODEL, DMODEL, pOf, DMODEL, 0, pWoh, pWol, DMODEL, 0,
        nullptr, pFINf + DMODEL, 2*DMODEL, 0, bo, 1.0f);
    // 13: W1 fp16 single
    cvt1(W1, pW1f, DFF * 2 * DMODEL);
    // 14: H = relu(FINf @ W1^T + b1)  (1-pass fp16)
    kW1<<<dim3(DFF/128, N_Q/128, 1), blk, DS_1B>>>(
        N_Q, DFF, 2*DMODEL, pFINf, 2*DMODEL, 0, pW1f, nullptr, 2*DMODEL, 0,
        nullptr, pHf, DFF, 0, b1, 1.0f);
    // 15: W2 fp16 single
    cvt1(W2, pW2f, DOUT * DFF);
    // 16: OUT = H @ W2^T + b2  (1-pass fp16, N = 1000)
    kW2<<<dim3((DOUT + 127)/128, N_Q/128, 1), blk, DS_1B>>>(
        N_Q, DOUT, DFF, pHf, DFF, 0, pW2f, nullptr, DFF, 0,
        out, nullptr, DOUT, 0, b2, 1.0f);
}

// round 15
// speedup vs baseline: 1.4611x; 1.0245x over previous
#include <cuda_runtime.h>
#include <cuda_bf16.h>
#include <cuda_fp16.h>
#include <cstdint>
#include <math.h>

// Problem dims (fixed by the dataset)
#define N_Q    2048
#define M_KV   4096
#define DMODEL 1024
#define NHEADS 16
#define DHEAD  64
#define DFF    4096
#define DOUT   1000
#define NROWS  (NHEADS * N_Q)

// ---------------- scratch (device globals; no allocation allowed) ----------------
__device__ uint16_t g_FINf[N_Q * 2 * DMODEL];                       // fp16 single: [enc | attn-out]
__device__ uint16_t g_memf[M_KV * DMODEL];                          // fp16 single
__device__ uint16_t g_Wqh[DMODEL*DMODEL],  g_Wql[DMODEL*DMODEL];    // fp16 split
__device__ uint16_t g_Wkh[DMODEL*DMODEL],  g_Wkl[DMODEL*DMODEL];    // fp16 split
__device__ uint16_t g_Wvh[DMODEL*DMODEL],  g_Wvl[DMODEL*DMODEL];    // fp16 split
__device__ uint16_t g_Woh[DMODEL*DMODEL],  g_Wol[DMODEL*DMODEL];    // fp16 split
__device__ uint16_t g_W1f[DFF*2*DMODEL];                            // fp16 single
__device__ uint16_t g_W2f[DOUT*DFF];                                // fp16 single
__device__ uint16_t g_Qf[N_Q*DMODEL];                               // fp16 single
__device__ uint16_t g_Kf[M_KV*DMODEL];                              // fp16 single
__device__ uint16_t g_Vf[M_KV*DMODEL];                              // fp16 single
__device__ uint16_t g_Sf[(size_t)NROWS * M_KV];                     // fp16 logits (256 MB)
__device__ uint32_t g_list[(size_t)NROWS * M_KV];                   // per-row (col | p<<16)
__device__ uint16_t g_nnz[2 * NROWS];                               // per-row segment counts
__device__ uint16_t g_Of[N_Q*DMODEL];                               // fp16 single
__device__ uint16_t g_Hf[N_Q*DFF];                                  // fp16 single

// ---------------- helpers ----------------
__device__ __forceinline__ uint32_t smem_u32(const void* p) {
    uint32_t a;
    asm("{ .reg .u64 t; cvta.to.shared.u64 t, %1; cvt.u32.u64 %0, t; }" : "=r"(a) : "l"(p));
    return a;
}
__device__ __forceinline__ void ldmx4(uint32_t* r, uint32_t a) {
    asm volatile("ldmatrix.sync.aligned.m8n8.x4.shared.b16 {%0,%1,%2,%3}, [%4];"
                 : "=r"(r[0]), "=r"(r[1]), "=r"(r[2]), "=r"(r[3]) : "r"(a));
}
__device__ __forceinline__ void mma_f16(float* d, const uint32_t* a, uint32_t b0, uint32_t b1) {
    asm volatile("mma.sync.aligned.m16n8k16.row.col.f32.f16.f16.f32 "
                 "{%0,%1,%2,%3}, {%4,%5,%6,%7}, {%8,%9}, {%0,%1,%2,%3};"
                 : "+f"(d[0]), "+f"(d[1]), "+f"(d[2]), "+f"(d[3])
                 : "r"(a[0]), "r"(a[1]), "r"(a[2]), "r"(a[3]), "r"(b0), "r"(b1));
}
__device__ __forceinline__ void cpa16(uint32_t s, const void* g) {
    asm volatile("cp.async.cg.shared.global [%0], [%1], 16;" :: "r"(s), "l"(g));
}
__device__ __forceinline__ void cpa16z(uint32_t s, const void* g, bool ok) {
    int sz = ok ? 16 : 0;
    asm volatile("cp.async.cg.shared.global [%0], [%1], 16, %2;" :: "r"(s), "l"(g), "r"(sz));
}
#define CPA_COMMIT() asm volatile("cp.async.commit_group;" ::: "memory")
#define CPA_WAIT0()  asm volatile("cp.async.wait_group 0;" ::: "memory")

// fp32 pair -> fp16 hi + fp16 residual
__device__ __forceinline__ void split2h(float a, float b, uint32_t& h, uint32_t& l) {
    __half2 hh = __floats2half2_rn(a, b);
    float2 hf = __half22float2(hh);
    __half2 ll = __floats2half2_rn(a - hf.x, b - hf.y);
    h = *reinterpret_cast<uint32_t*>(&hh);
    l = *reinterpret_cast<uint32_t*>(&ll);
}

// ====================== async double-buffered fp16 MMA GEMM ======================
// C = alpha * A @ B^T + bias (+ReLU).  A fp16 single.
// NPB=2: B fp16 hi/lo (2-pass).  NPB=1: B fp16 single (1-pass).
// Batch via blockIdx.z. EPI: 0 = fp32 -> Cf; 2 = fp16 single -> Chi.
template<int NPB, int BM, int BN, int WM, int WN, int EPI, bool RELU, bool NGUARD>
__global__ __launch_bounds__(256, 2)
void mma_gemm(int M, int N, int K,
              const uint16_t* __restrict__ Ah, int lda, long long sAz,
              const uint16_t* __restrict__ Bh, const uint16_t* __restrict__ Bl, int ldb, long long sBz,
              float* __restrict__ Cf, uint16_t* __restrict__ Chi,
              long long ldc, long long sCz,
              const float* __restrict__ bias, float alpha)
{
    constexpr int BK = 32, BKP = 40;
    constexpr int WNC = BN / WN;
    constexpr int MI = WM / 16, NI2 = WN / 16, NA = WN / 8;
    constexpr int SA = BM * BKP, SB = BN * BKP;
    constexpr int STAGE_BYTES = (SA + NPB * SB) * 2;

    extern __shared__ __align__(16) char smem[];
    const uint32_t uS = smem_u32(smem);

    const int tid = threadIdx.x, wid = tid >> 5, lane = tid & 31;
    Ah += (long long)blockIdx.z * sAz;
    Bh += (long long)blockIdx.z * sBz;
    if (NPB == 2) Bl += (long long)blockIdx.z * sBz;
    const long long coff = (long long)blockIdx.z * sCz;
    const int row0 = blockIdx.y * BM;
    const int col0 = blockIdx.x * BN;
    const int wm0 = (wid / WNC) * WM;
    const int wn0 = (wid % WNC) * WN;

    float acc[MI][NA][4];
    #pragma unroll
    for (int i = 0; i < MI; i++)
        #pragma unroll
        for (int j = 0; j < NA; j++)
            #pragma unroll
            for (int q = 0; q < 4; q++) acc[i][j][q] = 0.f;

    auto loadT = [&](int stage, int kt) {
        uint32_t base = uS + stage * STAGE_BYTES;
        #pragma unroll
        for (int i = 0; i < (BM * 4) / 256; i++) {
            int ch = tid + i * 256, r = ch >> 2, q = ch & 3;
            cpa16(base + r * 80 + q * 16, Ah + (size_t)(row0 + r) * lda + kt + q * 8);
        }
        #pragma unroll
        for (int i = 0; i < (BN * 4) / 256; i++) {
            int ch = tid + i * 256, r = ch >> 2, q = ch & 3;
            bool ok = !NGUARD || (col0 + r) < N;
            cpa16z(base + SA * 2 + r * 80 + q * 16,
                   Bh + (size_t)(col0 + r) * ldb + kt + q * 8, ok);
            if (NPB == 2)
                cpa16z(base + (SA + SB) * 2 + r * 80 + q * 16,
                       Bl + (size_t)(col0 + r) * ldb + kt + q * 8, ok);
        }
    };
    auto compute = [&](int stage) {
        uint32_t bA = uS + stage * STAGE_BYTES;
        uint32_t bBh = bA + SA * 2, bBl = bA + (SA + SB) * 2;
        const int lr = lane & 15, lc = (lane >> 4) * 8;
        #pragma unroll
        for (int kk = 0; kk < BK; kk += 16) {
            uint32_t bh[NI2][4], bl[NI2][4];
            #pragma unroll
            for (int ni = 0; ni < NI2; ni++) {
                uint32_t off = (uint32_t)((wn0 + ni * 16 + lr) * 80 + (kk + lc) * 2);
                ldmx4(bh[ni], bBh + off);
                if (NPB == 2) ldmx4(bl[ni], bBl + off);
            }
            #pragma unroll
            for (int mi = 0; mi < MI; mi++) {
                uint32_t ah[4];
                uint32_t off = (uint32_t)((wm0 + mi * 16 + lr) * 80 + (kk + lc) * 2);
                ldmx4(ah, bA + off);
                #pragma unroll
                for (int na = 0; na < NA; na++) {
                    int ni = na >> 1, sel = na & 1;
                    mma_f16(acc[mi][na], ah, bh[ni][sel], bh[ni][sel + 2]);
                    if (NPB == 2)
                        mma_f16(acc[mi][na], ah, bl[ni][sel], bl[ni][sel + 2]);
                }
            }
        }
    };

    const int tiles = K / BK;
    loadT(0, 0);
    CPA_COMMIT();
    for (int t = 0; t < tiles; t++) {
        int cur = t & 1;
        CPA_WAIT0();
        __syncthreads();
        if (t + 1 < tiles) loadT((t + 1) & 1, (t + 1) * BK);
        CPA_COMMIT();
        compute(cur);
    }

    // ---------------- epilogue ----------------
    const int lr4 = lane >> 2, lc2 = (lane & 3) * 2;
    #pragma unroll
    for (int mi = 0; mi < MI; mi++) {
        #pragma unroll
        for (int na = 0; na < NA; na++) {
            float* d = acc[mi][na];
            int col = col0 + wn0 + na * 8 + lc2;
            int r0 = row0 + wm0 + mi * 16 + lr4;
            float bb0 = 0.f, bb1 = 0.f;
            if (bias) {
                if (!NGUARD || col     < N) bb0 = bias[col];
                if (!NGUARD || col + 1 < N) bb1 = bias[col + 1];
            }
            float v0 = d[0] * alpha + bb0, v1 = d[1] * alpha + bb1;
            float v2 = d[2] * alpha + bb0, v3 = d[3] * alpha + bb1;
            if (RELU) {
                v0 = fmaxf(v0, 0.f); v1 = fmaxf(v1, 0.f);
                v2 = fmaxf(v2, 0.f); v3 = fmaxf(v3, 0.f);
            }
            long long b0i = (long long)r0 * ldc + col + coff;
            long long b1i = (long long)(r0 + 8) * ldc + col + coff;
            if (EPI == 0) {
                if (!NGUARD || col + 1 < N) {
                    *reinterpret_cast<float2*>(Cf + b0i) = make_float2(v0, v1);
                    *reinterpret_cast<float2*>(Cf + b1i) = make_float2(v2, v3);
                } else if (col < N) {
                    Cf[b0i] = v0;
                    Cf[b1i] = v2;
                }
            } else {  // EPI==2: fp16 single
                __half2 h01 = __floats2half2_rn(v0, v1);
                __half2 h23 = __floats2half2_rn(v2, v3);
                *reinterpret_cast<uint32_t*>(Chi + b0i) = *reinterpret_cast<uint32_t*>(&h01);
                *reinterpret_cast<uint32_t*>(Chi + b1i) = *reinterpret_cast<uint32_t*>(&h23);
            }
        }
    }
}

// ---------------- sparsemax + compaction: fp16 S in, (col,p) lists out ----------------
// 4 rows per 256-thread block, 64 threads (2 warps) per row; each warp owns 2048 row
// entries and compacts into its own 2048-entry list segment (overflow-impossible).
__global__ __launch_bounds__(256)
void sparsemax_compact(const uint16_t* __restrict__ S,
                       uint32_t* __restrict__ list, uint16_t* __restrict__ nnz)
{
    const int tid = threadIdx.x;
    const int grp = tid >> 6;
    const int gt  = tid & 63;
    const int lane = tid & 31;
    const int wid = tid >> 5;
    const long long row = (long long)blockIdx.x * 4 + grp;

    // 64 halves per thread: 16 x uint2 (4 halves each), stride 64 threads
    const uint2* z2 = reinterpret_cast<const uint2*>(S + row * (long long)M_KV);
    float v[64];
    #pragma unroll
    for (int j = 0; j < 16; j++) {
        uint2 p = z2[gt + j * 64];
        float2 a = __half22float2(*reinterpret_cast<const __half2*>(&p.x));
        float2 b = __half22float2(*reinterpret_cast<const __half2*>(&p.y));
        v[j * 4 + 0] = a.x; v[j * 4 + 1] = a.y;
        v[j * 4 + 2] = b.x; v[j * 4 + 3] = b.y;
    }

    __shared__ float red_s[8], red_c[8];
    __shared__ float s_tau[4];
    __shared__ int   s_done;

    float m = v[0];
    #pragma unroll
    for (int i = 1; i < 64; i++) m = fmaxf(m, v[i]);
    #pragma unroll
    for (int o = 16; o > 0; o >>= 1) m = fmaxf(m, __shfl_xor_sync(0xffffffffu, m, o));
    if (lane == 0) red_s[wid] = m;
    if (tid == 0) s_done = 0;
    __syncthreads();
    if (gt == 0) s_tau[grp] = fmaxf(red_s[grp * 2], red_s[grp * 2 + 1]) - 1.0f;
    __syncthreads();
    float t = s_tau[grp];

    for (int it = 0; it < 64; ++it) {
        float s = 0.f, c = 0.f;
        #pragma unroll
        for (int i = 0; i < 64; i++) {
            float d = v[i] - t;
            if (d > 0.f) { s += d; c += 1.f; }
        }
        #pragma unroll
        for (int o = 16; o > 0; o >>= 1) {
            s += __shfl_xor_sync(0xffffffffu, s, o);
            c += __shfl_xor_sync(0xffffffffu, c, o);
        }
        if (lane == 0) { red_s[wid] = s; red_c[wid] = c; }
        __syncthreads();
        if (gt == 0) {
            float St = red_s[grp * 2] + red_s[grp * 2 + 1];
            float Ct = red_c[grp * 2] + red_c[grp * 2 + 1];
            float delta = (St - 1.0f) / fmaxf(Ct, 1.0f);
            s_tau[grp] = t + delta;
            if (fabsf(delta) >= 1e-9f) atomicOr(&s_done, 1);
        }
        __syncthreads();
        t = s_tau[grp];
        int nd = s_done;
        __syncthreads();
        if (nd == 0) break;
        if (gt == 0) s_done = 0;
        __syncthreads();
    }

    // ---- deterministic compaction: warp-private list segment ----
    const int seg = gt >> 5;                       // uniform per warp
    uint32_t* Lrow = list + (size_t)row * M_KV + (size_t)seg * 2048;
    int base = 0;
    const uint32_t below = (1u << lane) - 1u;
    #pragma unroll
    for (int j = 0; j < 16; j++) {
        #pragma unroll
        for (int q = 0; q < 4; q++) {
            float p = v[j * 4 + q] - t;
            bool nz = p > 0.f;
            uint32_t mask = __ballot_sync(0xffffffffu, nz);
            if (nz) {
                int slot = base + __popc(mask & below);
                int col = 4 * (gt + j * 64) + q;
                __half ph = __float2half_rn(p);
                Lrow[slot] = (uint32_t)col | ((uint32_t)__half_as_ushort(ph) << 16);
            }
            base += __popc(mask);
        }
    }
    if (lane == 0) nnz[2 * row + seg] = (uint16_t)base;
}

// ---------------- PV gather: O[row] = sum_e p_e * V[col_e]  (one warp per row) ----------------
__global__ __launch_bounds__(256)
void pv_gather(const uint32_t* __restrict__ list, const uint16_t* __restrict__ nnz,
               const uint16_t* __restrict__ Vf, uint16_t* __restrict__ Of)
{
    const int gw = (blockIdx.x * 256 + threadIdx.x) >> 5;   // global warp index = row
    const int lane = threadIdx.x & 31;
    const int head = gw >> 11;                              // row / N_Q
    const int qrow = gw & (N_Q - 1);
    const uint32_t* L = list + (size_t)gw * M_KV;
    const int c0 = nnz[2 * gw], c1 = nnz[2 * gw + 1];
    const uint16_t* Vb = Vf + head * DHEAD + lane * 2;

    float a0 = 0.f, a1 = 0.f;
    for (int e = 0; e < c0; e++) {
        uint32_t ent = L[e];
        int col = ent & 0xFFFF;
        float pf = __half2float(__ushort_as_half((unsigned short)(ent >> 16)));
        uint32_t vv = *reinterpret_cast<const uint32_t*>(Vb + (size_t)col * DMODEL);
        float2 vf = __half22float2(*reinterpret_cast<const __half2*>(&vv));
        a0 += pf * vf.x;
        a1 += pf * vf.y;
    }
    for (int e = 0; e < c1; e++) {
        uint32_t ent = L[2048 + e];
        int col = ent & 0xFFFF;
        float pf = __half2float(__ushort_as_half((unsigned short)(ent >> 16)));
        uint32_t vv = *reinterpret_cast<const uint32_t*>(Vb + (size_t)col * DMODEL);
        float2 vf = __half22float2(*reinterpret_cast<const __half2*>(&vv));
        a0 += pf * vf.x;
        a1 += pf * vf.y;
    }
    __half2 r = __floats2half2_rn(a0, a1);
    *reinterpret_cast<uint32_t*>(Of + (size_t)qrow * DMODEL + head * DHEAD + lane * 2) =
        *reinterpret_cast<uint32_t*>(&r);
}

// ---------------- prep ----------------
__global__ __launch_bounds__(256)
void split_convert_f16(const float4* __restrict__ src, uint2* __restrict__ dh,
                       uint2* __restrict__ dl, int n4)
{
    int i = blockIdx.x * 256 + threadIdx.x;
    if (i >= n4) return;
    float4 v = src[i];
    uint32_t h01, l01, h23, l23;
    split2h(v.x, v.y, h01, l01);
    split2h(v.z, v.w, h23, l23);
    dh[i] = make_uint2(h01, h23);
    dl[i] = make_uint2(l01, l23);
}
__global__ __launch_bounds__(256)
void to_f16(const float4* __restrict__ src, uint2* __restrict__ dst, int n4)
{
    int i = blockIdx.x * 256 + threadIdx.x;
    if (i >= n4) return;
    float4 v = src[i];
    __half2 h01 = __floats2half2_rn(v.x, v.y);
    __half2 h23 = __floats2half2_rn(v.z, v.w);
    dst[i] = make_uint2(*reinterpret_cast<uint32_t*>(&h01), *reinterpret_cast<uint32_t*>(&h23));
}
// enc -> FINf fp16 single, columns [0, DMODEL)
__global__ __launch_bounds__(256)
void enc_to_fin(const float4* __restrict__ enc, uint16_t* __restrict__ f)
{
    int i = blockIdx.x * 256 + threadIdx.x;
    int row = i >> 8, cg = i & 255;
    float4 v = enc[i];
    __half2 h01 = __floats2half2_rn(v.x, v.y);
    __half2 h23 = __floats2half2_rn(v.z, v.w);
    int o = row * (2 * DMODEL) + cg * 4;
    *reinterpret_cast<uint2*>(f + o) =
        make_uint2(*reinterpret_cast<uint32_t*>(&h01), *reinterpret_cast<uint32_t*>(&h23));
}

// ---------------- host launcher ----------------
extern "C" void kernel_launch(void* const* d_in, const int* in_sizes, int n_in,
                              void* d_out, int out_size)
{
    const float* enc = (const float*)d_in[0];
    const float* mem = (const float*)d_in[1];
    const float* Wq  = (const float*)d_in[2];
    const float* bq  = (const float*)d_in[3];
    const float* Wk  = (const float*)d_in[4];
    const float* bk  = (const float*)d_in[5];
    const float* Wv  = (const float*)d_in[6];
    const float* bv  = (const float*)d_in[7];
    const float* Wo  = (const float*)d_in[8];
    const float* bo  = (const float*)d_in[9];
    const float* W1  = (const float*)d_in[10];
    const float* b1  = (const float*)d_in[11];
    const float* W2  = (const float*)d_in[12];
    const float* b2  = (const float*)d_in[13];
    float* out = (float*)d_out;

    uint16_t *pFINf, *pmemf;
    uint16_t *pWqh, *pWql, *pWkh, *pWkl, *pWvh, *pWvl, *pWoh, *pWol;
    uint16_t *pW1f, *pW2f;
    uint16_t *pQf, *pKf, *pVf, *pSf, *pOf, *pHf, *pNnz;
    uint32_t *pList;
    cudaGetSymbolAddress((void**)&pFINf, g_FINf);
    cudaGetSymbolAddress((void**)&pmemf, g_memf);
    cudaGetSymbolAddress((void**)&pWqh,  g_Wqh);  cudaGetSymbolAddress((void**)&pWql,  g_Wql);
    cudaGetSymbolAddress((void**)&pWkh,  g_Wkh);  cudaGetSymbolAddress((void**)&pWkl,  g_Wkl);
    cudaGetSymbolAddress((void**)&pWvh,  g_Wvh);  cudaGetSymbolAddress((void**)&pWvl,  g_Wvl);
    cudaGetSymbolAddress((void**)&pWoh,  g_Woh);  cudaGetSymbolAddress((void**)&pWol,  g_Wol);
    cudaGetSymbolAddress((void**)&pW1f,  g_W1f);
    cudaGetSymbolAddress((void**)&pW2f,  g_W2f);
    cudaGetSymbolAddress((void**)&pQf,   g_Qf);
    cudaGetSymbolAddress((void**)&pKf,   g_Kf);
    cudaGetSymbolAddress((void**)&pVf,   g_Vf);
    cudaGetSymbolAddress((void**)&pSf,   g_Sf);
    cudaGetSymbolAddress((void**)&pOf,   g_Of);
    cudaGetSymbolAddress((void**)&pHf,   g_Hf);
    cudaGetSymbolAddress((void**)&pList, g_list);
    cudaGetSymbolAddress((void**)&pNnz,  g_nnz);

    dim3 blk(256);
    auto cvtH = [&](const float* s, uint16_t* h, uint16_t* l, int n) {
        int n4 = n / 4;
        split_convert_f16<<<(n4 + 255) / 256, blk>>>((const float4*)s, (uint2*)h, (uint2*)l, n4);
    };
    auto cvt1 = [&](const float* s, uint16_t* d, int n) {
        int n4 = n / 4;
        to_f16<<<(n4 + 255) / 256, blk>>>((const float4*)s, (uint2*)d, n4);
    };

    constexpr int BKP = 40;
    const int DS_2B = 2 * (128 * BKP + 2 * 128 * BKP) * 2;            // 61440
    const int DS_1B = 2 * (128 * BKP + 1 * 128 * BKP) * 2;            // 40960

    auto* kProj  = mma_gemm<2,128,128,32,64,2,false,false>;  // Q/K/V/Wo: split-B, fp16 single out
    auto* kQK    = mma_gemm<1,128,128,32,64,2,false,false>;  // QK: 1-pass, fp16 out
    auto* kW1    = mma_gemm<1,128,128,32,64,2,true ,false>;  // W1: 1-pass + ReLU
    auto* kW2    = mma_gemm<1,128,128,32,64,0,false,true >;  // W2: 1-pass, N=1000 guarded
    cudaFuncSetAttribute(kProj, cudaFuncAttributeMaxDynamicSharedMemorySize, DS_2B);
    cudaFuncSetAttribute(kQK  , cudaFuncAttributeMaxDynamicSharedMemorySize, DS_1B);
    cudaFuncSetAttribute(kW1  , cudaFuncAttributeMaxDynamicSharedMemorySize, DS_1B);
    cudaFuncSetAttribute(kW2  , cudaFuncAttributeMaxDynamicSharedMemorySize, DS_1B);

    // 0: enc -> FINf left half (fp16)
    enc_to_fin<<<(N_Q * DMODEL / 4) / 256, blk>>>((const float4*)enc, pFINf);
    // 1: mem -> fp16 single
    cvt1(mem, pmemf, M_KV * DMODEL);
    // 2-4: projection weights fp16 split
    cvtH(Wq, pWqh, pWql, DMODEL * DMODEL);
    cvtH(Wk, pWkh, pWkl, DMODEL * DMODEL);
    cvtH(Wv, pWvh, pWvl, DMODEL * DMODEL);
    // 5: Q = enc @ Wq^T + bq -> fp16 single
    kProj<<<dim3(DMODEL/128, N_Q/128, 1), blk, DS_2B>>>(
        N_Q, DMODEL, DMODEL, pFINf, 2*DMODEL, 0, pWqh, pWql, DMODEL, 0,
        nullptr, pQf, DMODEL, 0, bq, 1.0f);
    // 6: K = mem @ Wk^T + bk -> fp16 single
    kProj<<<dim3(DMODEL/128, M_KV/128, 1), blk, DS_2B>>>(
        M_KV, DMODEL, DMODEL, pmemf, DMODEL, 0, pWkh, pWkl, DMODEL, 0,
        nullptr, pKf, DMODEL, 0, bk, 1.0f);
    // 7: V = mem @ Wv^T + bv -> fp16 single
    kProj<<<dim3(DMODEL/128, M_KV/128, 1), blk, DS_2B>>>(
        M_KV, DMODEL, DMODEL, pmemf, DMODEL, 0, pWvh, pWvl, DMODEL, 0,
        nullptr, pVf, DMODEL, 0, bv, 1.0f);
    // 8: S[h] = (Q_h @ K_h^T) / 32  (1-pass fp16, fp16 out)
    kQK<<<dim3(M_KV/128, N_Q/128, NHEADS), blk, DS_1B>>>(
        N_Q, M_KV, DHEAD, pQf, DMODEL, (long long)DHEAD,
        pKf, nullptr, DMODEL, (long long)DHEAD,
        nullptr, pSf, M_KV, (long long)N_Q * M_KV, nullptr, 0.03125f);
    // 9: Wo fp16 split
    cvtH(Wo, pWoh, pWol, DMODEL * DMODEL);
    // 10: sparsemax + compaction (fp16 S -> (col,p) lists)
    sparsemax_compact<<<NROWS / 4, blk>>>(pSf, pList, pNnz);
    // 11: O = gather(P sparse, V)
    pv_gather<<<NROWS * 32 / 256, blk>>>(pList, pNnz, pVf, pOf);
    // 12: FINf[:, 1024:2048] = O @ Wo^T + bo (fp16 single)
    kProj<<<dim3(DMODEL/128, N_Q/128, 1), blk, DS_2B>>>(
        N_Q, DMODEL, DMODEL, pOf, DMODEL, 0, pWoh, pWol, DMODEL, 0,
        nullptr, pFINf + DMODEL, 2*DMODEL, 0, bo, 1.0f);
    // 13: W1 fp16 single
    cvt1(W1, pW1f, DFF * 2 * DMODEL);
    // 14: H = relu(FINf @ W1^T + b1)  (1-pass fp16)
    kW1<<<dim3(DFF/128, N_Q/128, 1), blk, DS_1B>>>(
        N_Q, DFF, 2*DMODEL, pFINf, 2*DMODEL, 0, pW1f, nullptr, 2*DMODEL, 0,
        nullptr, pHf, DFF, 0, b1, 1.0f);
    // 15: W2 fp16 single
    cvt1(W2, pW2f, DOUT * DFF);
    // 16: OUT = H @ W2^T + b2  (1-pass fp16, N = 1000)
    kW2<<<dim3((DOUT + 127)/128, N_Q/128, 1), blk, DS_1B>>>(
        N_Q, DOUT, DFF, pHf, DFF, 0, pW2f, nullptr, DFF, 0,
        out, nullptr, DOUT, 0, b2, 1.0f);
}

// round 16
// speedup vs baseline: 1.4612x; 1.0001x over previous
#include <cuda_runtime.h>
#include <cuda_bf16.h>
#include <cuda_fp16.h>
#include <cstdint>
#include <math.h>

// Problem dims (fixed by the dataset)
#define N_Q    2048
#define M_KV   4096
#define DMODEL 1024
#define NHEADS 16
#define DHEAD  64
#define DFF    4096
#define DOUT   1000
#define NROWS  (NHEADS * N_Q)

// ---------------- scratch (device globals; no allocation allowed) ----------------
__device__ uint16_t g_FINf[N_Q * 2 * DMODEL];                        // fp16: [enc | attn-out]
__device__ uint16_t g_memf[M_KV * DMODEL];                           // fp16 single
__device__ uint16_t g_Wqh[DMODEL*DMODEL],   g_Wql[DMODEL*DMODEL];    // fp16 split
__device__ uint16_t g_WKVh[2*DMODEL*DMODEL], g_WKVl[2*DMODEL*DMODEL];// [Wk;Wv] fp16 split
__device__ float    g_bKV[2 * DMODEL];
__device__ uint16_t g_Woh[DMODEL*DMODEL],   g_Wol[DMODEL*DMODEL];    // fp16 split
__device__ uint16_t g_W1f[DFF*2*DMODEL];                             // fp16 single
__device__ uint16_t g_W2f[DOUT*DFF];                                 // fp16 single
__device__ uint16_t g_Qf[N_Q*DMODEL];                                // fp16 single
__device__ uint16_t g_KVf[M_KV * 2 * DMODEL];                        // fp16: K | V
__device__ uint16_t g_Sf[(size_t)NROWS * M_KV];                      // fp16 logits (256 MB)
__device__ uint32_t g_list[(size_t)NROWS * M_KV];                    // per-row (col | p<<16)
__device__ uint16_t g_nnz[2 * NROWS];                                // per-row segment counts
__device__ uint16_t g_Of[N_Q*DMODEL];                                // fp16 single
__device__ uint16_t g_Hf[N_Q*DFF];                                   // fp16 single

// ---------------- helpers ----------------
__device__ __forceinline__ uint32_t smem_u32(const void* p) {
    uint32_t a;
    asm("{ .reg .u64 t; cvta.to.shared.u64 t, %1; cvt.u32.u64 %0, t; }" : "=r"(a) : "l"(p));
    return a;
}
__device__ __forceinline__ void ldmx4(uint32_t* r, uint32_t a) {
    asm volatile("ldmatrix.sync.aligned.m8n8.x4.shared.b16 {%0,%1,%2,%3}, [%4];"
                 : "=r"(r[0]), "=r"(r[1]), "=r"(r[2]), "=r"(r[3]) : "r"(a));
}
__device__ __forceinline__ void mma_f16(float* d, const uint32_t* a, uint32_t b0, uint32_t b1) {
    asm volatile("mma.sync.aligned.m16n8k16.row.col.f32.f16.f16.f32 "
                 "{%0,%1,%2,%3}, {%4,%5,%6,%7}, {%8,%9}, {%0,%1,%2,%3};"
                 : "+f"(d[0]), "+f"(d[1]), "+f"(d[2]), "+f"(d[3])
                 : "r"(a[0]), "r"(a[1]), "r"(a[2]), "r"(a[3]), "r"(b0), "r"(b1));
}
__device__ __forceinline__ void cpa16(uint32_t s, const void* g) {
    asm volatile("cp.async.cg.shared.global [%0], [%1], 16;" :: "r"(s), "l"(g));
}
__device__ __forceinline__ void cpa16z(uint32_t s, const void* g, bool ok) {
    int sz = ok ? 16 : 0;
    asm volatile("cp.async.cg.shared.global [%0], [%1], 16, %2;" :: "r"(s), "l"(g), "r"(sz));
}
#define CPA_COMMIT() asm volatile("cp.async.commit_group;" ::: "memory")
#define CPA_WAIT0()  asm volatile("cp.async.wait_group 0;" ::: "memory")
#define CPA_WAIT1()  asm volatile("cp.async.wait_group 1;" ::: "memory")

// fp32 pair -> fp16 hi + fp16 residual
__device__ __forceinline__ void split2h(float a, float b, uint32_t& h, uint32_t& l) {
    __half2 hh = __floats2half2_rn(a, b);
    float2 hf = __half22float2(hh);
    __half2 ll = __floats2half2_rn(a - hf.x, b - hf.y);
    h = *reinterpret_cast<uint32_t*>(&hh);
    l = *reinterpret_cast<uint32_t*>(&ll);
}

// ====================== async 3-stage fp16 MMA GEMM ======================
// C = alpha * A @ B^T + bias (+ReLU).  A fp16 single.
// NPB=2: B fp16 hi/lo (2-pass).  NPB=1: B fp16 single (1-pass).
// Batch via blockIdx.z. EPI: 0 = fp32 -> Cf; 2 = fp16 single -> Chi.
template<int NPB, int BM, int BN, int WM, int WN, int EPI, bool RELU, bool NGUARD>
__global__ __launch_bounds__(256, 2)
void mma_gemm(int M, int N, int K,
              const uint16_t* __restrict__ Ah, int lda, long long sAz,
              const uint16_t* __restrict__ Bh, const uint16_t* __restrict__ Bl, int ldb, long long sBz,
              float* __restrict__ Cf, uint16_t* __restrict__ Chi,
              long long ldc, long long sCz,
              const float* __restrict__ bias, float alpha)
{
    constexpr int BK = 32, BKP = 40;
    constexpr int WNC = BN / WN;
    constexpr int MI = WM / 16, NI2 = WN / 16, NA = WN / 8;
    constexpr int SA = BM * BKP, SB = BN * BKP;
    constexpr int STAGE_BYTES = (SA + NPB * SB) * 2;

    extern __shared__ __align__(16) char smem[];
    const uint32_t uS = smem_u32(smem);

    const int tid = threadIdx.x, wid = tid >> 5, lane = tid & 31;
    Ah += (long long)blockIdx.z * sAz;
    Bh += (long long)blockIdx.z * sBz;
    if (NPB == 2) Bl += (long long)blockIdx.z * sBz;
    const long long coff = (long long)blockIdx.z * sCz;
    const int row0 = blockIdx.y * BM;
    const int col0 = blockIdx.x * BN;
    const int wm0 = (wid / WNC) * WM;
    const int wn0 = (wid % WNC) * WN;

    float acc[MI][NA][4];
    #pragma unroll
    for (int i = 0; i < MI; i++)
        #pragma unroll
        for (int j = 0; j < NA; j++)
            #pragma unroll
            for (int q = 0; q < 4; q++) acc[i][j][q] = 0.f;

    auto loadT = [&](int stage, int kt) {
        uint32_t base = uS + stage * STAGE_BYTES;
        #pragma unroll
        for (int i = 0; i < (BM * 4) / 256; i++) {
            int ch = tid + i * 256, r = ch >> 2, q = ch & 3;
            cpa16(base + r * 80 + q * 16, Ah + (size_t)(row0 + r) * lda + kt + q * 8);
        }
        #pragma unroll
        for (int i = 0; i < (BN * 4) / 256; i++) {
            int ch = tid + i * 256, r = ch >> 2, q = ch & 3;
            bool ok = !NGUARD || (col0 + r) < N;
            cpa16z(base + SA * 2 + r * 80 + q * 16,
                   Bh + (size_t)(col0 + r) * ldb + kt + q * 8, ok);
            if (NPB == 2)
                cpa16z(base + (SA + SB) * 2 + r * 80 + q * 16,
                       Bl + (size_t)(col0 + r) * ldb + kt + q * 8, ok);
        }
    };
    auto compute = [&](int stage) {
        uint32_t bA = uS + stage * STAGE_BYTES;
        uint32_t bBh = bA + SA * 2, bBl = bA + (SA + SB) * 2;
        const int lr = lane & 15, lc = (lane >> 4) * 8;
        #pragma unroll
        for (int kk = 0; kk < BK; kk += 16) {
            uint32_t bh[NI2][4], bl[NI2][4];
            #pragma unroll
            for (int ni = 0; ni < NI2; ni++) {
                uint32_t off = (uint32_t)((wn0 + ni * 16 + lr) * 80 + (kk + lc) * 2);
                ldmx4(bh[ni], bBh + off);
                if (NPB == 2) ldmx4(bl[ni], bBl + off);
            }
            #pragma unroll
            for (int mi = 0; mi < MI; mi++) {
                uint32_t ah[4];
                uint32_t off = (uint32_t)((wm0 + mi * 16 + lr) * 80 + (kk + lc) * 2);
                ldmx4(ah, bA + off);
                #pragma unroll
                for (int na = 0; na < NA; na++) {
                    int ni = na >> 1, sel = na & 1;
                    mma_f16(acc[mi][na], ah, bh[ni][sel], bh[ni][sel + 2]);
                    if (NPB == 2)
                        mma_f16(acc[mi][na], ah, bl[ni][sel], bl[ni][sel + 2]);
                }
            }
        }
    };

    const int tiles = K / BK;
    loadT(0, 0);
    CPA_COMMIT();
    if (tiles > 1) { loadT(1, BK); }
    CPA_COMMIT();
    for (int t = 0; t < tiles; t++) {
        if (t + 1 < tiles) { CPA_WAIT1(); } else { CPA_WAIT0(); }
        __syncthreads();
        compute(t % 3);
        if (t + 2 < tiles) loadT((t + 2) % 3, (t + 2) * BK);
        CPA_COMMIT();
    }

    // ---------------- epilogue ----------------
    const int lr4 = lane >> 2, lc2 = (lane & 3) * 2;
    #pragma unroll
    for (int mi = 0; mi < MI; mi++) {
        #pragma unroll
        for (int na = 0; na < NA; na++) {
            float* d = acc[mi][na];
            int col = col0 + wn0 + na * 8 + lc2;
            int r0 = row0 + wm0 + mi * 16 + lr4;
            float bb0 = 0.f, bb1 = 0.f;
            if (bias) {
                if (!NGUARD || col     < N) bb0 = bias[col];
                if (!NGUARD || col + 1 < N) bb1 = bias[col + 1];
            }
            float v0 = d[0] * alpha + bb0, v1 = d[1] * alpha + bb1;
            float v2 = d[2] * alpha + bb0, v3 = d[3] * alpha + bb1;
            if (RELU) {
                v0 = fmaxf(v0, 0.f); v1 = fmaxf(v1, 0.f);
                v2 = fmaxf(v2, 0.f); v3 = fmaxf(v3, 0.f);
            }
            long long b0i = (long long)r0 * ldc + col + coff;
            long long b1i = (long long)(r0 + 8) * ldc + col + coff;
            if (EPI == 0) {
                if (!NGUARD || col + 1 < N) {
                    *reinterpret_cast<float2*>(Cf + b0i) = make_float2(v0, v1);
                    *reinterpret_cast<float2*>(Cf + b1i) = make_float2(v2, v3);
                } else if (col < N) {
                    Cf[b0i] = v0;
                    Cf[b1i] = v2;
                }
            } else {  // EPI==2: fp16 single
                __half2 h01 = __floats2half2_rn(v0, v1);
                __half2 h23 = __floats2half2_rn(v2, v3);
                *reinterpret_cast<uint32_t*>(Chi + b0i) = *reinterpret_cast<uint32_t*>(&h01);
                *reinterpret_cast<uint32_t*>(Chi + b1i) = *reinterpret_cast<uint32_t*>(&h23);
            }
        }
    }
}

// ---------------- sparsemax + compaction: fp16 S in, (col,p) lists out ----------------
__global__ __launch_bounds__(256)
void sparsemax_compact(const uint16_t* __restrict__ S,
                       uint32_t* __restrict__ list, uint16_t* __restrict__ nnz)
{
    const int tid = threadIdx.x;
    const int grp = tid >> 6;
    const int gt  = tid & 63;
    const int lane = tid & 31;
    const int wid = tid >> 5;
    const long long row = (long long)blockIdx.x * 4 + grp;

    const uint2* z2 = reinterpret_cast<const uint2*>(S + row * (long long)M_KV);
    float v[64];
    #pragma unroll
    for (int j = 0; j < 16; j++) {
        uint2 p = z2[gt + j * 64];
        float2 a = __half22float2(*reinterpret_cast<const __half2*>(&p.x));
        float2 b = __half22float2(*reinterpret_cast<const __half2*>(&p.y));
        v[j * 4 + 0] = a.x; v[j * 4 + 1] = a.y;
        v[j * 4 + 2] = b.x; v[j * 4 + 3] = b.y;
    }

    __shared__ float red_s[8], red_c[8];
    __shared__ float s_tau[4];
    __shared__ int   s_done;

    float m = v[0];
    #pragma unroll
    for (int i = 1; i < 64; i++) m = fmaxf(m, v[i]);
    #pragma unroll
    for (int o = 16; o > 0; o >>= 1) m = fmaxf(m, __shfl_xor_sync(0xffffffffu, m, o));
    if (lane == 0) red_s[wid] = m;
    if (tid == 0) s_done = 0;
    __syncthreads();
    if (gt == 0) s_tau[grp] = fmaxf(red_s[grp * 2], red_s[grp * 2 + 1]) - 1.0f;
    __syncthreads();
    float t = s_tau[grp];

    for (int it = 0; it < 64; ++it) {
        float s = 0.f, c = 0.f;
        #pragma unroll
        for (int i = 0; i < 64; i++) {
            float d = v[i] - t;
            if (d > 0.f) { s += d; c += 1.f; }
        }
        #pragma unroll
        for (int o = 16; o > 0; o >>= 1) {
            s += __shfl_xor_sync(0xffffffffu, s, o);
            c += __shfl_xor_sync(0xffffffffu, c, o);
        }
        if (lane == 0) { red_s[wid] = s; red_c[wid] = c; }
        __syncthreads();
        if (gt == 0) {
            float St = red_s[grp * 2] + red_s[grp * 2 + 1];
            float Ct = red_c[grp * 2] + red_c[grp * 2 + 1];
            float delta = (St - 1.0f) / fmaxf(Ct, 1.0f);
            s_tau[grp] = t + delta;
            if (fabsf(delta) >= 1e-9f) atomicOr(&s_done, 1);
        }
        __syncthreads();
        t = s_tau[grp];
        int nd = s_done;
        __syncthreads();
        if (nd == 0) break;
        if (gt == 0) s_done = 0;
        __syncthreads();
    }

    // deterministic compaction: warp-private list segment
    const int seg = gt >> 5;
    uint32_t* Lrow = list + (size_t)row * M_KV + (size_t)seg * 2048;
    int base = 0;
    const uint32_t below = (1u << lane) - 1u;
    #pragma unroll
    for (int j = 0; j < 16; j++) {
        #pragma unroll
        for (int q = 0; q < 4; q++) {
            float p = v[j * 4 + q] - t;
            bool nz = p > 0.f;
            uint32_t mask = __ballot_sync(0xffffffffu, nz);
            if (nz) {
                int slot = base + __popc(mask & below);
                int col = 4 * (gt + j * 64) + q;
                __half ph = __float2half_rn(p);
                Lrow[slot] = (uint32_t)col | ((uint32_t)__half_as_ushort(ph) << 16);
            }
            base += __popc(mask);
        }
    }
    if (lane == 0) nnz[2 * row + seg] = (uint16_t)base;
}

// ---------------- PV gather: O[row] = sum_e p_e * V[col_e]  (one warp per row) ----------------
// V lives in the KV buffer at column offset DMODEL, row stride 2*DMODEL.
__global__ __launch_bounds__(256)
void pv_gather(const uint32_t* __restrict__ list, const uint16_t* __restrict__ nnz,
               const uint16_t* __restrict__ KVf, uint16_t* __restrict__ Of)
{
    const int gw = (blockIdx.x * 256 + threadIdx.x) >> 5;
    const int lane = threadIdx.x & 31;
    const int head = gw >> 11;
    const int qrow = gw & (N_Q - 1);
    const uint32_t* L = list + (size_t)gw * M_KV;
    const int c0 = nnz[2 * gw], c1 = nnz[2 * gw + 1];
    const uint16_t* Vb = KVf + DMODEL + head * DHEAD + lane * 2;

    float a0 = 0.f, a1 = 0.f;
    for (int e = 0; e < c0; e++) {
        uint32_t ent = L[e];
        int col = ent & 0xFFFF;
        float pf = __half2float(__ushort_as_half((unsigned short)(ent >> 16)));
        uint32_t vv = *reinterpret_cast<const uint32_t*>(Vb + (size_t)col * 2 * DMODEL);
        float2 vf = __half22float2(*reinterpret_cast<const __half2*>(&vv));
        a0 += pf * vf.x;
        a1 += pf * vf.y;
    }
    for (int e = 0; e < c1; e++) {
        uint32_t ent = L[2048 + e];
        int col = ent & 0xFFFF;
        float pf = __half2float(__ushort_as_half((unsigned short)(ent >> 16)));
        uint32_t vv = *reinterpret_cast<const uint32_t*>(Vb + (size_t)col * 2 * DMODEL);
        float2 vf = __half22float2(*reinterpret_cast<const __half2*>(&vv));
        a0 += pf * vf.x;
        a1 += pf * vf.y;
    }
    __half2 r = __floats2half2_rn(a0, a1);
    *reinterpret_cast<uint32_t*>(Of + (size_t)qrow * DMODEL + head * DHEAD + lane * 2) =
        *reinterpret_cast<uint32_t*>(&r);
}

// ---------------- prep ----------------
__global__ __launch_bounds__(256)
void split_convert_f16(const float4* __restrict__ src, uint2* __restrict__ dh,
                       uint2* __restrict__ dl, int n4)
{
    int i = blockIdx.x * 256 + threadIdx.x;
    if (i >= n4) return;
    float4 v = src[i];
    uint32_t h01, l01, h23, l23;
    split2h(v.x, v.y, h01, l01);
    split2h(v.z, v.w, h23, l23);
    dh[i] = make_uint2(h01, h23);
    dl[i] = make_uint2(l01, l23);
}
__global__ __launch_bounds__(256)
void to_f16(const float4* __restrict__ src, uint2* __restrict__ dst, int n4)
{
    int i = blockIdx.x * 256 + threadIdx.x;
    if (i >= n4) return;
    float4 v = src[i];
    __half2 h01 = __floats2half2_rn(v.x, v.y);
    __half2 h23 = __floats2half2_rn(v.z, v.w);
    dst[i] = make_uint2(*reinterpret_cast<uint32_t*>(&h01), *reinterpret_cast<uint32_t*>(&h23));
}
// enc -> FINf fp16 single, columns [0, DMODEL)
__global__ __launch_bounds__(256)
void enc_to_fin(const float4* __restrict__ enc, uint16_t* __restrict__ f)
{
    int i = blockIdx.x * 256 + threadIdx.x;
    int row = i >> 8, cg = i & 255;
    float4 v = enc[i];
    __half2 h01 = __floats2half2_rn(v.x, v.y);
    __half2 h23 = __floats2half2_rn(v.z, v.w);
    int o = row * (2 * DMODEL) + cg * 4;
    *reinterpret_cast<uint2*>(f + o) =
        make_uint2(*reinterpret_cast<uint32_t*>(&h01), *reinterpret_cast<uint32_t*>(&h23));
}
__global__ __launch_bounds__(256)
void combine_bias(const float* __restrict__ bk, const float* __restrict__ bv,
                  float* __restrict__ bkv)
{
    int i = blockIdx.x * 256 + threadIdx.x;
    bkv[i] = (i < DMODEL) ? bk[i] : bv[i - DMODEL];
}

// ---------------- host launcher ----------------
extern "C" void kernel_launch(void* const* d_in, const int* in_sizes, int n_in,
                              void* d_out, int out_size)
{
    const float* enc = (const float*)d_in[0];
    const float* mem = (const float*)d_in[1];
    const float* Wq  = (const float*)d_in[2];
    const float* bq  = (const float*)d_in[3];
    const float* Wk  = (const float*)d_in[4];
    const float* bk  = (const float*)d_in[5];
    const float* Wv  = (const float*)d_in[6];
    const float* bv  = (const float*)d_in[7];
    const float* Wo  = (const float*)d_in[8];
    const float* bo  = (const float*)d_in[9];
    const float* W1  = (const float*)d_in[10];
    const float* b1  = (const float*)d_in[11];
    const float* W2  = (const float*)d_in[12];
    const float* b2  = (const float*)d_in[13];
    float* out = (float*)d_out;

    uint16_t *pFINf, *pmemf;
    uint16_t *pWqh, *pWql, *pWKVh, *pWKVl, *pWoh, *pWol;
    uint16_t *pW1f, *pW2f;
    uint16_t *pQf, *pKVf, *pSf, *pOf, *pHf, *pNnz;
    uint32_t *pList;
    float *pbKV;
    cudaGetSymbolAddress((void**)&pFINf, g_FINf);
    cudaGetSymbolAddress((void**)&pmemf, g_memf);
    cudaGetSymbolAddress((void**)&pWqh,  g_Wqh);  cudaGetSymbolAddress((void**)&pWql,  g_Wql);
    cudaGetSymbolAddress((void**)&pWKVh, g_WKVh); cudaGetSymbolAddress((void**)&pWKVl, g_WKVl);
    cudaGetSymbolAddress((void**)&pWoh,  g_Woh);  cudaGetSymbolAddress((void**)&pWol,  g_Wol);
    cudaGetSymbolAddress((void**)&pW1f,  g_W1f);
    cudaGetSymbolAddress((void**)&pW2f,  g_W2f);
    cudaGetSymbolAddress((void**)&pQf,   g_Qf);
    cudaGetSymbolAddress((void**)&pKVf,  g_KVf);
    cudaGetSymbolAddress((void**)&pSf,   g_Sf);
    cudaGetSymbolAddress((void**)&pOf,   g_Of);
    cudaGetSymbolAddress((void**)&pHf,   g_Hf);
    cudaGetSymbolAddress((void**)&pList, g_list);
    cudaGetSymbolAddress((void**)&pNnz,  g_nnz);
    cudaGetSymbolAddress((void**)&pbKV,  g_bKV);

    dim3 blk(256);
    auto cvtH = [&](const float* s, uint16_t* h, uint16_t* l, int n) {
        int n4 = n / 4;
        split_convert_f16<<<(n4 + 255) / 256, blk>>>((const float4*)s, (uint2*)h, (uint2*)l, n4);
    };
    auto cvt1 = [&](const float* s, uint16_t* d, int n) {
        int n4 = n / 4;
        to_f16<<<(n4 + 255) / 256, blk>>>((const float4*)s, (uint2*)d, n4);
    };

    constexpr int BKP = 40;
    const int DS_2B = 3 * (128 * BKP + 2 * 128 * BKP) * 2;            // 92160
    const int DS_1B = 3 * (128 * BKP + 1 * 128 * BKP) * 2;            // 61440

    auto* kProj  = mma_gemm<2,128,128,32,64,2,false,false>;  // proj: split-B, fp16 single out
    auto* kQK    = mma_gemm<1,128,128,32,64,2,false,false>;  // QK: 1-pass, fp16 out
    auto* kW1    = mma_gemm<1,128,128,32,64,2,true ,false>;  // W1: 1-pass + ReLU
    auto* kW2    = mma_gemm<1,128,128,32,64,0,false,true >;  // W2: 1-pass, N=1000 guarded
    cudaFuncSetAttribute(kProj, cudaFuncAttributeMaxDynamicSharedMemorySize, DS_2B);
    cudaFuncSetAttribute(kQK  , cudaFuncAttributeMaxDynamicSharedMemorySize, DS_1B);
    cudaFuncSetAttribute(kW1  , cudaFuncAttributeMaxDynamicSharedMemorySize, DS_1B);
    cudaFuncSetAttribute(kW2  , cudaFuncAttributeMaxDynamicSharedMemorySize, DS_1B);

    // ---- launch order: user-launch index 4 = KV projection (ncu capture slot) ----
    // 0: mem -> fp16 single
    cvt1(mem, pmemf, M_KV * DMODEL);
    // 1: Wk -> WKV[0] fp16 split
    cvtH(Wk, pWKVh, pWKVl, DMODEL * DMODEL);
    // 2: Wv -> WKV[1] fp16 split
    cvtH(Wv, pWKVh + DMODEL*DMODEL, pWKVl + DMODEL*DMODEL, DMODEL * DMODEL);
    // 3: combined bias
    combine_bias<<<(2 * DMODEL) / 256, blk>>>(bk, bv, pbKV);
    // 4: KV = mem @ [Wk;Wv]^T + [bk;bv]   [4096, 2048]   <-- ncu capture
    kProj<<<dim3(2*DMODEL/128, M_KV/128, 1), blk, DS_2B>>>(
        M_KV, 2*DMODEL, DMODEL, pmemf, DMODEL, 0, pWKVh, pWKVl, DMODEL, 0,
        nullptr, pKVf, 2*DMODEL, 0, pbKV, 1.0f);
    // 5: enc -> FINf left half (fp16)
    enc_to_fin<<<(N_Q * DMODEL / 4) / 256, blk>>>((const float4*)enc, pFINf);
    // 6: Wq fp16 split
    cvtH(Wq, pWqh, pWql, DMODEL * DMODEL);
    // 7: Q = enc @ Wq^T + bq -> fp16 single
    kProj<<<dim3(DMODEL/128, N_Q/128, 1), blk, DS_2B>>>(
        N_Q, DMODEL, DMODEL, pFINf, 2*DMODEL, 0, pWqh, pWql, DMODEL, 0,
        nullptr, pQf, DMODEL, 0, bq, 1.0f);
    // 8: S[h] = (Q_h @ K_h^T) / 32  (K = KV cols [0,1024), ldb 2048)
    kQK<<<dim3(M_KV/128, N_Q/128, NHEADS), blk, DS_1B>>>(
        N_Q, M_KV, DHEAD, pQf, DMODEL, (long long)DHEAD,
        pKVf, nullptr, 2*DMODEL, (long long)DHEAD,
        nullptr, pSf, M_KV, (long long)N_Q * M_KV, nullptr, 0.03125f);
    // 9: Wo fp16 split
    cvtH(Wo, pWoh, pWol, DMODEL * DMODEL);
    // 10: sparsemax + compaction
    sparsemax_compact<<<NROWS / 4, blk>>>(pSf, pList, pNnz);
    // 11: O = gather(P sparse, V)
    pv_gather<<<NROWS * 32 / 256, blk>>>(pList, pNnz, pKVf, pOf);
    // 12: FINf[:, 1024:2048] = O @ Wo^T + bo
    kProj<<<dim3(DMODEL/128, N_Q/128, 1), blk, DS_2B>>>(
        N_Q, DMODEL, DMODEL, pOf, DMODEL, 0, pWoh, pWol, DMODEL, 0,
        nullptr, pFINf + DMODEL, 2*DMODEL, 0, bo, 1.0f);
    // 13: W1 fp16 single
    cvt1(W1, pW1f, DFF * 2 * DMODEL);
    // 14: H = relu(FINf @ W1^T + b1)
    kW1<<<dim3(DFF/128, N_Q/128, 1), blk, DS_1B>>>(
        N_Q, DFF, 2*DMODEL, pFINf, 2*DMODEL, 0, pW1f, nullptr, 2*DMODEL, 0,
        nullptr, pHf, DFF, 0, b1, 1.0f);
    // 15: W2 fp16 single
    cvt1(W2, pW2f, DOUT * DFF);
    // 16: OUT = H @ W2^T + b2  (N = 1000)
    kW2<<<dim3((DOUT + 127)/128, N_Q/128, 1), blk, DS_1B>>>(
        N_Q, DOUT, DFF, pHf, DFF, 0, pW2f, nullptr, DFF, 0,
        out, nullptr, DOUT, 0, b2, 1.0f);
}

// round 17
// speedup vs baseline: 3.3464x; 2.2901x over previous
#include <cuda_runtime.h>
#include <cuda_bf16.h>
#include <cuda_fp16.h>
#include <cstdint>
#include <math.h>

// Problem dims (fixed by the dataset)
#define N_Q    2048
#define M_KV   4096
#define DMODEL 1024
#define NHEADS 16
#define DHEAD  64
#define DFF    4096
#define DOUT   1000
#define NROWS  (NHEADS * N_Q)

// ---------------- scratch (device globals; no allocation allowed) ----------------
__device__ uint16_t g_FINf[N_Q * 2 * DMODEL];                        // fp16: [enc | attn-out]
__device__ uint16_t g_memf[M_KV * DMODEL];                           // fp16 single
__device__ uint16_t g_Wqh[DMODEL*DMODEL],   g_Wql[DMODEL*DMODEL];    // fp16 split
__device__ uint16_t g_WKVh[2*DMODEL*DMODEL], g_WKVl[2*DMODEL*DMODEL];// [Wk;Wv] fp16 split
__device__ uint16_t g_Woh[DMODEL*DMODEL],   g_Wol[DMODEL*DMODEL];    // fp16 split
__device__ uint16_t g_W1f[DFF*2*DMODEL];                             // fp16 single
__device__ uint16_t g_W2f[DOUT*DFF];                                 // fp16 single
__device__ uint16_t g_Qf[N_Q*DMODEL];                                // fp16 single
__device__ uint16_t g_KVf[M_KV * 2 * DMODEL];                        // fp16: K | V
__device__ uint16_t g_Sf[(size_t)NROWS * M_KV];                      // fp16 logits (256 MB)
__device__ uint32_t g_list[(size_t)NROWS * M_KV];                    // per-row (col | p<<16)
__device__ uint16_t g_nnz[2 * NROWS];                                // per-row segment counts
__device__ uint16_t g_Of[N_Q*DMODEL];                                // fp16 single
__device__ uint16_t g_Hf[N_Q*DFF];                                   // fp16 single

// ---------------- helpers ----------------
__device__ __forceinline__ uint32_t smem_u32(const void* p) {
    uint32_t a;
    asm("{ .reg .u64 t; cvta.to.shared.u64 t, %1; cvt.u32.u64 %0, t; }" : "=r"(a) : "l"(p));
    return a;
}
__device__ __forceinline__ void ldmx4(uint32_t* r, uint32_t a) {
    asm volatile("ldmatrix.sync.aligned.m8n8.x4.shared.b16 {%0,%1,%2,%3}, [%4];"
                 : "=r"(r[0]), "=r"(r[1]), "=r"(r[2]), "=r"(r[3]) : "r"(a));
}
__device__ __forceinline__ void mma_f16(float* d, const uint32_t* a, uint32_t b0, uint32_t b1) {
    asm volatile("mma.sync.aligned.m16n8k16.row.col.f32.f16.f16.f32 "
                 "{%0,%1,%2,%3}, {%4,%5,%6,%7}, {%8,%9}, {%0,%1,%2,%3};"
                 : "+f"(d[0]), "+f"(d[1]), "+f"(d[2]), "+f"(d[3])
                 : "r"(a[0]), "r"(a[1]), "r"(a[2]), "r"(a[3]), "r"(b0), "r"(b1));
}
__device__ __forceinline__ void cpa16(uint32_t s, const void* g) {
    asm volatile("cp.async.cg.shared.global [%0], [%1], 16;" :: "r"(s), "l"(g));
}
__device__ __forceinline__ void cpa16z(uint32_t s, const void* g, bool ok) {
    int sz = ok ? 16 : 0;
    asm volatile("cp.async.cg.shared.global [%0], [%1], 16, %2;" :: "r"(s), "l"(g), "r"(sz));
}
#define CPA_COMMIT() asm volatile("cp.async.commit_group;" ::: "memory")
#define CPA_WAIT0()  asm volatile("cp.async.wait_group 0;" ::: "memory")

// fp32 pair -> fp16 hi + fp16 residual
__device__ __forceinline__ void split2h(float a, float b, uint32_t& h, uint32_t& l) {
    __half2 hh = __floats2half2_rn(a, b);
    float2 hf = __half22float2(hh);
    __half2 ll = __floats2half2_rn(a - hf.x, b - hf.y);
    h = *reinterpret_cast<uint32_t*>(&hh);
    l = *reinterpret_cast<uint32_t*>(&ll);
}

// ====================== async double-buffered fp16 MMA GEMM ======================
// C = alpha * A @ B^T + bias (+ReLU).  A fp16 single.
// NPB=2: B fp16 hi/lo (2-pass).  NPB=1: B fp16 single (1-pass).
// bias2 != nullptr: columns >= DMODEL take bias from bias2[col-DMODEL].
// Batch via blockIdx.z. EPI: 0 = fp32 -> Cf; 2 = fp16 single -> Chi.
template<int NPB, int BM, int BN, int WM, int WN, int EPI, bool RELU, bool NGUARD>
__global__ __launch_bounds__(256, 2)
void mma_gemm(int M, int N, int K,
              const uint16_t* __restrict__ Ah, int lda, long long sAz,
              const uint16_t* __restrict__ Bh, const uint16_t* __restrict__ Bl, int ldb, long long sBz,
              float* __restrict__ Cf, uint16_t* __restrict__ Chi,
              long long ldc, long long sCz,
              const float* __restrict__ bias, const float* __restrict__ bias2, float alpha)
{
    constexpr int BK = 32, BKP = 40;
    constexpr int WNC = BN / WN;
    constexpr int MI = WM / 16, NI2 = WN / 16, NA = WN / 8;
    constexpr int SA = BM * BKP, SB = BN * BKP;
    constexpr int STAGE_BYTES = (SA + NPB * SB) * 2;

    extern __shared__ __align__(16) char smem[];
    const uint32_t uS = smem_u32(smem);

    const int tid = threadIdx.x, wid = tid >> 5, lane = tid & 31;
    Ah += (long long)blockIdx.z * sAz;
    Bh += (long long)blockIdx.z * sBz;
    if (NPB == 2) Bl += (long long)blockIdx.z * sBz;
    const long long coff = (long long)blockIdx.z * sCz;
    const int row0 = blockIdx.y * BM;
    const int col0 = blockIdx.x * BN;
    const int wm0 = (wid / WNC) * WM;
    const int wn0 = (wid % WNC) * WN;

    float acc[MI][NA][4];
    #pragma unroll
    for (int i = 0; i < MI; i++)
        #pragma unroll
        for (int j = 0; j < NA; j++)
            #pragma unroll
            for (int q = 0; q < 4; q++) acc[i][j][q] = 0.f;

    auto loadT = [&](int stage, int kt) {
        uint32_t base = uS + stage * STAGE_BYTES;
        #pragma unroll
        for (int i = 0; i < (BM * 4) / 256; i++) {
            int ch = tid + i * 256, r = ch >> 2, q = ch & 3;
            cpa16(base + r * 80 + q * 16, Ah + (size_t)(row0 + r) * lda + kt + q * 8);
        }
        #pragma unroll
        for (int i = 0; i < (BN * 4) / 256; i++) {
            int ch = tid + i * 256, r = ch >> 2, q = ch & 3;
            bool ok = !NGUARD || (col0 + r) < N;
            cpa16z(base + SA * 2 + r * 80 + q * 16,
                   Bh + (size_t)(col0 + r) * ldb + kt + q * 8, ok);
            if (NPB == 2)
                cpa16z(base + (SA + SB) * 2 + r * 80 + q * 16,
                       Bl + (size_t)(col0 + r) * ldb + kt + q * 8, ok);
        }
    };
    auto compute = [&](int stage) {
        uint32_t bA = uS + stage * STAGE_BYTES;
        uint32_t bBh = bA + SA * 2, bBl = bA + (SA + SB) * 2;
        const int lr = lane & 15, lc = (lane >> 4) * 8;
        #pragma unroll
        for (int kk = 0; kk < BK; kk += 16) {
            uint32_t bh[NI2][4], bl[NI2][4];
            #pragma unroll
            for (int ni = 0; ni < NI2; ni++) {
                uint32_t off = (uint32_t)((wn0 + ni * 16 + lr) * 80 + (kk + lc) * 2);
                ldmx4(bh[ni], bBh + off);
                if (NPB == 2) ldmx4(bl[ni], bBl + off);
            }
            #pragma unroll
            for (int mi = 0; mi < MI; mi++) {
                uint32_t ah[4];
                uint32_t off = (uint32_t)((wm0 + mi * 16 + lr) * 80 + (kk + lc) * 2);
                ldmx4(ah, bA + off);
                #pragma unroll
                for (int na = 0; na < NA; na++) {
                    int ni = na >> 1, sel = na & 1;
                    mma_f16(acc[mi][na], ah, bh[ni][sel], bh[ni][sel + 2]);
                    if (NPB == 2)
                        mma_f16(acc[mi][na], ah, bl[ni][sel], bl[ni][sel + 2]);
                }
            }
        }
    };

    const int tiles = K / BK;
    loadT(0, 0);
    CPA_COMMIT();
    for (int t = 0; t < tiles; t++) {
        int cur = t & 1;
        CPA_WAIT0();
        __syncthreads();
        if (t + 1 < tiles) loadT((t + 1) & 1, (t + 1) * BK);
        CPA_COMMIT();
        compute(cur);
    }

    // ---------------- epilogue ----------------
    const int lr4 = lane >> 2, lc2 = (lane & 3) * 2;
    #pragma unroll
    for (int mi = 0; mi < MI; mi++) {
        #pragma unroll
        for (int na = 0; na < NA; na++) {
            float* d = acc[mi][na];
            int col = col0 + wn0 + na * 8 + lc2;
            int r0 = row0 + wm0 + mi * 16 + lr4;
            // col is even; bias segment never straddles col/col+1
            const float* bp = bias;
            int bcol = col;
            if (bias2 && col >= DMODEL) { bp = bias2; bcol = col - DMODEL; }
            float bb0 = 0.f, bb1 = 0.f;
            if (bp) {
                if (!NGUARD || col     < N) bb0 = bp[bcol];
                if (!NGUARD || col + 1 < N) bb1 = bp[bcol + 1];
            }
            float v0 = d[0] * alpha + bb0, v1 = d[1] * alpha + bb1;
            float v2 = d[2] * alpha + bb0, v3 = d[3] * alpha + bb1;
            if (RELU) {
                v0 = fmaxf(v0, 0.f); v1 = fmaxf(v1, 0.f);
                v2 = fmaxf(v2, 0.f); v3 = fmaxf(v3, 0.f);
            }
            long long b0i = (long long)r0 * ldc + col + coff;
            long long b1i = (long long)(r0 + 8) * ldc + col + coff;
            if (EPI == 0) {
                if (!NGUARD || col + 1 < N) {
                    *reinterpret_cast<float2*>(Cf + b0i) = make_float2(v0, v1);
                    *reinterpret_cast<float2*>(Cf + b1i) = make_float2(v2, v3);
                } else if (col < N) {
                    Cf[b0i] = v0;
                    Cf[b1i] = v2;
                }
            } else {  // EPI==2: fp16 single
                __half2 h01 = __floats2half2_rn(v0, v1);
                __half2 h23 = __floats2half2_rn(v2, v3);
                *reinterpret_cast<uint32_t*>(Chi + b0i) = *reinterpret_cast<uint32_t*>(&h01);
                *reinterpret_cast<uint32_t*>(Chi + b1i) = *reinterpret_cast<uint32_t*>(&h23);
            }
        }
    }
}

// ---------------- sparsemax + compaction: fp16 S in, (col,p) lists out ----------------
__global__ __launch_bounds__(256)
void sparsemax_compact(const uint16_t* __restrict__ S,
                       uint32_t* __restrict__ list, uint16_t* __restrict__ nnz)
{
    const int tid = threadIdx.x;
    const int grp = tid >> 6;
    const int gt  = tid & 63;
    const int lane = tid & 31;
    const int wid = tid >> 5;
    const long long row = (long long)blockIdx.x * 4 + grp;

    const uint2* z2 = reinterpret_cast<const uint2*>(S + row * (long long)M_KV);
    float v[64];
    #pragma unroll
    for (int j = 0; j < 16; j++) {
        uint2 p = z2[gt + j * 64];
        float2 a = __half22float2(*reinterpret_cast<const __half2*>(&p.x));
        float2 b = __half22float2(*reinterpret_cast<const __half2*>(&p.y));
        v[j * 4 + 0] = a.x; v[j * 4 + 1] = a.y;
        v[j * 4 + 2] = b.x; v[j * 4 + 3] = b.y;
    }

    __shared__ float red_s[8], red_c[8];
    __shared__ float s_tau[4];
    __shared__ int   s_done;

    float m = v[0];
    #pragma unroll
    for (int i = 1; i < 64; i++) m = fmaxf(m, v[i]);
    #pragma unroll
    for (int o = 16; o > 0; o >>= 1) m = fmaxf(m, __shfl_xor_sync(0xffffffffu, m, o));
    if (lane == 0) red_s[wid] = m;
    if (tid == 0) s_done = 0;
    __syncthreads();
    if (gt == 0) s_tau[grp] = fmaxf(red_s[grp * 2], red_s[grp * 2 + 1]) - 1.0f;
    __syncthreads();
    float t = s_tau[grp];

    for (int it = 0; it < 64; ++it) {
        float s = 0.f, c = 0.f;
        #pragma unroll
        for (int i = 0; i < 64; i++) {
            float d = v[i] - t;
            if (d > 0.f) { s += d; c += 1.f; }
        }
        #pragma unroll
        for (int o = 16; o > 0; o >>= 1) {
            s += __shfl_xor_sync(0xffffffffu, s, o);
            c += __shfl_xor_sync(0xffffffffu, c, o);
        }
        if (lane == 0) { red_s[wid] = s; red_c[wid] = c; }
        __syncthreads();
        if (gt == 0) {
            float St = red_s[grp * 2] + red_s[grp * 2 + 1];
            float Ct = red_c[grp * 2] + red_c[grp * 2 + 1];
            float delta = (St - 1.0f) / fmaxf(Ct, 1.0f);
            s_tau[grp] = t + delta;
            // fp32 rounding keeps |delta| ~1e-8 at the fixed point; 1e-6 is the
            // practical convergence level (tau error 1e-6 -> P error ~1e-5 rel).
            if (fabsf(delta) >= 1e-6f) atomicOr(&s_done, 1);
        }
        __syncthreads();
        t = s_tau[grp];
        int nd = s_done;
        __syncthreads();
        if (nd == 0) break;
        if (gt == 0) s_done = 0;
        __syncthreads();
    }

    // deterministic compaction: warp-private list segment
    const int seg = gt >> 5;
    uint32_t* Lrow = list + (size_t)row * M_KV + (size_t)seg * 2048;
    int base = 0;
    const uint32_t below = (1u << lane) - 1u;
    #pragma unroll
    for (int j = 0; j < 16; j++) {
        #pragma unroll
        for (int q = 0; q < 4; q++) {
            float p = v[j * 4 + q] - t;
            bool nz = p > 0.f;
            uint32_t mask = __ballot_sync(0xffffffffu, nz);
            if (nz) {
                int slot = base + __popc(mask & below);
                int col = 4 * (gt + j * 64) + q;
                __half ph = __float2half_rn(p);
                Lrow[slot] = (uint32_t)col | ((uint32_t)__half_as_ushort(ph) << 16);
            }
            base += __popc(mask);
        }
    }
    if (lane == 0) nnz[2 * row + seg] = (uint16_t)base;
}

// ---------------- PV gather: O[row] = sum_e p_e * V[col_e]  (one warp per row) ----------------
__global__ __launch_bounds__(256)
void pv_gather(const uint32_t* __restrict__ list, const uint16_t* __restrict__ nnz,
               const uint16_t* __restrict__ KVf, uint16_t* __restrict__ Of)
{
    const int gw = (blockIdx.x * 256 + threadIdx.x) >> 5;
    const int lane = threadIdx.x & 31;
    const int head = gw >> 11;
    const int qrow = gw & (N_Q - 1);
    const uint32_t* L = list + (size_t)gw * M_KV;
    const int c0 = nnz[2 * gw], c1 = nnz[2 * gw + 1];
    const uint16_t* Vb = KVf + DMODEL + head * DHEAD + lane * 2;

    float a0 = 0.f, a1 = 0.f;
    for (int e = 0; e < c0; e++) {
        uint32_t ent = L[e];
        int col = ent & 0xFFFF;
        float pf = __half2float(__ushort_as_half((unsigned short)(ent >> 16)));
        uint32_t vv = *reinterpret_cast<const uint32_t*>(Vb + (size_t)col * 2 * DMODEL);
        float2 vf = __half22float2(*reinterpret_cast<const __half2*>(&vv));
        a0 += pf * vf.x;
        a1 += pf * vf.y;
    }
    for (int e = 0; e < c1; e++) {
        uint32_t ent = L[2048 + e];
        int col = ent & 0xFFFF;
        float pf = __half2float(__ushort_as_half((unsigned short)(ent >> 16)));
        uint32_t vv = *reinterpret_cast<const uint32_t*>(Vb + (size_t)col * 2 * DMODEL);
        float2 vf = __half22float2(*reinterpret_cast<const __half2*>(&vv));
        a0 += pf * vf.x;
        a1 += pf * vf.y;
    }
    __half2 r = __floats2half2_rn(a0, a1);
    *reinterpret_cast<uint32_t*>(Of + (size_t)qrow * DMODEL + head * DHEAD + lane * 2) =
        *reinterpret_cast<uint32_t*>(&r);
}

// ---------------- prep ----------------
__global__ __launch_bounds__(256)
void split_convert_f16(const float4* __restrict__ src, uint2* __restrict__ dh,
                       uint2* __restrict__ dl, int n4)
{
    int i = blockIdx.x * 256 + threadIdx.x;
    if (i >= n4) return;
    float4 v = src[i];
    uint32_t h01, l01, h23, l23;
    split2h(v.x, v.y, h01, l01);
    split2h(v.z, v.w, h23, l23);
    dh[i] = make_uint2(h01, h23);
    dl[i] = make_uint2(l01, l23);
}
__global__ __launch_bounds__(256)
void to_f16(const float4* __restrict__ src, uint2* __restrict__ dst, int n4)
{
    int i = blockIdx.x * 256 + threadIdx.x;
    if (i >= n4) return;
    float4 v = src[i];
    __half2 h01 = __floats2half2_rn(v.x, v.y);
    __half2 h23 = __floats2half2_rn(v.z, v.w);
    dst[i] = make_uint2(*reinterpret_cast<uint32_t*>(&h01), *reinterpret_cast<uint32_t*>(&h23));
}
// enc -> FINf fp16 single, columns [0, DMODEL)
__global__ __launch_bounds__(256)
void enc_to_fin(const float4* __restrict__ enc, uint16_t* __restrict__ f)
{
    int i = blockIdx.x * 256 + threadIdx.x;
    int row = i >> 8, cg = i & 255;
    float4 v = enc[i];
    __half2 h01 = __floats2half2_rn(v.x, v.y);
    __half2 h23 = __floats2half2_rn(v.z, v.w);
    int o = row * (2 * DMODEL) + cg * 4;
    *reinterpret_cast<uint2*>(f + o) =
        make_uint2(*reinterpret_cast<uint32_t*>(&h01), *reinterpret_cast<uint32_t*>(&h23));
}

// ---------------- host launcher ----------------
extern "C" void kernel_launch(void* const* d_in, const int* in_sizes, int n_in,
                              void* d_out, int out_size)
{
    const float* enc = (const float*)d_in[0];
    const float* mem = (const float*)d_in[1];
    const float* Wq  = (const float*)d_in[2];
    const float* bq  = (const float*)d_in[3];
    const float* Wk  = (const float*)d_in[4];
    const float* bk  = (const float*)d_in[5];
    const float* Wv  = (const float*)d_in[6];
    const float* bv  = (const float*)d_in[7];
    const float* Wo  = (const float*)d_in[8];
    const float* bo  = (const float*)d_in[9];
    const float* W1  = (const float*)d_in[10];
    const float* b1  = (const float*)d_in[11];
    const float* W2  = (const float*)d_in[12];
    const float* b2  = (const float*)d_in[13];
    float* out = (float*)d_out;

    uint16_t *pFINf, *pmemf;
    uint16_t *pWqh, *pWql, *pWKVh, *pWKVl, *pWoh, *pWol;
    uint16_t *pW1f, *pW2f;
    uint16_t *pQf, *pKVf, *pSf, *pOf, *pHf, *pNnz;
    uint32_t *pList;
    cudaGetSymbolAddress((void**)&pFINf, g_FINf);
    cudaGetSymbolAddress((void**)&pmemf, g_memf);
    cudaGetSymbolAddress((void**)&pWqh,  g_Wqh);  cudaGetSymbolAddress((void**)&pWql,  g_Wql);
    cudaGetSymbolAddress((void**)&pWKVh, g_WKVh); cudaGetSymbolAddress((void**)&pWKVl, g_WKVl);
    cudaGetSymbolAddress((void**)&pWoh,  g_Woh);  cudaGetSymbolAddress((void**)&pWol,  g_Wol);
    cudaGetSymbolAddress((void**)&pW1f,  g_W1f);
    cudaGetSymbolAddress((void**)&pW2f,  g_W2f);
    cudaGetSymbolAddress((void**)&pQf,   g_Qf);
    cudaGetSymbolAddress((void**)&pKVf,  g_KVf);
    cudaGetSymbolAddress((void**)&pSf,   g_Sf);
    cudaGetSymbolAddress((void**)&pOf,   g_Of);
    cudaGetSymbolAddress((void**)&pHf,   g_Hf);
    cudaGetSymbolAddress((void**)&pList, g_list);
    cudaGetSymbolAddress((void**)&pNnz,  g_nnz);

    dim3 blk(256);
    auto cvtH = [&](const float* s, uint16_t* h, uint16_t* l, int n) {
        int n4 = n / 4;
        split_convert_f16<<<(n4 + 255) / 256, blk>>>((const float4*)s, (uint2*)h, (uint2*)l, n4);
    };
    auto cvt1 = [&](const float* s, uint16_t* d, int n) {
        int n4 = n / 4;
        to_f16<<<(n4 + 255) / 256, blk>>>((const float4*)s, (uint2*)d, n4);
    };

    constexpr int BKP = 40;
    const int DS_2B = 2 * (128 * BKP + 2 * 128 * BKP) * 2;            // 61440
    const int DS_1B = 2 * (128 * BKP + 1 * 128 * BKP) * 2;            // 40960

    auto* kProj  = mma_gemm<2,128,128,32,64,2,false,false>;  // proj: split-B, fp16 single out
    auto* kQK    = mma_gemm<1,128,128,32,64,2,false,false>;  // QK: 1-pass, fp16 out
    auto* kW1    = mma_gemm<1,128,128,32,64,2,true ,false>;  // W1: 1-pass + ReLU
    auto* kW2    = mma_gemm<1,128,128,32,64,0,false,true >;  // W2: 1-pass, N=1000 guarded
    cudaFuncSetAttribute(kProj, cudaFuncAttributeMaxDynamicSharedMemorySize, DS_2B);
    cudaFuncSetAttribute(kQK  , cudaFuncAttributeMaxDynamicSharedMemorySize, DS_1B);
    cudaFuncSetAttribute(kW1  , cudaFuncAttributeMaxDynamicSharedMemorySize, DS_1B);
    cudaFuncSetAttribute(kW2  , cudaFuncAttributeMaxDynamicSharedMemorySize, DS_1B);

    // ---- launch order: user-launch index 3 = KV projection (ncu capture slot) ----
    // 0: mem -> fp16 single
    cvt1(mem, pmemf, M_KV * DMODEL);
    // 1: Wk -> WKV[0] fp16 split
    cvtH(Wk, pWKVh, pWKVl, DMODEL * DMODEL);
    // 2: Wv -> WKV[1] fp16 split
    cvtH(Wv, pWKVh + DMODEL*DMODEL, pWKVl + DMODEL*DMODEL, DMODEL * DMODEL);
    // 3: KV = mem @ [Wk;Wv]^T + [bk|bv]   [4096, 2048]   <-- ncu capture
    kProj<<<dim3(2*DMODEL/128, M_KV/128, 1), blk, DS_2B>>>(
        M_KV, 2*DMODEL, DMODEL, pmemf, DMODEL, 0, pWKVh, pWKVl, DMODEL, 0,
        nullptr, pKVf, 2*DMODEL, 0, bk, bv, 1.0f);
    // 4: enc -> FINf left half (fp16)
    enc_to_fin<<<(N_Q * DMODEL / 4) / 256, blk>>>((const float4*)enc, pFINf);
    // 5: Wq fp16 split
    cvtH(Wq, pWqh, pWql, DMODEL * DMODEL);
    // 6: Q = enc @ Wq^T + bq -> fp16 single
    kProj<<<dim3(DMODEL/128, N_Q/128, 1), blk, DS_2B>>>(
        N_Q, DMODEL, DMODEL, pFINf, 2*DMODEL, 0, pWqh, pWql, DMODEL, 0,
        nullptr, pQf, DMODEL, 0, bq, nullptr, 1.0f);
    // 7: S[h] = (Q_h @ K_h^T) / 32  (K = KV cols [0,1024), ldb 2048)
    kQK<<<dim3(M_KV/128, N_Q/128, NHEADS), blk, DS_1B>>>(
        N_Q, M_KV, DHEAD, pQf, DMODEL, (long long)DHEAD,
        pKVf, nullptr, 2*DMODEL, (long long)DHEAD,
        nullptr, pSf, M_KV, (long long)N_Q * M_KV, nullptr, nullptr, 0.03125f);
    // 8: Wo fp16 split
    cvtH(Wo, pWoh, pWol, DMODEL * DMODEL);
    // 9: sparsemax + compaction
    sparsemax_compact<<<NROWS / 4, blk>>>(pSf, pList, pNnz);
    // 10: O = gather(P sparse, V)
    pv_gather<<<NROWS * 32 / 256, blk>>>(pList, pNnz, pKVf, pOf);
    // 11: FINf[:, 1024:2048] = O @ Wo^T + bo
    kProj<<<dim3(DMODEL/128, N_Q/128, 1), blk, DS_2B>>>(
        N_Q, DMODEL, DMODEL, pOf, DMODEL, 0, pWoh, pWol, DMODEL, 0,
        nullptr, pFINf + DMODEL, 2*DMODEL, 0, bo, nullptr, 1.0f);
    // 12: W1 fp16 single
    cvt1(W1, pW1f, DFF * 2 * DMODEL);
    // 13: H = relu(FINf @ W1^T + b1)
    kW1<<<dim3(DFF/128, N_Q/128, 1), blk, DS_1B>>>(
        N_Q, DFF, 2*DMODEL, pFINf, 2*DMODEL, 0, pW1f, nullptr, 2*DMODEL, 0,
        nullptr, pHf, DFF, 0, b1, nullptr, 1.0f);
    // 14: W2 fp16 single
    cvt1(W2, pW2f, DOUT * DFF);
    // 15: OUT = H @ W2^T + b2  (N = 1000)
    kW2<<<dim3((DOUT + 127)/128, N_Q/128, 1), blk, DS_1B>>>(
        N_Q, DOUT, DFF, pHf, DFF, 0, pW2f, nullptr, DFF, 0,
        out, nullptr, DOUT, 0, b2, nullptr, 1.0f);
}